// round 2
// baseline (speedup 1.0000x reference)
#include <cuda_runtime.h>
#include <cuda_bf16.h>
#include <cstdint>

typedef unsigned long long ull;

#define Bn     16
#define CIN    128
#define Hh     8
#define MODESn 256
#define Ln     16384
#define BC     (Bn*CIN)     // 2048
#define NF     (2*MODESn)   // 512

// ---------------- device scratch (no allocations allowed) -------------------
__device__ float2 g_sc[Ln];                     // cos,sin table
__device__ float  g_Bf[(size_t)Ln*NF];          // forward basis  (33.5 MB)
__device__ float  g_Bi[(size_t)NF*Ln];          // inverse basis  (33.5 MB)
__device__ float  g_Xf[BC*NF];                  // forward spectrum (re,im)
__device__ float  g_Yf[BC*NF];                  // mixed spectrum
__device__ float  g_wT[3*CIN*CIN];              // conv weights [ci][d][co]

// ---------------- packed f32x2 helpers --------------------------------------
__device__ __forceinline__ ull pk2(float v) {
    ull d; unsigned u = __float_as_uint(v);
    asm("mov.b64 %0, {%1, %2};" : "=l"(d) : "r"(u), "r"(u));
    return d;
}
__device__ __forceinline__ void upk(ull v, float& lo, float& hi) {
    unsigned a, b;
    asm("mov.b64 {%0, %1}, %2;" : "=r"(a), "=r"(b) : "l"(v));
    lo = __uint_as_float(a); hi = __uint_as_float(b);
}
__device__ __forceinline__ ull fma2(ull a, ull b, ull c) {
    ull d;
    asm("fma.rn.f32x2 %0, %1, %2, %3;" : "=l"(d) : "l"(a), "l"(b), "l"(c));
    return d;
}
// (hi of a, lo of b)
__device__ __forceinline__ ull packmid(ull a, ull b) {
    unsigned a0, a1, b0, b1; ull r;
    asm("mov.b64 {%0, %1}, %2;" : "=r"(a0), "=r"(a1) : "l"(a));
    asm("mov.b64 {%0, %1}, %2;" : "=r"(b0), "=r"(b1) : "l"(b));
    asm("mov.b64 %0, {%1, %2};" : "=l"(r) : "r"(a1), "r"(b0));
    return r;
}

// ---------------- init kernels -----------------------------------------------
__global__ void k_sincos() {
    int j = blockIdx.x * 256 + threadIdx.x;          // 0..16383
    float s, c;
    sincospif((float)j * (2.0f / Ln), &s, &c);       // theta = 2*pi*j/L (exact arg)
    g_sc[j] = make_float2(c, s);
}

__global__ void k_fillBf() {
    int col = blockIdx.x * 256 + threadIdx.x;        // 0..511
    int n   = blockIdx.y;                            // 0..16383
    int k   = col >> 1;
    float2 sc = g_sc[(k * n) & (Ln - 1)];
    const float inv = 1.0f / Ln;
    g_Bf[(size_t)n * NF + col] = (col & 1) ? (-sc.y * inv) : (sc.x * inv);
}

__global__ void k_fillBi() {
    int n   = blockIdx.x * 256 + threadIdx.x;        // 0..16383
    int row = blockIdx.y;                            // 0..511
    int k   = row >> 1;
    float2 sc = g_sc[(k * n) & (Ln - 1)];
    float ck = (k == 0) ? 1.0f : 2.0f;
    g_Bi[(size_t)row * Ln + n] = (row & 1) ? (-ck * sc.y) : (ck * sc.x);
}

__global__ void k_wT(const float* __restrict__ w) {
    int idx = blockIdx.x * 256 + threadIdx.x;        // (co*128+ci)*3+d
    if (idx < CIN * CIN * 3) {
        int d = idx % 3; int t = idx / 3;
        int ci = t & 127; int co = t >> 7;
        g_wT[(ci * 3 + d) * CIN + co] = w[idx];
    }
}

// ---------------- 64x64 GEMM, BK=16, 256 thr, 4x4/thr, f32x2 over M ----------
// EPI=false: g_Xf = x @ g_Bf
// EPI=true : d_out = g*(g_Yf @ g_Bi + bias) + (1-g)*d_out   (d_out holds conv)
template<int KSTEPS, bool EPI>
__global__ void __launch_bounds__(256) k_gemm64(const float* __restrict__ Aext,
                                                float* __restrict__ Cext,
                                                const float* __restrict__ bias,
                                                const float* __restrict__ gate) {
    const float* A  = EPI ? (const float*)g_Yf : Aext;
    const float* Bm = EPI ? (const float*)g_Bi : (const float*)g_Bf;
    float*       C  = EPI ? Cext : (float*)g_Xf;
    const int lda = EPI ? NF : Ln;
    const int ldb = EPI ? Ln : NF;
    const int ldc = EPI ? Ln : NF;

    __shared__ __align__(16) float As[2][16][68];
    __shared__ __align__(16) float Bs[2][16][68];

    const int tid = threadIdx.x;
    const int tx  = tid & 15;
    const int ty  = tid >> 4;
    const int mBase = blockIdx.y * 64;
    const int nBase = blockIdx.x * 64;

    const int la_m = tid >> 2;
    const int la_k = (tid & 3) << 2;
    const int lb_k = tid >> 4;
    const int lb_n = (tid & 15) << 2;

    const float* Ap = A  + (size_t)(mBase + la_m) * lda + la_k;
    const float* Bp = Bm + (size_t)lb_k * ldb + nBase + lb_n;

    ull acc[2][4];
#pragma unroll
    for (int p = 0; p < 2; p++)
#pragma unroll
        for (int n = 0; n < 4; n++) acc[p][n] = 0ULL;

    float4 a4 = *(const float4*)Ap;
    float4 b4 = *(const float4*)Bp;
    As[0][la_k + 0][la_m] = a4.x;
    As[0][la_k + 1][la_m] = a4.y;
    As[0][la_k + 2][la_m] = a4.z;
    As[0][la_k + 3][la_m] = a4.w;
    *(float4*)&Bs[0][lb_k][lb_n] = b4;
    __syncthreads();

    int cur = 0;
#pragma unroll 1
    for (int t = 0; t < KSTEPS; ++t) {
        float4 na, nb;
        if (t + 1 < KSTEPS) {
            na = *(const float4*)(Ap + (size_t)(t + 1) * 16);
            nb = *(const float4*)(Bp + (size_t)(t + 1) * 16 * ldb);
        }
#pragma unroll
        for (int kk = 0; kk < 16; ++kk) {
            ull a0 = *(const ull*)&As[cur][kk][ty * 4];
            ull a1 = *(const ull*)&As[cur][kk][ty * 4 + 2];
            float4 bv = *(const float4*)&Bs[cur][kk][tx * 4];
            ull b0 = pk2(bv.x), b1 = pk2(bv.y), b2 = pk2(bv.z), b3 = pk2(bv.w);
            acc[0][0] = fma2(a0, b0, acc[0][0]);
            acc[0][1] = fma2(a0, b1, acc[0][1]);
            acc[0][2] = fma2(a0, b2, acc[0][2]);
            acc[0][3] = fma2(a0, b3, acc[0][3]);
            acc[1][0] = fma2(a1, b0, acc[1][0]);
            acc[1][1] = fma2(a1, b1, acc[1][1]);
            acc[1][2] = fma2(a1, b2, acc[1][2]);
            acc[1][3] = fma2(a1, b3, acc[1][3]);
        }
        if (t + 1 < KSTEPS) {
            int nxt = cur ^ 1;
            As[nxt][la_k + 0][la_m] = na.x;
            As[nxt][la_k + 1][la_m] = na.y;
            As[nxt][la_k + 2][la_m] = na.z;
            As[nxt][la_k + 3][la_m] = na.w;
            *(float4*)&Bs[nxt][lb_k][lb_n] = nb;
            __syncthreads();
            cur = nxt;
        }
    }

    const int n0g = nBase + tx * 4;
    float gg = 0.f, og = 0.f;
    if (EPI) { gg = 1.0f / (1.0f + expf(-gate[0])); og = 1.0f - gg; }
#pragma unroll
    for (int p = 0; p < 2; p++) {
        float l0, h0, l1, h1, l2, h2, l3, h3;
        upk(acc[p][0], l0, h0);
        upk(acc[p][1], l1, h1);
        upk(acc[p][2], l2, h2);
        upk(acc[p][3], l3, h3);
        const int mlo = mBase + ty * 4 + 2 * p;
        const int mhi = mlo + 1;
        float4 vlo = make_float4(l0, l1, l2, l3);
        float4 vhi = make_float4(h0, h1, h2, h3);
        float* Clo = C + (size_t)mlo * ldc + n0g;
        float* Chi = C + (size_t)mhi * ldc + n0g;
        if (EPI) {
            float blo = bias[mlo & (CIN - 1)];
            float bhi = bias[mhi & (CIN - 1)];
            float4 cl = *(const float4*)Clo;
            float4 ch = *(const float4*)Chi;
            vlo = make_float4(gg * (vlo.x + blo) + og * cl.x,
                              gg * (vlo.y + blo) + og * cl.y,
                              gg * (vlo.z + blo) + og * cl.z,
                              gg * (vlo.w + blo) + og * cl.w);
            vhi = make_float4(gg * (vhi.x + bhi) + og * ch.x,
                              gg * (vhi.y + bhi) + og * ch.y,
                              gg * (vhi.z + bhi) + og * ch.z,
                              gg * (vhi.w + bhi) + og * ch.w);
        }
        *(float4*)Clo = vlo;
        *(float4*)Chi = vhi;
    }
}

// ---------------- per-mode complex 16x16 head mixing -------------------------
__global__ void __launch_bounds__(128) k_mix(const float* __restrict__ wre,
                                             const float* __restrict__ wim) {
    const int kc = blockIdx.x;           // 0..1
    const int h  = blockIdx.y;           // 0..7
    const int b  = blockIdx.z;           // 0..15
    const int kg = kc * 128 + threadIdx.x;

    float xr[16], xi[16];
#pragma unroll
    for (int i = 0; i < 16; i++) {
        float2 v = *(const float2*)&g_Xf[((b * CIN + h * 16 + i) * NF) + 2 * kg];
        xr[i] = v.x; xi[i] = v.y;
    }
#pragma unroll 1
    for (int o = 0; o < 16; o++) {
        float ar = 0.f, ai = 0.f;
#pragma unroll
        for (int i = 0; i < 16; i++) {
            int widx = ((h * 16 + i) * 16 + o) * MODESn + kg;
            float wr = wre[widx], wi = wim[widx];
            ar = fmaf(xr[i], wr, ar);
            ar = fmaf(-xi[i], wi, ar);
            ai = fmaf(xr[i], wi, ai);
            ai = fmaf(xi[i], wr, ai);
        }
        *(float2*)&g_Yf[((b * CIN + h * 16 + o) * NF) + 2 * kg] = make_float2(ar, ai);
    }
}

// ---------------- conv1d(k=3, SAME) + conv_b -> d_out ------------------------
// block: (n-tile 128, batch). Xs[ci][130] = x[n0-1 .. n0+128]. Thread = one co,
// one 64-n half; 32 f32x2 accumulators; smem-staged coalesced store.
__global__ void __launch_bounds__(256) k_conv(const float* __restrict__ x,
                                              const float* __restrict__ cb,
                                              float* __restrict__ out) {
    extern __shared__ float Xs[];                    // 128*130 floats
    const int b  = blockIdx.y;
    const int n0 = blockIdx.x * 128;
    const int tid = threadIdx.x;
    const float* xb = x + (size_t)b * CIN * Ln;

    for (int idx = tid; idx < CIN * 130; idx += 256) {
        int ci = idx / 130;
        int j  = idx - ci * 130;
        int n  = n0 - 1 + j;
        Xs[idx] = ((unsigned)n < (unsigned)Ln) ? xb[(size_t)ci * Ln + n] : 0.f;
    }
    __syncthreads();

    const int co   = tid & 127;
    const int base = (tid >> 7) * 64;

    ull acc[32];
#pragma unroll
    for (int m = 0; m < 32; m++) acc[m] = 0ULL;

#pragma unroll 1
    for (int ci = 0; ci < CIN; ci++) {
        const float* wp = g_wT + ci * 3 * CIN + co;
        ull w0 = pk2(wp[0]), w1 = pk2(wp[CIN]), w2 = pk2(wp[2 * CIN]);
        const float* xr = Xs + ci * 130 + base;
        ull e = *(const ull*)xr;
#pragma unroll
        for (int m = 0; m < 32; m++) {
            ull e2 = *(const ull*)(xr + 2 * m + 2);
            ull md = packmid(e, e2);
            acc[m] = fma2(w0, e, acc[m]);
            acc[m] = fma2(w1, md, acc[m]);
            acc[m] = fma2(w2, e2, acc[m]);
            e = e2;
        }
    }
    __syncthreads();

    const float bv = cb[co];
#pragma unroll
    for (int m = 0; m < 32; m++) {
        float lo, hi; upk(acc[m], lo, hi);
        Xs[co * 130 + base + 2 * m]     = lo + bv;
        Xs[co * 130 + base + 2 * m + 1] = hi + bv;
    }
    __syncthreads();

    float* ob = out + (size_t)b * CIN * Ln + n0;
    for (int idx = tid; idx < CIN * 128; idx += 256) {
        int c = idx >> 7;
        int n = idx & 127;
        ob[(size_t)c * Ln + n] = Xs[c * 130 + n];
    }
}

// ---------------- launch ------------------------------------------------------
extern "C" void kernel_launch(void* const* d_in, const int* in_sizes, int n_in,
                              void* d_out, int out_size) {
    const float* x      = (const float*)d_in[0];
    const float* wre    = (const float*)d_in[1];
    const float* wim    = (const float*)d_in[2];
    const float* bias   = (const float*)d_in[3];
    const float* conv_w = (const float*)d_in[4];
    const float* conv_b = (const float*)d_in[5];
    const float* gate   = (const float*)d_in[6];
    float* out = (float*)d_out;

    static bool attr_set = false;
    // (idempotent host-side attribute; not a graph node)
    cudaFuncSetAttribute(k_conv, cudaFuncAttributeMaxDynamicSharedMemorySize,
                         CIN * 130 * sizeof(float));
    (void)attr_set;

    k_sincos<<<Ln / 256, 256>>>();
    k_fillBf<<<dim3(NF / 256, Ln), 256>>>();
    k_fillBi<<<dim3(Ln / 256, NF), 256>>>();
    k_wT<<<(CIN * CIN * 3 + 255) / 256, 256>>>(conv_w);

    // forward DFT: g_Xf[2048,512] = x[2048,16384] @ g_Bf
    k_gemm64<Ln / 16, false><<<dim3(NF / 64, BC / 64), 256>>>(x, nullptr, nullptr, nullptr);

    // complex head mixing
    k_mix<<<dim3(2, Hh, Bn), 128>>>(wre, wim);

    // conv branch staged into d_out
    k_conv<<<dim3(Ln / 128, Bn), 256, CIN * 130 * sizeof(float)>>>(x, conv_b, out);

    // inverse DFT + bias + gated blend with conv (reads+writes d_out)
    k_gemm64<NF / 16, true><<<dim3(Ln / 64, BC / 64), 256>>>(nullptr, out, bias, gate);
}

// round 6
// speedup vs baseline: 1.8117x; 1.8117x over previous
#include <cuda_runtime.h>
#include <cuda_bf16.h>
#include <cstdint>

typedef unsigned long long ull;

#define Bn     16
#define CIN    128
#define Hh     8
#define MODESn 256
#define Ln     16384
#define BC     (Bn*CIN)     // 2048
#define NF     (2*MODESn)   // 512
#define SPLITS 4

// ---------------- device scratch (no allocations allowed) -------------------
__device__ float2        g_sc[Ln];
__device__ __align__(16) __nv_bfloat16 g_Bf_h[(size_t)NF*Ln];   // fwd B [512,16384]
__device__ __align__(16) __nv_bfloat16 g_Bf_l[(size_t)NF*Ln];
__device__ __align__(16) __nv_bfloat16 g_Bi_h[(size_t)Ln*NF];   // inv B [16384,512]
__device__ __align__(16) __nv_bfloat16 g_Bi_l[(size_t)Ln*NF];
__device__ __align__(16) __nv_bfloat16 g_xs_h[(size_t)BC*Ln];   // fwd A [2048,16384]
__device__ __align__(16) __nv_bfloat16 g_xs_l[(size_t)BC*Ln];
__device__ float         g_XfP[(size_t)SPLITS*BC*NF];           // split-K partials
__device__ __align__(16) __nv_bfloat16 g_Ys_h[(size_t)BC*NF];   // inv A [2048,512]
__device__ __align__(16) __nv_bfloat16 g_Ys_l[(size_t)BC*NF];
__device__ float         g_wT[3*CIN*CIN];                       // conv w [ci][d][co]

// ---------------- ptx helpers -------------------------------------------------
__device__ __forceinline__ uint32_t smem_u32(const void* p) {
    uint32_t a;
    asm("{ .reg .u64 t; cvta.to.shared.u64 t, %1; cvt.u32.u64 %0, t; }" : "=r"(a) : "l"(p));
    return a;
}
__device__ __forceinline__ void cpa16(uint32_t sdst, const void* gsrc) {
    asm volatile("cp.async.cg.shared.global [%0], [%1], 16;" :: "r"(sdst), "l"(gsrc));
}
#define CP_COMMIT() asm volatile("cp.async.commit_group;" ::: "memory")
#define CP_WAIT1()  asm volatile("cp.async.wait_group 1;" ::: "memory")

__device__ __forceinline__ uint32_t lds32(uint32_t addr) {
    uint32_t v;
    asm volatile("ld.shared.b32 %0, [%1];" : "=r"(v) : "r"(addr));
    return v;
}
__device__ __forceinline__ void mma16816(float* c, const uint32_t* a,
                                         uint32_t b0, uint32_t b1) {
    asm volatile("mma.sync.aligned.m16n8k16.row.col.f32.bf16.bf16.f32 "
                 "{%0,%1,%2,%3}, {%4,%5,%6,%7}, {%8,%9}, {%0,%1,%2,%3};"
                 : "+f"(c[0]), "+f"(c[1]), "+f"(c[2]), "+f"(c[3])
                 : "r"(a[0]), "r"(a[1]), "r"(a[2]), "r"(a[3]), "r"(b0), "r"(b1));
}

// ---------------- packed f32x2 helpers (for conv) ----------------------------
__device__ __forceinline__ ull pk2(float v) {
    ull d; unsigned u = __float_as_uint(v);
    asm("mov.b64 %0, {%1, %2};" : "=l"(d) : "r"(u), "r"(u));
    return d;
}
__device__ __forceinline__ void upk(ull v, float& lo, float& hi) {
    unsigned a, b;
    asm("mov.b64 {%0, %1}, %2;" : "=r"(a), "=r"(b) : "l"(v));
    lo = __uint_as_float(a); hi = __uint_as_float(b);
}
__device__ __forceinline__ ull fma2(ull a, ull b, ull c) {
    ull d;
    asm("fma.rn.f32x2 %0, %1, %2, %3;" : "=l"(d) : "l"(a), "l"(b), "l"(c));
    return d;
}
__device__ __forceinline__ ull packmid(ull a, ull b) {
    unsigned a0, a1, b0, b1; ull r;
    asm("mov.b64 {%0, %1}, %2;" : "=r"(a0), "=r"(a1) : "l"(a));
    asm("mov.b64 {%0, %1}, %2;" : "=r"(b0), "=r"(b1) : "l"(b));
    asm("mov.b64 %0, {%1, %2};" : "=l"(r) : "r"(a1), "r"(b0));
    return r;
}
__device__ __forceinline__ void split2(float v, __nv_bfloat16& h, __nv_bfloat16& l) {
    h = __float2bfloat16(v);
    l = __float2bfloat16(v - __bfloat162float(h));
}

// ---------------- init kernels ------------------------------------------------
__global__ void k_sincos() {
    int j = blockIdx.x * 256 + threadIdx.x;
    float s, c;
    sincospif((float)j * (2.0f / Ln), &s, &c);
    g_sc[j] = make_float2(c, s);
}

__global__ void k_fillBf() {                       // [col=512 rows][K=16384]
    int n   = blockIdx.x * 256 + threadIdx.x;
    int col = blockIdx.y;
    int k   = col >> 1;
    float2 sc = g_sc[(k * n) & (Ln - 1)];
    const float inv = 1.0f / Ln;
    float v = (col & 1) ? (-sc.y * inv) : (sc.x * inv);
    __nv_bfloat16 h, l; split2(v, h, l);
    size_t idx = (size_t)col * Ln + n;
    g_Bf_h[idx] = h; g_Bf_l[idx] = l;
}

__global__ void k_fillBi() {                       // [n=16384 rows][K=512]
    int j = blockIdx.x * 256 + threadIdx.x;
    int n = blockIdx.y;
    int k = j >> 1;
    float2 sc = g_sc[(k * n) & (Ln - 1)];
    float ck = (k == 0) ? 1.0f : 2.0f;
    float v = (j & 1) ? (-ck * sc.y) : (ck * sc.x);
    __nv_bfloat16 h, l; split2(v, h, l);
    size_t idx = (size_t)n * NF + j;
    g_Bi_h[idx] = h; g_Bi_l[idx] = l;
}

__global__ void k_xsplit(const float* __restrict__ x) {
    size_t i4 = (size_t)blockIdx.x * 256 + threadIdx.x;
    float4 v = ((const float4*)x)[i4];
    __nv_bfloat16 h0,l0,h1,l1,h2,l2,h3,l3;
    split2(v.x,h0,l0); split2(v.y,h1,l1); split2(v.z,h2,l2); split2(v.w,h3,l3);
    size_t e = i4 * 4;
    g_xs_h[e]=h0; g_xs_h[e+1]=h1; g_xs_h[e+2]=h2; g_xs_h[e+3]=h3;
    g_xs_l[e]=l0; g_xs_l[e+1]=l1; g_xs_l[e+2]=l2; g_xs_l[e+3]=l3;
}

__global__ void k_wT(const float* __restrict__ w) {
    int idx = blockIdx.x * 256 + threadIdx.x;
    if (idx < CIN * CIN * 3) {
        int d = idx % 3; int t = idx / 3;
        int ci = t & 127; int co = t >> 7;
        g_wT[(ci * 3 + d) * CIN + co] = w[idx];
    }
}

// ---------------- mma.sync bf16 3-split GEMM ----------------------------------
// C[128,128] tile, BK=64, 8 warps (warp tile 32x64), cp.async double buffer.
// SMEM planes: 128 rows x 64 bf16, row stride 144B (pad -> conflict-free lds).
#define ROWB   144
#define PLANE  (128*ROWB)                // 18432
#define BUFSZ  (4*PLANE)                 // Ah,Al,Bh,Bl = 73728
#define TCSM   (2*BUFSZ + 1024)

template<bool EPI>
__global__ void __launch_bounds__(256, 1) k_tc(
    const __nv_bfloat16* __restrict__ Ah, const __nv_bfloat16* __restrict__ Al,
    const __nv_bfloat16* __restrict__ Bh, const __nv_bfloat16* __restrict__ Bl,
    int ldA, int ldB, int nChunks, int kSplit,
    float* __restrict__ C, size_t cPlane, int ldC,
    const float* __restrict__ bias, const float* __restrict__ gate)
{
    extern __shared__ char smraw[];
    const uint32_t smBase = (smem_u32(smraw) + 1023u) & ~1023u;

    const int tid  = threadIdx.x;
    const int lane = tid & 31;
    const int w    = tid >> 5;
    const int wm   = w & 3;              // 4 m-subtiles of 32
    const int wn   = w >> 2;             // 2 n-subtiles of 64
    const int mBase = blockIdx.x * 128;
    const int nBase = blockIdx.y * 128;
    const int kOff  = blockIdx.z * kSplit;

    const __nv_bfloat16* srcs[4] = {Ah, Al, Bh, Bl};

    const int sRow = tid >> 3;
    const int sC8  = tid & 7;

    const int g  = lane >> 2;            // 0..7
    const int t4 = (lane & 3) * 4;       // k-pair byte offset

    float c[2][8][4];
#pragma unroll
    for (int mt = 0; mt < 2; mt++)
#pragma unroll
        for (int nt = 0; nt < 8; nt++)
#pragma unroll
            for (int q = 0; q < 4; q++) c[mt][nt][q] = 0.f;

    auto loadStage = [&](int st) {
        const int buf = st & 1;
        const int kB  = kOff + st * 64;
        const uint32_t bufBase = smBase + buf * BUFSZ;
#pragma unroll
        for (int p = 0; p < 4; ++p) {
            const __nv_bfloat16* src = srcs[p];
            const int rB = (p < 2) ? mBase : nBase;
            const int ld = (p < 2) ? ldA : ldB;
            const __nv_bfloat16* g0 = src + (size_t)(rB + sRow) * ld + kB + sC8 * 8;
            const uint32_t d0 = bufBase + p * PLANE + sRow * ROWB + sC8 * 16;
#pragma unroll
            for (int i = 0; i < 4; ++i)
                cpa16(d0 + i * 32 * ROWB, g0 + (size_t)(32 * i) * ld);
        }
    };

    loadStage(0); CP_COMMIT();
    if (nChunks > 1) loadStage(1);
    CP_COMMIT();

#pragma unroll 1
    for (int ch = 0; ch < nChunks; ++ch) {
        CP_WAIT1();
        __syncthreads();

        const uint32_t bufBase = smBase + (ch & 1) * BUFSZ;

#pragma unroll
        for (int k16 = 0; k16 < 4; ++k16) {
            const uint32_t kb = (uint32_t)(k16 * 32 + t4);
            uint32_t ah[2][4], al[2][4], bh[4][4], bl[4][4];

#pragma unroll
            for (int mt = 0; mt < 2; ++mt) {
                const uint32_t rA = bufBase + (wm * 32 + mt * 16 + g) * ROWB + kb;
                ah[mt][0] = lds32(rA);
                ah[mt][1] = lds32(rA + 8 * ROWB);
                ah[mt][2] = lds32(rA + 16);
                ah[mt][3] = lds32(rA + 8 * ROWB + 16);
                const uint32_t rAl = rA + PLANE;
                al[mt][0] = lds32(rAl);
                al[mt][1] = lds32(rAl + 8 * ROWB);
                al[mt][2] = lds32(rAl + 16);
                al[mt][3] = lds32(rAl + 8 * ROWB + 16);
            }
#pragma unroll
            for (int pr = 0; pr < 4; ++pr) {
                const uint32_t rB0 = bufBase + 2 * PLANE + (wn * 64 + pr * 16 + g) * ROWB + kb;
                bh[pr][0] = lds32(rB0);
                bh[pr][1] = lds32(rB0 + 16);
                bh[pr][2] = lds32(rB0 + 8 * ROWB);
                bh[pr][3] = lds32(rB0 + 8 * ROWB + 16);
                const uint32_t rBl = rB0 + PLANE;
                bl[pr][0] = lds32(rBl);
                bl[pr][1] = lds32(rBl + 16);
                bl[pr][2] = lds32(rBl + 8 * ROWB);
                bl[pr][3] = lds32(rBl + 8 * ROWB + 16);
            }
#pragma unroll
            for (int mt = 0; mt < 2; ++mt)
#pragma unroll
                for (int nt = 0; nt < 8; ++nt) {
                    const int pr = nt >> 1, hf = (nt & 1) * 2;
                    mma16816(c[mt][nt], ah[mt], bh[pr][hf], bh[pr][hf + 1]);
                    mma16816(c[mt][nt], ah[mt], bl[pr][hf], bl[pr][hf + 1]);
                    mma16816(c[mt][nt], al[mt], bh[pr][hf], bh[pr][hf + 1]);
                }
        }
        __syncthreads();
        if (ch + 2 < nChunks) loadStage(ch + 2);
        CP_COMMIT();
    }

    float gg = 0.f, og = 0.f;
    if (EPI) { gg = 1.0f / (1.0f + expf(-gate[0])); og = 1.0f - gg; }
    float* Cz = C + (size_t)blockIdx.z * cPlane;
#pragma unroll
    for (int mt = 0; mt < 2; ++mt) {
        const int r0 = mBase + wm * 32 + mt * 16 + g;
        float bv0 = 0.f, bv1 = 0.f;
        if (EPI) { bv0 = bias[r0 & (CIN - 1)]; bv1 = bias[(r0 + 8) & (CIN - 1)]; }
#pragma unroll
        for (int nt = 0; nt < 8; ++nt) {
            const int cc = nBase + wn * 64 + nt * 8 + (lane & 3) * 2;
            float* p0 = Cz + (size_t)r0 * ldC + cc;
            float* p1 = Cz + (size_t)(r0 + 8) * ldC + cc;
            if (EPI) {
                float2 o0 = *(const float2*)p0;
                float2 o1 = *(const float2*)p1;
                *(float2*)p0 = make_float2(gg * (c[mt][nt][0] + bv0) + og * o0.x,
                                           gg * (c[mt][nt][1] + bv0) + og * o0.y);
                *(float2*)p1 = make_float2(gg * (c[mt][nt][2] + bv1) + og * o1.x,
                                           gg * (c[mt][nt][3] + bv1) + og * o1.y);
            } else {
                *(float2*)p0 = make_float2(c[mt][nt][0], c[mt][nt][1]);
                *(float2*)p1 = make_float2(c[mt][nt][2], c[mt][nt][3]);
            }
        }
    }
}

// ---------------- per-mode complex 16x16 head mixing ---------------------------
__global__ void __launch_bounds__(128) k_mix(const float* __restrict__ wre,
                                             const float* __restrict__ wim) {
    const int kc = blockIdx.x;
    const int h  = blockIdx.y;
    const int b  = blockIdx.z;
    const int kg = kc * 128 + threadIdx.x;
    const size_t PL = (size_t)BC * NF;

    float xr[16], xi[16];
#pragma unroll
    for (int i = 0; i < 16; i++) {
        size_t off = ((size_t)(b * CIN + h * 16 + i) * NF) + 2 * kg;
        float sr = 0.f, si = 0.f;
#pragma unroll
        for (int s = 0; s < SPLITS; s++) {
            float2 v = *(const float2*)&g_XfP[s * PL + off];
            sr += v.x; si += v.y;
        }
        xr[i] = sr; xi[i] = si;
    }
#pragma unroll 1
    for (int o = 0; o < 16; o++) {
        float ar = 0.f, ai = 0.f;
#pragma unroll
        for (int i = 0; i < 16; i++) {
            int widx = ((h * 16 + i) * 16 + o) * MODESn + kg;
            float wr = wre[widx], wi = wim[widx];
            ar = fmaf(xr[i], wr, ar);
            ar = fmaf(-xi[i], wi, ar);
            ai = fmaf(xr[i], wi, ai);
            ai = fmaf(xi[i], wr, ai);
        }
        size_t off = ((size_t)(b * CIN + h * 16 + o) * NF) + 2 * kg;
        __nv_bfloat16 hh, ll;
        split2(ar, hh, ll); g_Ys_h[off] = hh;     g_Ys_l[off] = ll;
        split2(ai, hh, ll); g_Ys_h[off + 1] = hh; g_Ys_l[off + 1] = ll;
    }
}

// ---------------- conv1d(k=3, SAME) + conv_b -> d_out (fp32 f32x2) ------------
__global__ void __launch_bounds__(256) k_conv(const float* __restrict__ x,
                                              const float* __restrict__ cb,
                                              float* __restrict__ out) {
    extern __shared__ float Xs[];                    // 128*130 floats
    const int b  = blockIdx.y;
    const int n0 = blockIdx.x * 128;
    const int tid = threadIdx.x;
    const float* xb = x + (size_t)b * CIN * Ln;

    for (int idx = tid; idx < CIN * 130; idx += 256) {
        int ci = idx / 130;
        int j  = idx - ci * 130;
        int n  = n0 - 1 + j;
        Xs[idx] = ((unsigned)n < (unsigned)Ln) ? xb[(size_t)ci * Ln + n] : 0.f;
    }
    __syncthreads();

    const int co   = tid & 127;
    const int base = (tid >> 7) * 64;

    ull acc[32];
#pragma unroll
    for (int m = 0; m < 32; m++) acc[m] = 0ULL;

#pragma unroll 1
    for (int ci = 0; ci < CIN; ci++) {
        const float* wp = g_wT + ci * 3 * CIN + co;
        ull w0 = pk2(wp[0]), w1 = pk2(wp[CIN]), w2 = pk2(wp[2 * CIN]);
        const float* xr = Xs + ci * 130 + base;
        ull e = *(const ull*)xr;
#pragma unroll
        for (int m = 0; m < 32; m++) {
            ull e2 = *(const ull*)(xr + 2 * m + 2);
            ull md = packmid(e, e2);
            acc[m] = fma2(w0, e, acc[m]);
            acc[m] = fma2(w1, md, acc[m]);
            acc[m] = fma2(w2, e2, acc[m]);
            e = e2;
        }
    }
    __syncthreads();

    const float bv = cb[co];
#pragma unroll
    for (int m = 0; m < 32; m++) {
        float lo, hi; upk(acc[m], lo, hi);
        Xs[co * 130 + base + 2 * m]     = lo + bv;
        Xs[co * 130 + base + 2 * m + 1] = hi + bv;
    }
    __syncthreads();

    float* ob = out + (size_t)b * CIN * Ln + n0;
    for (int idx = tid; idx < CIN * 128; idx += 256) {
        int c = idx >> 7;
        int n = idx & 127;
        ob[(size_t)c * Ln + n] = Xs[c * 130 + n];
    }
}

// ---------------- launch --------------------------------------------------------
extern "C" void kernel_launch(void* const* d_in, const int* in_sizes, int n_in,
                              void* d_out, int out_size) {
    const float* x      = (const float*)d_in[0];
    const float* wre    = (const float*)d_in[1];
    const float* wim    = (const float*)d_in[2];
    const float* bias   = (const float*)d_in[3];
    const float* conv_w = (const float*)d_in[4];
    const float* conv_b = (const float*)d_in[5];
    const float* gate   = (const float*)d_in[6];
    float* out = (float*)d_out;

    // Resolve REAL device addresses of __device__ scratch (host-side symbol
    // names are host shadows — dereferenceable via ATS but wrong memory!).
    void *p_xs_h, *p_xs_l, *p_Bf_h, *p_Bf_l, *p_Bi_h, *p_Bi_l,
         *p_XfP, *p_Ys_h, *p_Ys_l;
    cudaGetSymbolAddress(&p_xs_h, g_xs_h);
    cudaGetSymbolAddress(&p_xs_l, g_xs_l);
    cudaGetSymbolAddress(&p_Bf_h, g_Bf_h);
    cudaGetSymbolAddress(&p_Bf_l, g_Bf_l);
    cudaGetSymbolAddress(&p_Bi_h, g_Bi_h);
    cudaGetSymbolAddress(&p_Bi_l, g_Bi_l);
    cudaGetSymbolAddress(&p_XfP, g_XfP);
    cudaGetSymbolAddress(&p_Ys_h, g_Ys_h);
    cudaGetSymbolAddress(&p_Ys_l, g_Ys_l);

    cudaFuncSetAttribute(k_conv, cudaFuncAttributeMaxDynamicSharedMemorySize,
                         CIN * 130 * sizeof(float));
    cudaFuncSetAttribute(k_tc<false>, cudaFuncAttributeMaxDynamicSharedMemorySize, TCSM);
    cudaFuncSetAttribute(k_tc<true>,  cudaFuncAttributeMaxDynamicSharedMemorySize, TCSM);

    // prep
    k_sincos<<<Ln / 256, 256>>>();
    k_fillBf<<<dim3(Ln / 256, NF), 256>>>();
    k_fillBi<<<dim3(NF / 256, Ln), 256>>>();
    k_xsplit<<<(BC * Ln / 4) / 256, 256>>>(x);
    k_wT<<<(CIN * CIN * 3 + 255) / 256, 256>>>(conv_w);

    // forward DFT (split-K=4): g_XfP[s] = xs @ Bf^T
    k_tc<false><<<dim3(BC / 128, NF / 128, SPLITS), 256, TCSM>>>(
        (const __nv_bfloat16*)p_xs_h, (const __nv_bfloat16*)p_xs_l,
        (const __nv_bfloat16*)p_Bf_h, (const __nv_bfloat16*)p_Bf_l,
        Ln, Ln, (Ln / SPLITS) / 64, Ln / SPLITS,
        (float*)p_XfP, (size_t)BC * NF, NF, nullptr, nullptr);

    // complex head mixing (+ split-K reduce, bf16-split Y)
    k_mix<<<dim3(2, Hh, Bn), 128>>>(wre, wim);

    // conv branch staged into d_out
    k_conv<<<dim3(Ln / 128, Bn), 256, CIN * 130 * sizeof(float)>>>(x, conv_b, out);

    // inverse DFT + bias + gated blend with conv
    k_tc<true><<<dim3(BC / 128, Ln / 128, 1), 256, TCSM>>>(
        (const __nv_bfloat16*)p_Ys_h, (const __nv_bfloat16*)p_Ys_l,
        (const __nv_bfloat16*)p_Bi_h, (const __nv_bfloat16*)p_Bi_l,
        NF, NF, NF / 64, 0,
        out, 0, Ln, bias, gate);
}

// round 7
// speedup vs baseline: 2.4225x; 1.3372x over previous
#include <cuda_runtime.h>
#include <cuda_bf16.h>
#include <cstdint>

typedef unsigned long long ull;

#define Bn     16
#define CIN    128
#define Hh     8
#define MODESn 256
#define Ln     16384
#define BC     (Bn*CIN)     // 2048
#define NF     (2*MODESn)   // 512
#define SPLITS 4
#define XTROWS 16386        // 1 zero row + 16384 + 1 zero row
#define KC     384          // conv GEMM K = 3*128

// ---------------- device scratch (no allocations allowed) -------------------
__device__ float2        g_sc[Ln];
__device__ __align__(16) __nv_bfloat16 g_Bf_h[(size_t)NF*Ln];   // fwd B [512,16384]
__device__ __align__(16) __nv_bfloat16 g_Bf_l[(size_t)NF*Ln];
__device__ __align__(16) __nv_bfloat16 g_Bi_h[(size_t)Ln*NF];   // inv B [16384,512]
__device__ __align__(16) __nv_bfloat16 g_Bi_l[(size_t)Ln*NF];
__device__ __align__(16) __nv_bfloat16 g_xs_h[(size_t)BC*Ln];   // fwd A [2048,16384]
__device__ __align__(16) __nv_bfloat16 g_xs_l[(size_t)BC*Ln];
__device__ float         g_XfP[(size_t)SPLITS*BC*NF];           // split-K partials
__device__ __align__(16) __nv_bfloat16 g_Ys_h[(size_t)BC*NF];   // inv A [2048,512]
__device__ __align__(16) __nv_bfloat16 g_Ys_l[(size_t)BC*NF];
// conv: padded transposed x [b][16386 rows][128 ci]; rows 0 & 16385 stay zero
__device__ __align__(16) __nv_bfloat16 g_xT_h[(size_t)Bn*XTROWS*CIN];
__device__ __align__(16) __nv_bfloat16 g_xT_l[(size_t)Bn*XTROWS*CIN];
__device__ __align__(16) __nv_bfloat16 g_Wk_h[CIN*KC];          // conv w [co][d*128+ci]
__device__ __align__(16) __nv_bfloat16 g_Wk_l[CIN*KC];

// ---------------- ptx helpers -------------------------------------------------
__device__ __forceinline__ uint32_t smem_u32(const void* p) {
    uint32_t a;
    asm("{ .reg .u64 t; cvta.to.shared.u64 t, %1; cvt.u32.u64 %0, t; }" : "=r"(a) : "l"(p));
    return a;
}
__device__ __forceinline__ void cpa16(uint32_t sdst, const void* gsrc) {
    asm volatile("cp.async.cg.shared.global [%0], [%1], 16;" :: "r"(sdst), "l"(gsrc));
}
#define CP_COMMIT() asm volatile("cp.async.commit_group;" ::: "memory")
#define CP_WAIT1()  asm volatile("cp.async.wait_group 1;" ::: "memory")

__device__ __forceinline__ uint32_t lds32(uint32_t addr) {
    uint32_t v;
    asm volatile("ld.shared.b32 %0, [%1];" : "=r"(v) : "r"(addr));
    return v;
}
__device__ __forceinline__ void mma16816(float* c, const uint32_t* a,
                                         uint32_t b0, uint32_t b1) {
    asm volatile("mma.sync.aligned.m16n8k16.row.col.f32.bf16.bf16.f32 "
                 "{%0,%1,%2,%3}, {%4,%5,%6,%7}, {%8,%9}, {%0,%1,%2,%3};"
                 : "+f"(c[0]), "+f"(c[1]), "+f"(c[2]), "+f"(c[3])
                 : "r"(a[0]), "r"(a[1]), "r"(a[2]), "r"(a[3]), "r"(b0), "r"(b1));
}
__device__ __forceinline__ void split2(float v, __nv_bfloat16& h, __nv_bfloat16& l) {
    h = __float2bfloat16(v);
    l = __float2bfloat16(v - __bfloat162float(h));
}

// ---------------- init kernels ------------------------------------------------
__global__ void k_sincos() {
    int j = blockIdx.x * 256 + threadIdx.x;
    float s, c;
    sincospif((float)j * (2.0f / Ln), &s, &c);
    g_sc[j] = make_float2(c, s);
}

__global__ void k_fillBf() {                       // [col=512 rows][K=16384]
    int n   = blockIdx.x * 256 + threadIdx.x;
    int col = blockIdx.y;
    int k   = col >> 1;
    float2 sc = g_sc[(k * n) & (Ln - 1)];
    const float inv = 1.0f / Ln;
    float v = (col & 1) ? (-sc.y * inv) : (sc.x * inv);
    __nv_bfloat16 h, l; split2(v, h, l);
    size_t idx = (size_t)col * Ln + n;
    g_Bf_h[idx] = h; g_Bf_l[idx] = l;
}

__global__ void k_fillBi() {                       // [n=16384 rows][K=512]
    int j = blockIdx.x * 256 + threadIdx.x;
    int n = blockIdx.y;
    int k = j >> 1;
    float2 sc = g_sc[(k * n) & (Ln - 1)];
    float ck = (k == 0) ? 1.0f : 2.0f;
    float v = (j & 1) ? (-ck * sc.y) : (ck * sc.x);
    __nv_bfloat16 h, l; split2(v, h, l);
    size_t idx = (size_t)n * NF + j;
    g_Bi_h[idx] = h; g_Bi_l[idx] = l;
}

__global__ void k_xsplit(const float* __restrict__ x) {
    size_t i4 = (size_t)blockIdx.x * 256 + threadIdx.x;
    float4 v = ((const float4*)x)[i4];
    __nv_bfloat16 h0,l0,h1,l1,h2,l2,h3,l3;
    split2(v.x,h0,l0); split2(v.y,h1,l1); split2(v.z,h2,l2); split2(v.w,h3,l3);
    size_t e = i4 * 4;
    g_xs_h[e]=h0; g_xs_h[e+1]=h1; g_xs_h[e+2]=h2; g_xs_h[e+3]=h3;
    g_xs_l[e]=l0; g_xs_l[e+1]=l1; g_xs_l[e+2]=l2; g_xs_l[e+3]=l3;
}

// transpose x[b][ci][n] -> xT[b][1+n][ci] (bf16 split planes)
__global__ void __launch_bounds__(256) k_xT(const float* __restrict__ x) {
    __shared__ float tile[32][33];
    const int b   = blockIdx.z;
    const int ciB = blockIdx.y * 32;
    const int nB  = blockIdx.x * 32;
    const int tx = threadIdx.x, ty = threadIdx.y;     // 32 x 8

#pragma unroll
    for (int j = 0; j < 4; ++j) {
        int ci = ciB + ty + j * 8;
        tile[ty + j * 8][tx] = x[((size_t)b * CIN + ci) * Ln + nB + tx];
    }
    __syncthreads();
#pragma unroll
    for (int j = 0; j < 4; ++j) {
        int nl = ty + j * 8;
        float v = tile[tx][nl];
        __nv_bfloat16 h, l; split2(v, h, l);
        size_t off = ((size_t)b * XTROWS + 1 + nB + nl) * CIN + ciB + tx;
        g_xT_h[off] = h; g_xT_l[off] = l;
    }
}

// conv weights -> Wk[co][d*128+ci] bf16 split
__global__ void k_wk(const float* __restrict__ w) {
    int idx = blockIdx.x * 256 + threadIdx.x;        // co*384 + d*128 + ci
    if (idx < CIN * KC) {
        int co = idx / KC;
        int r  = idx - co * KC;
        int d  = r >> 7;
        int ci = r & 127;
        float v = w[(co * CIN + ci) * 3 + d];
        __nv_bfloat16 h, l; split2(v, h, l);
        g_Wk_h[idx] = h; g_Wk_l[idx] = l;
    }
}

// ---------------- mma.sync bf16 3-split GEMM ----------------------------------
// C[128,128] tile, BK=64, 8 warps (warp tile 32x64), cp.async double buffer.
// SMEM planes: 128 rows x 64 bf16, row stride 144B (conflict-free lds).
// MODE 0: C[z] = A@B^T (fwd, z = k-split)
// MODE 1: C = g*(A@B^T + bias[m&127]) + (1-g)*C (inv blend)
// MODE 2: C[z] = A@B[z]^T + bias[m&127] (conv; z = batch, B has bPlane stride)
#define ROWB   144
#define PLANE  (128*ROWB)                // 18432
#define BUFSZ  (4*PLANE)                 // 73728
#define TCSM   (2*BUFSZ + 1024)

template<int MODE>
__global__ void __launch_bounds__(256, 1) k_tc(
    const __nv_bfloat16* __restrict__ Ah, const __nv_bfloat16* __restrict__ Al,
    const __nv_bfloat16* __restrict__ Bh, const __nv_bfloat16* __restrict__ Bl,
    int ldA, int ldB, int nChunks, int kSplit, size_t bPlane,
    float* __restrict__ C, size_t cPlane, int ldC,
    const float* __restrict__ bias, const float* __restrict__ gate)
{
    extern __shared__ char smraw[];
    const uint32_t smBase = (smem_u32(smraw) + 1023u) & ~1023u;

    const int tid  = threadIdx.x;
    const int lane = tid & 31;
    const int w    = tid >> 5;
    const int wm   = w & 3;
    const int wn   = w >> 2;
    const int mBase = blockIdx.x * 128;
    const int nBase = blockIdx.y * 128;
    const int kOff  = blockIdx.z * kSplit;

    Bh += (size_t)blockIdx.z * bPlane;
    Bl += (size_t)blockIdx.z * bPlane;
    const __nv_bfloat16* srcs[4] = {Ah, Al, Bh, Bl};

    const int sRow = tid >> 3;
    const int sC8  = tid & 7;

    const int g  = lane >> 2;
    const int t4 = (lane & 3) * 4;

    float c[2][8][4];
#pragma unroll
    for (int mt = 0; mt < 2; mt++)
#pragma unroll
        for (int nt = 0; nt < 8; nt++)
#pragma unroll
            for (int q = 0; q < 4; q++) c[mt][nt][q] = 0.f;

    auto loadStage = [&](int st) {
        const int buf = st & 1;
        const int kB  = kOff + st * 64;
        const uint32_t bufBase = smBase + buf * BUFSZ;
#pragma unroll
        for (int p = 0; p < 4; ++p) {
            const __nv_bfloat16* src = srcs[p];
            const int rB = (p < 2) ? mBase : nBase;
            const int ld = (p < 2) ? ldA : ldB;
            const __nv_bfloat16* g0 = src + (size_t)(rB + sRow) * ld + kB + sC8 * 8;
            const uint32_t d0 = bufBase + p * PLANE + sRow * ROWB + sC8 * 16;
#pragma unroll
            for (int i = 0; i < 4; ++i)
                cpa16(d0 + i * 32 * ROWB, g0 + (size_t)(32 * i) * ld);
        }
    };

    loadStage(0); CP_COMMIT();
    if (nChunks > 1) loadStage(1);
    CP_COMMIT();

#pragma unroll 1
    for (int ch = 0; ch < nChunks; ++ch) {
        CP_WAIT1();
        __syncthreads();

        const uint32_t bufBase = smBase + (ch & 1) * BUFSZ;

#pragma unroll
        for (int k16 = 0; k16 < 4; ++k16) {
            const uint32_t kb = (uint32_t)(k16 * 32 + t4);
            uint32_t ah[2][4], al[2][4], bh[4][4], bl[4][4];

#pragma unroll
            for (int mt = 0; mt < 2; ++mt) {
                const uint32_t rA = bufBase + (wm * 32 + mt * 16 + g) * ROWB + kb;
                ah[mt][0] = lds32(rA);
                ah[mt][1] = lds32(rA + 8 * ROWB);
                ah[mt][2] = lds32(rA + 16);
                ah[mt][3] = lds32(rA + 8 * ROWB + 16);
                const uint32_t rAl = rA + PLANE;
                al[mt][0] = lds32(rAl);
                al[mt][1] = lds32(rAl + 8 * ROWB);
                al[mt][2] = lds32(rAl + 16);
                al[mt][3] = lds32(rAl + 8 * ROWB + 16);
            }
#pragma unroll
            for (int pr = 0; pr < 4; ++pr) {
                const uint32_t rB0 = bufBase + 2 * PLANE + (wn * 64 + pr * 16 + g) * ROWB + kb;
                bh[pr][0] = lds32(rB0);
                bh[pr][1] = lds32(rB0 + 16);
                bh[pr][2] = lds32(rB0 + 8 * ROWB);
                bh[pr][3] = lds32(rB0 + 8 * ROWB + 16);
                const uint32_t rBl = rB0 + PLANE;
                bl[pr][0] = lds32(rBl);
                bl[pr][1] = lds32(rBl + 16);
                bl[pr][2] = lds32(rBl + 8 * ROWB);
                bl[pr][3] = lds32(rBl + 8 * ROWB + 16);
            }
#pragma unroll
            for (int mt = 0; mt < 2; ++mt)
#pragma unroll
                for (int nt = 0; nt < 8; ++nt) {
                    const int pr = nt >> 1, hf = (nt & 1) * 2;
                    mma16816(c[mt][nt], ah[mt], bh[pr][hf], bh[pr][hf + 1]);
                    mma16816(c[mt][nt], ah[mt], bl[pr][hf], bl[pr][hf + 1]);
                    mma16816(c[mt][nt], al[mt], bh[pr][hf], bh[pr][hf + 1]);
                }
        }
        __syncthreads();
        if (ch + 2 < nChunks) loadStage(ch + 2);
        CP_COMMIT();
    }

    float gg = 0.f, og = 0.f;
    if (MODE == 1) { gg = 1.0f / (1.0f + expf(-gate[0])); og = 1.0f - gg; }
    float* Cz = C + (size_t)blockIdx.z * cPlane;
#pragma unroll
    for (int mt = 0; mt < 2; ++mt) {
        const int r0 = mBase + wm * 32 + mt * 16 + g;
        float bv0 = 0.f, bv1 = 0.f;
        if (MODE != 0) { bv0 = bias[r0 & (CIN - 1)]; bv1 = bias[(r0 + 8) & (CIN - 1)]; }
#pragma unroll
        for (int nt = 0; nt < 8; ++nt) {
            const int cc = nBase + wn * 64 + nt * 8 + (lane & 3) * 2;
            float* p0 = Cz + (size_t)r0 * ldC + cc;
            float* p1 = Cz + (size_t)(r0 + 8) * ldC + cc;
            if (MODE == 1) {
                float2 o0 = *(const float2*)p0;
                float2 o1 = *(const float2*)p1;
                *(float2*)p0 = make_float2(gg * (c[mt][nt][0] + bv0) + og * o0.x,
                                           gg * (c[mt][nt][1] + bv0) + og * o0.y);
                *(float2*)p1 = make_float2(gg * (c[mt][nt][2] + bv1) + og * o1.x,
                                           gg * (c[mt][nt][3] + bv1) + og * o1.y);
            } else if (MODE == 2) {
                *(float2*)p0 = make_float2(c[mt][nt][0] + bv0, c[mt][nt][1] + bv0);
                *(float2*)p1 = make_float2(c[mt][nt][2] + bv1, c[mt][nt][3] + bv1);
            } else {
                *(float2*)p0 = make_float2(c[mt][nt][0], c[mt][nt][1]);
                *(float2*)p1 = make_float2(c[mt][nt][2], c[mt][nt][3]);
            }
        }
    }
}

// ---------------- per-mode complex 16x16 head mixing ---------------------------
__global__ void __launch_bounds__(128) k_mix(const float* __restrict__ wre,
                                             const float* __restrict__ wim) {
    const int kc = blockIdx.x;
    const int h  = blockIdx.y;
    const int b  = blockIdx.z;
    const int kg = kc * 128 + threadIdx.x;
    const size_t PL = (size_t)BC * NF;

    float xr[16], xi[16];
#pragma unroll
    for (int i = 0; i < 16; i++) {
        size_t off = ((size_t)(b * CIN + h * 16 + i) * NF) + 2 * kg;
        float sr = 0.f, si = 0.f;
#pragma unroll
        for (int s = 0; s < SPLITS; s++) {
            float2 v = *(const float2*)&g_XfP[s * PL + off];
            sr += v.x; si += v.y;
        }
        xr[i] = sr; xi[i] = si;
    }
#pragma unroll 1
    for (int o = 0; o < 16; o++) {
        float ar = 0.f, ai = 0.f;
#pragma unroll
        for (int i = 0; i < 16; i++) {
            int widx = ((h * 16 + i) * 16 + o) * MODESn + kg;
            float wr = wre[widx], wi = wim[widx];
            ar = fmaf(xr[i], wr, ar);
            ar = fmaf(-xi[i], wi, ar);
            ai = fmaf(xr[i], wi, ai);
            ai = fmaf(xi[i], wr, ai);
        }
        size_t off = ((size_t)(b * CIN + h * 16 + o) * NF) + 2 * kg;
        __nv_bfloat16 hh, ll;
        split2(ar, hh, ll); g_Ys_h[off] = hh;     g_Ys_l[off] = ll;
        split2(ai, hh, ll); g_Ys_h[off + 1] = hh; g_Ys_l[off + 1] = ll;
    }
}

// ---------------- launch --------------------------------------------------------
extern "C" void kernel_launch(void* const* d_in, const int* in_sizes, int n_in,
                              void* d_out, int out_size) {
    const float* x      = (const float*)d_in[0];
    const float* wre    = (const float*)d_in[1];
    const float* wim    = (const float*)d_in[2];
    const float* bias   = (const float*)d_in[3];
    const float* conv_w = (const float*)d_in[4];
    const float* conv_b = (const float*)d_in[5];
    const float* gate   = (const float*)d_in[6];
    float* out = (float*)d_out;

    // Resolve REAL device addresses of __device__ scratch (host shadows are
    // ATS-dereferenceable host memory — NOT the device arrays).
    void *p_xs_h, *p_xs_l, *p_Bf_h, *p_Bf_l, *p_Bi_h, *p_Bi_l,
         *p_XfP, *p_Ys_h, *p_Ys_l, *p_xT_h, *p_xT_l, *p_Wk_h, *p_Wk_l;
    cudaGetSymbolAddress(&p_xs_h, g_xs_h);
    cudaGetSymbolAddress(&p_xs_l, g_xs_l);
    cudaGetSymbolAddress(&p_Bf_h, g_Bf_h);
    cudaGetSymbolAddress(&p_Bf_l, g_Bf_l);
    cudaGetSymbolAddress(&p_Bi_h, g_Bi_h);
    cudaGetSymbolAddress(&p_Bi_l, g_Bi_l);
    cudaGetSymbolAddress(&p_XfP, g_XfP);
    cudaGetSymbolAddress(&p_Ys_h, g_Ys_h);
    cudaGetSymbolAddress(&p_Ys_l, g_Ys_l);
    cudaGetSymbolAddress(&p_xT_h, g_xT_h);
    cudaGetSymbolAddress(&p_xT_l, g_xT_l);
    cudaGetSymbolAddress(&p_Wk_h, g_Wk_h);
    cudaGetSymbolAddress(&p_Wk_l, g_Wk_l);

    cudaFuncSetAttribute(k_tc<0>, cudaFuncAttributeMaxDynamicSharedMemorySize, TCSM);
    cudaFuncSetAttribute(k_tc<1>, cudaFuncAttributeMaxDynamicSharedMemorySize, TCSM);
    cudaFuncSetAttribute(k_tc<2>, cudaFuncAttributeMaxDynamicSharedMemorySize, TCSM);

    // prep
    k_sincos<<<Ln / 256, 256>>>();
    k_fillBf<<<dim3(Ln / 256, NF), 256>>>();
    k_fillBi<<<dim3(NF / 256, Ln), 256>>>();
    k_xsplit<<<(BC * Ln / 4) / 256, 256>>>(x);
    k_xT<<<dim3(Ln / 32, CIN / 32, Bn), dim3(32, 8)>>>(x);
    k_wk<<<(CIN * KC + 255) / 256, 256>>>(conv_w);

    // forward DFT (split-K=4): g_XfP[s] = xs @ Bf^T
    k_tc<0><<<dim3(BC / 128, NF / 128, SPLITS), 256, TCSM>>>(
        (const __nv_bfloat16*)p_xs_h, (const __nv_bfloat16*)p_xs_l,
        (const __nv_bfloat16*)p_Bf_h, (const __nv_bfloat16*)p_Bf_l,
        Ln, Ln, (Ln / SPLITS) / 64, Ln / SPLITS, 0,
        (float*)p_XfP, (size_t)BC * NF, NF, nullptr, nullptr);

    // complex head mixing (+ split-K reduce, bf16-split Y)
    k_mix<<<dim3(2, Hh, Bn), 128>>>(wre, wim);

    // conv branch as GEMM (tensor cores): out[b] = Wk @ xT[b]^T + conv_b
    k_tc<2><<<dim3(1, Ln / 128, Bn), 256, TCSM>>>(
        (const __nv_bfloat16*)p_Wk_h, (const __nv_bfloat16*)p_Wk_l,
        (const __nv_bfloat16*)p_xT_h, (const __nv_bfloat16*)p_xT_l,
        KC, CIN, KC / 64, 0, (size_t)XTROWS * CIN,
        out, (size_t)CIN * Ln, Ln, conv_b, nullptr);

    // inverse DFT + bias + gated blend with conv
    k_tc<1><<<dim3(BC / 128, Ln / 128, 1), 256, TCSM>>>(
        (const __nv_bfloat16*)p_Ys_h, (const __nv_bfloat16*)p_Ys_l,
        (const __nv_bfloat16*)p_Bi_h, (const __nv_bfloat16*)p_Bi_l,
        NF, NF, NF / 64, 0, 0,
        out, 0, Ln, bias, gate);
}

// round 8
// speedup vs baseline: 2.4401x; 1.0072x over previous
#include <cuda_runtime.h>
#include <cuda_bf16.h>
#include <cstdint>

typedef unsigned long long ull;

#define Bn     16
#define CIN    128
#define Hh     8
#define MODESn 256
#define Ln     16384
#define BC     (Bn*CIN)     // 2048
#define NF     (2*MODESn)   // 512
#define SPLITS 4
#define XTROWS 16386        // 1 zero row + 16384 + 1 zero row
#define KC     384          // conv GEMM K = 3*128

// ---------------- device scratch (no allocations allowed) -------------------
__device__ float2        g_sc[Ln];
__device__ __align__(16) __nv_bfloat16 g_Bf_h[(size_t)NF*Ln];   // fwd B [512,16384]
__device__ __align__(16) __nv_bfloat16 g_Bf_l[(size_t)NF*Ln];
__device__ __align__(16) __nv_bfloat16 g_Bi_h[(size_t)Ln*NF];   // inv B [16384,512]
__device__ __align__(16) __nv_bfloat16 g_Bi_l[(size_t)Ln*NF];
__device__ __align__(16) __nv_bfloat16 g_xs_h[(size_t)BC*Ln];   // fwd A [2048,16384]
__device__ __align__(16) __nv_bfloat16 g_xs_l[(size_t)BC*Ln];
__device__ float         g_XfP[(size_t)SPLITS*BC*NF];           // split-K partials
__device__ __align__(16) __nv_bfloat16 g_Ys_h[(size_t)BC*NF];   // inv A [2048,512]
__device__ __align__(16) __nv_bfloat16 g_Ys_l[(size_t)BC*NF];
// conv: padded transposed x [b][16386 rows][128 ci]; rows 0 & 16385 stay zero
__device__ __align__(16) __nv_bfloat16 g_xT_h[(size_t)Bn*XTROWS*CIN];
__device__ __align__(16) __nv_bfloat16 g_xT_l[(size_t)Bn*XTROWS*CIN];
__device__ __align__(16) __nv_bfloat16 g_Wk_h[CIN*KC];          // conv w [co][d*128+ci]
__device__ __align__(16) __nv_bfloat16 g_Wk_l[CIN*KC];

// ---------------- ptx helpers -------------------------------------------------
__device__ __forceinline__ uint32_t smem_u32(const void* p) {
    uint32_t a;
    asm("{ .reg .u64 t; cvta.to.shared.u64 t, %1; cvt.u32.u64 %0, t; }" : "=r"(a) : "l"(p));
    return a;
}
__device__ __forceinline__ void cpa16(uint32_t sdst, const void* gsrc) {
    asm volatile("cp.async.cg.shared.global [%0], [%1], 16;" :: "r"(sdst), "l"(gsrc));
}
#define CP_COMMIT() asm volatile("cp.async.commit_group;" ::: "memory")
#define CP_WAIT1()  asm volatile("cp.async.wait_group 1;" ::: "memory")

__device__ __forceinline__ void ldm4(uint32_t* r, uint32_t addr) {
    asm volatile("ldmatrix.sync.aligned.m8n8.x4.shared.b16 {%0,%1,%2,%3}, [%4];"
                 : "=r"(r[0]), "=r"(r[1]), "=r"(r[2]), "=r"(r[3]) : "r"(addr));
}
__device__ __forceinline__ void mma16816(float* c, const uint32_t* a,
                                         uint32_t b0, uint32_t b1) {
    asm volatile("mma.sync.aligned.m16n8k16.row.col.f32.bf16.bf16.f32 "
                 "{%0,%1,%2,%3}, {%4,%5,%6,%7}, {%8,%9}, {%0,%1,%2,%3};"
                 : "+f"(c[0]), "+f"(c[1]), "+f"(c[2]), "+f"(c[3])
                 : "r"(a[0]), "r"(a[1]), "r"(a[2]), "r"(a[3]), "r"(b0), "r"(b1));
}
__device__ __forceinline__ void split2(float v, __nv_bfloat16& h, __nv_bfloat16& l) {
    h = __float2bfloat16(v);
    l = __float2bfloat16(v - __bfloat162float(h));
}

// ---------------- init kernels ------------------------------------------------
__global__ void k_sincos() {
    int j = blockIdx.x * 256 + threadIdx.x;
    float s, c;
    sincospif((float)j * (2.0f / Ln), &s, &c);
    g_sc[j] = make_float2(c, s);
}

__global__ void k_fillBf() {                       // [col=512 rows][K=16384]
    int n   = blockIdx.x * 256 + threadIdx.x;
    int col = blockIdx.y;
    int k   = col >> 1;
    float2 sc = g_sc[(k * n) & (Ln - 1)];
    const float inv = 1.0f / Ln;
    float v = (col & 1) ? (-sc.y * inv) : (sc.x * inv);
    __nv_bfloat16 h, l; split2(v, h, l);
    size_t idx = (size_t)col * Ln + n;
    g_Bf_h[idx] = h; g_Bf_l[idx] = l;
}

__global__ void k_fillBi() {                       // [n=16384 rows][K=512]
    int j = blockIdx.x * 256 + threadIdx.x;
    int n = blockIdx.y;
    int k = j >> 1;
    float2 sc = g_sc[(k * n) & (Ln - 1)];
    float ck = (k == 0) ? 1.0f : 2.0f;
    float v = (j & 1) ? (-ck * sc.y) : (ck * sc.x);
    __nv_bfloat16 h, l; split2(v, h, l);
    size_t idx = (size_t)n * NF + j;
    g_Bi_h[idx] = h; g_Bi_l[idx] = l;
}

__global__ void k_xsplit(const float* __restrict__ x) {
    size_t i4 = (size_t)blockIdx.x * 256 + threadIdx.x;
    float4 v = ((const float4*)x)[i4];
    __nv_bfloat16 h0,l0,h1,l1,h2,l2,h3,l3;
    split2(v.x,h0,l0); split2(v.y,h1,l1); split2(v.z,h2,l2); split2(v.w,h3,l3);
    size_t e = i4 * 4;
    g_xs_h[e]=h0; g_xs_h[e+1]=h1; g_xs_h[e+2]=h2; g_xs_h[e+3]=h3;
    g_xs_l[e]=l0; g_xs_l[e+1]=l1; g_xs_l[e+2]=l2; g_xs_l[e+3]=l3;
}

// transpose x[b][ci][n] -> xT[b][1+n][ci] (bf16 split planes)
__global__ void __launch_bounds__(256) k_xT(const float* __restrict__ x) {
    __shared__ float tile[32][33];
    const int b   = blockIdx.z;
    const int ciB = blockIdx.y * 32;
    const int nB  = blockIdx.x * 32;
    const int tx = threadIdx.x, ty = threadIdx.y;     // 32 x 8

#pragma unroll
    for (int j = 0; j < 4; ++j) {
        int ci = ciB + ty + j * 8;
        tile[ty + j * 8][tx] = x[((size_t)b * CIN + ci) * Ln + nB + tx];
    }
    __syncthreads();
#pragma unroll
    for (int j = 0; j < 4; ++j) {
        int nl = ty + j * 8;
        float v = tile[tx][nl];
        __nv_bfloat16 h, l; split2(v, h, l);
        size_t off = ((size_t)b * XTROWS + 1 + nB + nl) * CIN + ciB + tx;
        g_xT_h[off] = h; g_xT_l[off] = l;
    }
}

// conv weights -> Wk[co][d*128+ci] bf16 split
__global__ void k_wk(const float* __restrict__ w) {
    int idx = blockIdx.x * 256 + threadIdx.x;        // co*384 + d*128 + ci
    if (idx < CIN * KC) {
        int co = idx / KC;
        int r  = idx - co * KC;
        int d  = r >> 7;
        int ci = r & 127;
        float v = w[(co * CIN + ci) * 3 + d];
        __nv_bfloat16 h, l; split2(v, h, l);
        g_Wk_h[idx] = h; g_Wk_l[idx] = l;
    }
}

// ---------------- mma.sync bf16 3-split GEMM ----------------------------------
// C[128,128] tile, BK=64, 8 warps (warp tile 32x64), cp.async double buffer.
// SMEM planes: 128 rows x 64 bf16, row stride 144B. Fragments via ldmatrix.x4
// (pad stride keeps all ldmatrix phases bank-conflict-free; no XOR needed).
// MODE 0: C[z] = A@B^T (fwd, z = k-split)
// MODE 1: C = g*(A@B^T + bias[m&127]) + (1-g)*C (inv blend)
// MODE 2: C[z] = A@B[z]^T + bias[m&127] (conv; z = batch, B has bPlane stride)
#define ROWB   144
#define PLANE  (128*ROWB)                // 18432
#define BUFSZ  (4*PLANE)                 // 73728
#define TCSM   (2*BUFSZ + 1024)

template<int MODE>
__global__ void __launch_bounds__(256, 1) k_tc(
    const __nv_bfloat16* __restrict__ Ah, const __nv_bfloat16* __restrict__ Al,
    const __nv_bfloat16* __restrict__ Bh, const __nv_bfloat16* __restrict__ Bl,
    int ldA, int ldB, int nChunks, int kSplit, size_t bPlane,
    float* __restrict__ C, size_t cPlane, int ldC,
    const float* __restrict__ bias, const float* __restrict__ gate)
{
    extern __shared__ char smraw[];
    const uint32_t smBase = (smem_u32(smraw) + 1023u) & ~1023u;

    const int tid  = threadIdx.x;
    const int lane = tid & 31;
    const int w    = tid >> 5;
    const int wm   = w & 3;
    const int wn   = w >> 2;
    const int mBase = blockIdx.x * 128;
    const int nBase = blockIdx.y * 128;
    const int kOff  = blockIdx.z * kSplit;

    Bh += (size_t)blockIdx.z * bPlane;
    Bl += (size_t)blockIdx.z * bPlane;
    const __nv_bfloat16* srcs[4] = {Ah, Al, Bh, Bl};

    const int sRow = tid >> 3;
    const int sC8  = tid & 7;

    const int g = lane >> 2;             // epilogue row group

    // ldmatrix.x4 per-lane source offsets (sel = lane>>3):
    //   A matrices: (m + 8*(sel&1)) rows, k + 16B*(sel>>1)
    //   B matrices: (n + 8*(sel>>1)) rows, k + 16B*(sel&1)
    const int lrow = lane & 7;
    const int sel0 = (lane >> 3) & 1;
    const int sel1 = (lane >> 4) & 1;
    const uint32_t aLane = (uint32_t)((lrow + sel0 * 8) * ROWB + sel1 * 16);
    const uint32_t bLane = (uint32_t)((lrow + sel1 * 8) * ROWB + sel0 * 16);

    float c[2][8][4];
#pragma unroll
    for (int mt = 0; mt < 2; mt++)
#pragma unroll
        for (int nt = 0; nt < 8; nt++)
#pragma unroll
            for (int q = 0; q < 4; q++) c[mt][nt][q] = 0.f;

    auto loadStage = [&](int st) {
        const int buf = st & 1;
        const int kB  = kOff + st * 64;
        const uint32_t bufBase = smBase + buf * BUFSZ;
#pragma unroll
        for (int p = 0; p < 4; ++p) {
            const __nv_bfloat16* src = srcs[p];
            const int rB = (p < 2) ? mBase : nBase;
            const int ld = (p < 2) ? ldA : ldB;
            const __nv_bfloat16* g0 = src + (size_t)(rB + sRow) * ld + kB + sC8 * 8;
            const uint32_t d0 = bufBase + p * PLANE + sRow * ROWB + sC8 * 16;
#pragma unroll
            for (int i = 0; i < 4; ++i)
                cpa16(d0 + i * 32 * ROWB, g0 + (size_t)(32 * i) * ld);
        }
    };

    loadStage(0); CP_COMMIT();
    if (nChunks > 1) loadStage(1);
    CP_COMMIT();

#pragma unroll 1
    for (int ch = 0; ch < nChunks; ++ch) {
        CP_WAIT1();
        __syncthreads();

        const uint32_t bufBase = smBase + (ch & 1) * BUFSZ;
        const uint32_t aBase = bufBase + (wm * 32) * ROWB + aLane;
        const uint32_t bBase = bufBase + 2 * PLANE + (wn * 64) * ROWB + bLane;

#pragma unroll
        for (int k16 = 0; k16 < 4; ++k16) {
            const uint32_t kb = (uint32_t)(k16 * 32);
            uint32_t ah[2][4], al[2][4], bh[4][4], bl[4][4];

#pragma unroll
            for (int mt = 0; mt < 2; ++mt) {
                const uint32_t rA = aBase + mt * 16 * ROWB + kb;
                ldm4(ah[mt], rA);
                ldm4(al[mt], rA + PLANE);
            }
#pragma unroll
            for (int pr = 0; pr < 4; ++pr) {
                const uint32_t rB0 = bBase + pr * 16 * ROWB + kb;
                ldm4(bh[pr], rB0);
                ldm4(bl[pr], rB0 + PLANE);
            }
#pragma unroll
            for (int mt = 0; mt < 2; ++mt)
#pragma unroll
                for (int nt = 0; nt < 8; ++nt) {
                    const int pr = nt >> 1, hf = (nt & 1) * 2;
                    mma16816(c[mt][nt], ah[mt], bh[pr][hf], bh[pr][hf + 1]);
                    mma16816(c[mt][nt], ah[mt], bl[pr][hf], bl[pr][hf + 1]);
                    mma16816(c[mt][nt], al[mt], bh[pr][hf], bh[pr][hf + 1]);
                }
        }
        __syncthreads();
        if (ch + 2 < nChunks) loadStage(ch + 2);
        CP_COMMIT();
    }

    float gg = 0.f, og = 0.f;
    if (MODE == 1) { gg = 1.0f / (1.0f + expf(-gate[0])); og = 1.0f - gg; }
    float* Cz = C + (size_t)blockIdx.z * cPlane;
#pragma unroll
    for (int mt = 0; mt < 2; ++mt) {
        const int r0 = mBase + wm * 32 + mt * 16 + g;
        float bv0 = 0.f, bv1 = 0.f;
        if (MODE != 0) { bv0 = bias[r0 & (CIN - 1)]; bv1 = bias[(r0 + 8) & (CIN - 1)]; }
#pragma unroll
        for (int nt = 0; nt < 8; ++nt) {
            const int cc = nBase + wn * 64 + nt * 8 + (lane & 3) * 2;
            float* p0 = Cz + (size_t)r0 * ldC + cc;
            float* p1 = Cz + (size_t)(r0 + 8) * ldC + cc;
            if (MODE == 1) {
                float2 o0 = *(const float2*)p0;
                float2 o1 = *(const float2*)p1;
                *(float2*)p0 = make_float2(gg * (c[mt][nt][0] + bv0) + og * o0.x,
                                           gg * (c[mt][nt][1] + bv0) + og * o0.y);
                *(float2*)p1 = make_float2(gg * (c[mt][nt][2] + bv1) + og * o1.x,
                                           gg * (c[mt][nt][3] + bv1) + og * o1.y);
            } else if (MODE == 2) {
                *(float2*)p0 = make_float2(c[mt][nt][0] + bv0, c[mt][nt][1] + bv0);
                *(float2*)p1 = make_float2(c[mt][nt][2] + bv1, c[mt][nt][3] + bv1);
            } else {
                *(float2*)p0 = make_float2(c[mt][nt][0], c[mt][nt][1]);
                *(float2*)p1 = make_float2(c[mt][nt][2], c[mt][nt][3]);
            }
        }
    }
}

// ---------------- per-mode complex 16x16 head mixing ---------------------------
__global__ void __launch_bounds__(128) k_mix(const float* __restrict__ wre,
                                             const float* __restrict__ wim) {
    const int kc = blockIdx.x;
    const int h  = blockIdx.y;
    const int b  = blockIdx.z;
    const int kg = kc * 128 + threadIdx.x;
    const size_t PL = (size_t)BC * NF;

    float xr[16], xi[16];
#pragma unroll
    for (int i = 0; i < 16; i++) {
        size_t off = ((size_t)(b * CIN + h * 16 + i) * NF) + 2 * kg;
        float sr = 0.f, si = 0.f;
#pragma unroll
        for (int s = 0; s < SPLITS; s++) {
            float2 v = *(const float2*)&g_XfP[s * PL + off];
            sr += v.x; si += v.y;
        }
        xr[i] = sr; xi[i] = si;
    }
#pragma unroll 1
    for (int o = 0; o < 16; o++) {
        float ar = 0.f, ai = 0.f;
#pragma unroll
        for (int i = 0; i < 16; i++) {
            int widx = ((h * 16 + i) * 16 + o) * MODESn + kg;
            float wr = wre[widx], wi = wim[widx];
            ar = fmaf(xr[i], wr, ar);
            ar = fmaf(-xi[i], wi, ar);
            ai = fmaf(xr[i], wi, ai);
            ai = fmaf(xi[i], wr, ai);
        }
        size_t off = ((size_t)(b * CIN + h * 16 + o) * NF) + 2 * kg;
        __nv_bfloat16 hh, ll;
        split2(ar, hh, ll); g_Ys_h[off] = hh;     g_Ys_l[off] = ll;
        split2(ai, hh, ll); g_Ys_h[off + 1] = hh; g_Ys_l[off + 1] = ll;
    }
}

// ---------------- launch --------------------------------------------------------
extern "C" void kernel_launch(void* const* d_in, const int* in_sizes, int n_in,
                              void* d_out, int out_size) {
    const float* x      = (const float*)d_in[0];
    const float* wre    = (const float*)d_in[1];
    const float* wim    = (const float*)d_in[2];
    const float* bias   = (const float*)d_in[3];
    const float* conv_w = (const float*)d_in[4];
    const float* conv_b = (const float*)d_in[5];
    const float* gate   = (const float*)d_in[6];
    float* out = (float*)d_out;

    // Resolve REAL device addresses of __device__ scratch (host shadows are
    // ATS-dereferenceable host memory — NOT the device arrays).
    void *p_xs_h, *p_xs_l, *p_Bf_h, *p_Bf_l, *p_Bi_h, *p_Bi_l,
         *p_XfP, *p_Ys_h, *p_Ys_l, *p_xT_h, *p_xT_l, *p_Wk_h, *p_Wk_l;
    cudaGetSymbolAddress(&p_xs_h, g_xs_h);
    cudaGetSymbolAddress(&p_xs_l, g_xs_l);
    cudaGetSymbolAddress(&p_Bf_h, g_Bf_h);
    cudaGetSymbolAddress(&p_Bf_l, g_Bf_l);
    cudaGetSymbolAddress(&p_Bi_h, g_Bi_h);
    cudaGetSymbolAddress(&p_Bi_l, g_Bi_l);
    cudaGetSymbolAddress(&p_XfP, g_XfP);
    cudaGetSymbolAddress(&p_Ys_h, g_Ys_h);
    cudaGetSymbolAddress(&p_Ys_l, g_Ys_l);
    cudaGetSymbolAddress(&p_xT_h, g_xT_h);
    cudaGetSymbolAddress(&p_xT_l, g_xT_l);
    cudaGetSymbolAddress(&p_Wk_h, g_Wk_h);
    cudaGetSymbolAddress(&p_Wk_l, g_Wk_l);

    cudaFuncSetAttribute(k_tc<0>, cudaFuncAttributeMaxDynamicSharedMemorySize, TCSM);
    cudaFuncSetAttribute(k_tc<1>, cudaFuncAttributeMaxDynamicSharedMemorySize, TCSM);
    cudaFuncSetAttribute(k_tc<2>, cudaFuncAttributeMaxDynamicSharedMemorySize, TCSM);

    // prep
    k_sincos<<<Ln / 256, 256>>>();
    k_fillBf<<<dim3(Ln / 256, NF), 256>>>();
    k_fillBi<<<dim3(NF / 256, Ln), 256>>>();
    k_xsplit<<<(BC * Ln / 4) / 256, 256>>>(x);
    k_xT<<<dim3(Ln / 32, CIN / 32, Bn), dim3(32, 8)>>>(x);
    k_wk<<<(CIN * KC + 255) / 256, 256>>>(conv_w);

    // forward DFT (split-K=4): g_XfP[s] = xs @ Bf^T
    k_tc<0><<<dim3(BC / 128, NF / 128, SPLITS), 256, TCSM>>>(
        (const __nv_bfloat16*)p_xs_h, (const __nv_bfloat16*)p_xs_l,
        (const __nv_bfloat16*)p_Bf_h, (const __nv_bfloat16*)p_Bf_l,
        Ln, Ln, (Ln / SPLITS) / 64, Ln / SPLITS, 0,
        (float*)p_XfP, (size_t)BC * NF, NF, nullptr, nullptr);

    // complex head mixing (+ split-K reduce, bf16-split Y)
    k_mix<<<dim3(2, Hh, Bn), 128>>>(wre, wim);

    // conv branch as GEMM (tensor cores): out[b] = Wk @ xT[b]^T + conv_b
    k_tc<2><<<dim3(1, Ln / 128, Bn), 256, TCSM>>>(
        (const __nv_bfloat16*)p_Wk_h, (const __nv_bfloat16*)p_Wk_l,
        (const __nv_bfloat16*)p_xT_h, (const __nv_bfloat16*)p_xT_l,
        KC, CIN, KC / 64, 0, (size_t)XTROWS * CIN,
        out, (size_t)CIN * Ln, Ln, conv_b, nullptr);

    // inverse DFT + bias + gated blend with conv
    k_tc<1><<<dim3(BC / 128, Ln / 128, 1), 256, TCSM>>>(
        (const __nv_bfloat16*)p_Ys_h, (const __nv_bfloat16*)p_Ys_l,
        (const __nv_bfloat16*)p_Bi_h, (const __nv_bfloat16*)p_Bi_l,
        NF, NF, NF / 64, 0, 0,
        out, 0, Ln, bias, gate);
}

// round 9
// speedup vs baseline: 2.9487x; 1.2085x over previous
#include <cuda_runtime.h>
#include <cuda_bf16.h>
#include <cuda_fp16.h>
#include <cstdint>

typedef unsigned long long ull;

#define Bn     16
#define CIN    128
#define Hh     8
#define MODESn 256
#define Ln     16384
#define BC     (Bn*CIN)     // 2048
#define NF     (2*MODESn)   // 512
#define SPLITS 4
#define XTROWS 16386        // 1 zero row + 16384 + 1 zero row
#define KC     384          // conv GEMM K = 3*128
#define YSCALE 1024.0f
#define YINV   (1.0f/1024.0f)

// ---------------- device scratch (no allocations allowed) -------------------
__device__ float2        g_sc[Ln];
__device__ __align__(16) __half        g_Bf[(size_t)NF*Ln];    // fwd B fp16 (unscaled)
__device__ __align__(16) __half        g_Bi[(size_t)Ln*NF];    // inv B fp16
__device__ __align__(16) __half        g_xs_h[(size_t)BC*Ln];  // fwd A fp16 hi
__device__ __align__(16) __half        g_xs_l[(size_t)BC*Ln];  // fwd A fp16 lo
__device__ float         g_XfP[(size_t)SPLITS*BC*NF];          // split-K partials
__device__ __align__(16) __half        g_Ys_h[(size_t)BC*NF];  // inv A fp16 hi (x1024)
__device__ __align__(16) __half        g_Ys_l[(size_t)BC*NF];
// conv stays bf16 3-product
__device__ __align__(16) __nv_bfloat16 g_xT_h[(size_t)Bn*XTROWS*CIN];
__device__ __align__(16) __nv_bfloat16 g_xT_l[(size_t)Bn*XTROWS*CIN];
__device__ __align__(16) __nv_bfloat16 g_Wk_h[CIN*KC];
__device__ __align__(16) __nv_bfloat16 g_Wk_l[CIN*KC];

// ---------------- ptx helpers -------------------------------------------------
__device__ __forceinline__ uint32_t smem_u32(const void* p) {
    uint32_t a;
    asm("{ .reg .u64 t; cvta.to.shared.u64 t, %1; cvt.u32.u64 %0, t; }" : "=r"(a) : "l"(p));
    return a;
}
__device__ __forceinline__ void cpa16(uint32_t sdst, const void* gsrc) {
    asm volatile("cp.async.cg.shared.global [%0], [%1], 16;" :: "r"(sdst), "l"(gsrc));
}
#define CP_COMMIT() asm volatile("cp.async.commit_group;" ::: "memory")
#define CP_WAIT1()  asm volatile("cp.async.wait_group 1;" ::: "memory")

__device__ __forceinline__ void ldm4(uint32_t* r, uint32_t addr) {
    asm volatile("ldmatrix.sync.aligned.m8n8.x4.shared.b16 {%0,%1,%2,%3}, [%4];"
                 : "=r"(r[0]), "=r"(r[1]), "=r"(r[2]), "=r"(r[3]) : "r"(addr));
}
__device__ __forceinline__ void mma_bf16(float* c, const uint32_t* a,
                                         uint32_t b0, uint32_t b1) {
    asm volatile("mma.sync.aligned.m16n8k16.row.col.f32.bf16.bf16.f32 "
                 "{%0,%1,%2,%3}, {%4,%5,%6,%7}, {%8,%9}, {%0,%1,%2,%3};"
                 : "+f"(c[0]), "+f"(c[1]), "+f"(c[2]), "+f"(c[3])
                 : "r"(a[0]), "r"(a[1]), "r"(a[2]), "r"(a[3]), "r"(b0), "r"(b1));
}
__device__ __forceinline__ void mma_f16(float* c, const uint32_t* a,
                                        uint32_t b0, uint32_t b1) {
    asm volatile("mma.sync.aligned.m16n8k16.row.col.f32.f16.f16.f32 "
                 "{%0,%1,%2,%3}, {%4,%5,%6,%7}, {%8,%9}, {%0,%1,%2,%3};"
                 : "+f"(c[0]), "+f"(c[1]), "+f"(c[2]), "+f"(c[3])
                 : "r"(a[0]), "r"(a[1]), "r"(a[2]), "r"(a[3]), "r"(b0), "r"(b1));
}
__device__ __forceinline__ void split2(float v, __nv_bfloat16& h, __nv_bfloat16& l) {
    h = __float2bfloat16(v);
    l = __float2bfloat16(v - __bfloat162float(h));
}
__device__ __forceinline__ void split2h(float v, __half& h, __half& l) {
    h = __float2half(v);
    l = __float2half(v - __half2float(h));
}

// ---------------- init kernels ------------------------------------------------
__global__ void k_sincos() {
    int j = blockIdx.x * 256 + threadIdx.x;
    float s, c;
    sincospif((float)j * (2.0f / Ln), &s, &c);
    g_sc[j] = make_float2(c, s);
}

__global__ void k_fillBf() {                       // [col=512 rows][K=16384], UNSCALED
    int n   = blockIdx.x * 256 + threadIdx.x;
    int col = blockIdx.y;
    int k   = col >> 1;
    float2 sc = g_sc[(k * n) & (Ln - 1)];
    float v = (col & 1) ? (-sc.y) : (sc.x);
    g_Bf[(size_t)col * Ln + n] = __float2half(v);
}

__global__ void k_fillBi() {                       // [n=16384 rows][K=512]
    int j = blockIdx.x * 256 + threadIdx.x;
    int n = blockIdx.y;
    int k = j >> 1;
    float2 sc = g_sc[(k * n) & (Ln - 1)];
    float ck = (k == 0) ? 1.0f : 2.0f;
    float v = (j & 1) ? (-ck * sc.y) : (ck * sc.x);
    g_Bi[(size_t)n * NF + j] = __float2half(v);
}

// fused: x -> fp16 h/l planes (fwd A) + transposed padded bf16 h/l planes (conv B)
__global__ void __launch_bounds__(256) k_xprep(const float* __restrict__ x) {
    __shared__ float tile[32][33];
    const int b   = blockIdx.z;
    const int ciB = blockIdx.y * 32;
    const int nB  = blockIdx.x * 32;
    const int tx = threadIdx.x, ty = threadIdx.y;     // 32 x 8

#pragma unroll
    for (int j = 0; j < 4; ++j) {
        int ci = ciB + ty + j * 8;
        float v = x[((size_t)b * CIN + ci) * Ln + nB + tx];
        tile[ty + j * 8][tx] = v;
        __half hh, hl; split2h(v, hh, hl);
        size_t off = ((size_t)b * CIN + ci) * Ln + nB + tx;
        g_xs_h[off] = hh; g_xs_l[off] = hl;
    }
    __syncthreads();
#pragma unroll
    for (int j = 0; j < 4; ++j) {
        int nl = ty + j * 8;
        float v = tile[tx][nl];
        __nv_bfloat16 h, l; split2(v, h, l);
        size_t off = ((size_t)b * XTROWS + 1 + nB + nl) * CIN + ciB + tx;
        g_xT_h[off] = h; g_xT_l[off] = l;
    }
}

// conv weights -> Wk[co][d*128+ci] bf16 split
__global__ void k_wk(const float* __restrict__ w) {
    int idx = blockIdx.x * 256 + threadIdx.x;        // co*384 + d*128 + ci
    if (idx < CIN * KC) {
        int co = idx / KC;
        int r  = idx - co * KC;
        int d  = r >> 7;
        int ci = r & 127;
        float v = w[(co * CIN + ci) * 3 + d];
        __nv_bfloat16 h, l; split2(v, h, l);
        g_Wk_h[idx] = h; g_Wk_l[idx] = l;
    }
}

// ---------------- mma.sync GEMM -------------------------------------------------
// C[128,128] tile, BK=64, 8 warps, cp.async double buffer, ldmatrix fragments.
// MODE 0: fp16 2-product, C[z] = A@B^T (fwd, z = k-split)
// MODE 1: fp16 2-product, C = g*(A@B^T*YINV + bias[m&127]) + (1-g)*C (inv blend)
// MODE 2: bf16 3-product, C[z] = A@B[z]^T + bias[m&127] (conv; z = batch)
#define ROWB   144
#define PLANE  (128*ROWB)                // 18432
#define BUFSZ  (4*PLANE)                 // 73728
#define TCSM   (2*BUFSZ + 1024)

template<int MODE>
__global__ void __launch_bounds__(256, 1) k_tc(
    const __nv_bfloat16* __restrict__ Ah, const __nv_bfloat16* __restrict__ Al,
    const __nv_bfloat16* __restrict__ Bh, const __nv_bfloat16* __restrict__ Bl,
    int ldA, int ldB, int nChunks, int kSplit, size_t bPlane,
    float* __restrict__ C, size_t cPlane, int ldC,
    const float* __restrict__ bias, const float* __restrict__ gate)
{
    constexpr int NPL = (MODE == 2) ? 4 : 3;   // planes staged per chunk

    extern __shared__ char smraw[];
    const uint32_t smBase = (smem_u32(smraw) + 1023u) & ~1023u;

    const int tid  = threadIdx.x;
    const int lane = tid & 31;
    const int w    = tid >> 5;
    const int wm   = w & 3;
    const int wn   = w >> 2;
    const int mBase = blockIdx.x * 128;
    const int nBase = blockIdx.y * 128;
    const int kOff  = blockIdx.z * kSplit;

    Bh += (size_t)blockIdx.z * bPlane;
    if (MODE == 2) Bl += (size_t)blockIdx.z * bPlane;
    const __nv_bfloat16* srcs[4] = {Ah, Al, Bh, Bl};

    const int sRow = tid >> 3;
    const int sC8  = tid & 7;

    const int g = lane >> 2;             // epilogue row group

    const int lrow = lane & 7;
    const int sel0 = (lane >> 3) & 1;
    const int sel1 = (lane >> 4) & 1;
    const uint32_t aLane = (uint32_t)((lrow + sel0 * 8) * ROWB + sel1 * 16);
    const uint32_t bLane = (uint32_t)((lrow + sel1 * 8) * ROWB + sel0 * 16);

    float c[2][8][4];
#pragma unroll
    for (int mt = 0; mt < 2; mt++)
#pragma unroll
        for (int nt = 0; nt < 8; nt++)
#pragma unroll
            for (int q = 0; q < 4; q++) c[mt][nt][q] = 0.f;

    auto loadStage = [&](int st) {
        const int buf = st & 1;
        const int kB  = kOff + st * 64;
        const uint32_t bufBase = smBase + buf * BUFSZ;
#pragma unroll
        for (int p = 0; p < NPL; ++p) {
            const __nv_bfloat16* src = srcs[p];
            const int rB = (p < 2) ? mBase : nBase;
            const int ld = (p < 2) ? ldA : ldB;
            const __nv_bfloat16* g0 = src + (size_t)(rB + sRow) * ld + kB + sC8 * 8;
            const uint32_t d0 = bufBase + p * PLANE + sRow * ROWB + sC8 * 16;
#pragma unroll
            for (int i = 0; i < 4; ++i)
                cpa16(d0 + i * 32 * ROWB, g0 + (size_t)(32 * i) * ld);
        }
    };

    loadStage(0); CP_COMMIT();
    if (nChunks > 1) loadStage(1);
    CP_COMMIT();

#pragma unroll 1
    for (int ch = 0; ch < nChunks; ++ch) {
        CP_WAIT1();
        __syncthreads();

        const uint32_t bufBase = smBase + (ch & 1) * BUFSZ;
        const uint32_t aBase = bufBase + (wm * 32) * ROWB + aLane;
        const uint32_t bBase = bufBase + 2 * PLANE + (wn * 64) * ROWB + bLane;

#pragma unroll
        for (int k16 = 0; k16 < 4; ++k16) {
            const uint32_t kb = (uint32_t)(k16 * 32);
            uint32_t ah[2][4], al[2][4], bh[4][4];

#pragma unroll
            for (int mt = 0; mt < 2; ++mt) {
                const uint32_t rA = aBase + mt * 16 * ROWB + kb;
                ldm4(ah[mt], rA);
                ldm4(al[mt], rA + PLANE);
            }
            if (MODE == 2) {
                uint32_t bl[4][4];
#pragma unroll
                for (int pr = 0; pr < 4; ++pr) {
                    const uint32_t rB0 = bBase + pr * 16 * ROWB + kb;
                    ldm4(bh[pr], rB0);
                    ldm4(bl[pr], rB0 + PLANE);
                }
#pragma unroll
                for (int mt = 0; mt < 2; ++mt)
#pragma unroll
                    for (int nt = 0; nt < 8; ++nt) {
                        const int pr = nt >> 1, hf = (nt & 1) * 2;
                        mma_bf16(c[mt][nt], ah[mt], bh[pr][hf], bh[pr][hf + 1]);
                        mma_bf16(c[mt][nt], ah[mt], bl[pr][hf], bl[pr][hf + 1]);
                        mma_bf16(c[mt][nt], al[mt], bh[pr][hf], bh[pr][hf + 1]);
                    }
            } else {
#pragma unroll
                for (int pr = 0; pr < 4; ++pr)
                    ldm4(bh[pr], bBase + pr * 16 * ROWB + kb);
#pragma unroll
                for (int mt = 0; mt < 2; ++mt)
#pragma unroll
                    for (int nt = 0; nt < 8; ++nt) {
                        const int pr = nt >> 1, hf = (nt & 1) * 2;
                        mma_f16(c[mt][nt], ah[mt], bh[pr][hf], bh[pr][hf + 1]);
                        mma_f16(c[mt][nt], al[mt], bh[pr][hf], bh[pr][hf + 1]);
                    }
            }
        }
        __syncthreads();
        if (ch + 2 < nChunks) loadStage(ch + 2);
        CP_COMMIT();
    }

    float gg = 0.f, og = 0.f;
    if (MODE == 1) { gg = 1.0f / (1.0f + expf(-gate[0])); og = 1.0f - gg; }
    float* Cz = C + (size_t)blockIdx.z * cPlane;
#pragma unroll
    for (int mt = 0; mt < 2; ++mt) {
        const int r0 = mBase + wm * 32 + mt * 16 + g;
        float bv0 = 0.f, bv1 = 0.f;
        if (MODE != 0) { bv0 = bias[r0 & (CIN - 1)]; bv1 = bias[(r0 + 8) & (CIN - 1)]; }
#pragma unroll
        for (int nt = 0; nt < 8; ++nt) {
            const int cc = nBase + wn * 64 + nt * 8 + (lane & 3) * 2;
            float* p0 = Cz + (size_t)r0 * ldC + cc;
            float* p1 = Cz + (size_t)(r0 + 8) * ldC + cc;
            if (MODE == 1) {
                float2 o0 = *(const float2*)p0;
                float2 o1 = *(const float2*)p1;
                *(float2*)p0 = make_float2(gg * (c[mt][nt][0] * YINV + bv0) + og * o0.x,
                                           gg * (c[mt][nt][1] * YINV + bv0) + og * o0.y);
                *(float2*)p1 = make_float2(gg * (c[mt][nt][2] * YINV + bv1) + og * o1.x,
                                           gg * (c[mt][nt][3] * YINV + bv1) + og * o1.y);
            } else if (MODE == 2) {
                *(float2*)p0 = make_float2(c[mt][nt][0] + bv0, c[mt][nt][1] + bv0);
                *(float2*)p1 = make_float2(c[mt][nt][2] + bv1, c[mt][nt][3] + bv1);
            } else {
                *(float2*)p0 = make_float2(c[mt][nt][0], c[mt][nt][1]);
                *(float2*)p1 = make_float2(c[mt][nt][2], c[mt][nt][3]);
            }
        }
    }
}

// ---------------- per-mode complex 16x16 head mixing ---------------------------
// XfP is UNSCALED (basis had no 1/L): apply 2^-14 here; emit Ys = Y*1024 fp16 h/l.
__global__ void __launch_bounds__(128) k_mix(const float* __restrict__ wre,
                                             const float* __restrict__ wim) {
    const int kc = blockIdx.x;
    const int h  = blockIdx.y;
    const int b  = blockIdx.z;
    const int kg = kc * 128 + threadIdx.x;
    const size_t PL = (size_t)BC * NF;
    const float LI = 1.0f / (float)Ln;

    float xr[16], xi[16];
#pragma unroll
    for (int i = 0; i < 16; i++) {
        size_t off = ((size_t)(b * CIN + h * 16 + i) * NF) + 2 * kg;
        float sr = 0.f, si = 0.f;
#pragma unroll
        for (int s = 0; s < SPLITS; s++) {
            float2 v = *(const float2*)&g_XfP[s * PL + off];
            sr += v.x; si += v.y;
        }
        xr[i] = sr * LI; xi[i] = si * LI;
    }
#pragma unroll 1
    for (int o = 0; o < 16; o++) {
        float ar = 0.f, ai = 0.f;
#pragma unroll
        for (int i = 0; i < 16; i++) {
            int widx = ((h * 16 + i) * 16 + o) * MODESn + kg;
            float wr = wre[widx], wi = wim[widx];
            ar = fmaf(xr[i], wr, ar);
            ar = fmaf(-xi[i], wi, ar);
            ai = fmaf(xr[i], wi, ai);
            ai = fmaf(xi[i], wr, ai);
        }
        size_t off = ((size_t)(b * CIN + h * 16 + o) * NF) + 2 * kg;
        __half hh, ll;
        split2h(ar * YSCALE, hh, ll); g_Ys_h[off] = hh;     g_Ys_l[off] = ll;
        split2h(ai * YSCALE, hh, ll); g_Ys_h[off + 1] = hh; g_Ys_l[off + 1] = ll;
    }
}

// ---------------- launch --------------------------------------------------------
extern "C" void kernel_launch(void* const* d_in, const int* in_sizes, int n_in,
                              void* d_out, int out_size) {
    const float* x      = (const float*)d_in[0];
    const float* wre    = (const float*)d_in[1];
    const float* wim    = (const float*)d_in[2];
    const float* bias   = (const float*)d_in[3];
    const float* conv_w = (const float*)d_in[4];
    const float* conv_b = (const float*)d_in[5];
    const float* gate   = (const float*)d_in[6];
    float* out = (float*)d_out;

    // Resolve REAL device addresses of __device__ scratch (host shadows are
    // ATS-dereferenceable host memory — NOT the device arrays).
    void *p_xs_h, *p_xs_l, *p_Bf, *p_Bi, *p_XfP, *p_Ys_h, *p_Ys_l,
         *p_xT_h, *p_xT_l, *p_Wk_h, *p_Wk_l;
    cudaGetSymbolAddress(&p_xs_h, g_xs_h);
    cudaGetSymbolAddress(&p_xs_l, g_xs_l);
    cudaGetSymbolAddress(&p_Bf, g_Bf);
    cudaGetSymbolAddress(&p_Bi, g_Bi);
    cudaGetSymbolAddress(&p_XfP, g_XfP);
    cudaGetSymbolAddress(&p_Ys_h, g_Ys_h);
    cudaGetSymbolAddress(&p_Ys_l, g_Ys_l);
    cudaGetSymbolAddress(&p_xT_h, g_xT_h);
    cudaGetSymbolAddress(&p_xT_l, g_xT_l);
    cudaGetSymbolAddress(&p_Wk_h, g_Wk_h);
    cudaGetSymbolAddress(&p_Wk_l, g_Wk_l);

    cudaFuncSetAttribute(k_tc<0>, cudaFuncAttributeMaxDynamicSharedMemorySize, TCSM);
    cudaFuncSetAttribute(k_tc<1>, cudaFuncAttributeMaxDynamicSharedMemorySize, TCSM);
    cudaFuncSetAttribute(k_tc<2>, cudaFuncAttributeMaxDynamicSharedMemorySize, TCSM);

    // prep (ordered so tc<0> is the 4th launch -> lands in ncu's window)
    k_sincos<<<Ln / 256, 256>>>();
    k_xprep<<<dim3(Ln / 32, CIN / 32, Bn), dim3(32, 8)>>>(x);
    k_fillBf<<<dim3(Ln / 256, NF), 256>>>();

    // forward DFT (fp16 2-product, split-K=4): g_XfP[s] = xs @ Bf^T  (unscaled)
    k_tc<0><<<dim3(BC / 128, NF / 128, SPLITS), 256, TCSM>>>(
        (const __nv_bfloat16*)p_xs_h, (const __nv_bfloat16*)p_xs_l,
        (const __nv_bfloat16*)p_Bf, nullptr,
        Ln, Ln, (Ln / SPLITS) / 64, Ln / SPLITS, 0,
        (float*)p_XfP, (size_t)BC * NF, NF, nullptr, nullptr);

    k_wk<<<(CIN * KC + 255) / 256, 256>>>(conv_w);
    k_fillBi<<<dim3(NF / 256, Ln), 256>>>();

    // complex head mixing (+ split-K reduce, 1/L scale, Ys = Y*1024 fp16)
    k_mix<<<dim3(2, Hh, Bn), 128>>>(wre, wim);

    // conv branch as GEMM (bf16 3-product): out[b] = Wk @ xT[b]^T + conv_b
    k_tc<2><<<dim3(1, Ln / 128, Bn), 256, TCSM>>>(
        (const __nv_bfloat16*)p_Wk_h, (const __nv_bfloat16*)p_Wk_l,
        (const __nv_bfloat16*)p_xT_h, (const __nv_bfloat16*)p_xT_l,
        KC, CIN, KC / 64, 0, (size_t)XTROWS * CIN,
        out, (size_t)CIN * Ln, Ln, conv_b, nullptr);

    // inverse DFT (fp16 2-product) + 1/1024 + bias + gated blend with conv
    k_tc<1><<<dim3(BC / 128, Ln / 128, 1), 256, TCSM>>>(
        (const __nv_bfloat16*)p_Ys_h, (const __nv_bfloat16*)p_Ys_l,
        (const __nv_bfloat16*)p_Bi, nullptr,
        NF, NF, NF / 64, 0, 0,
        out, 0, Ln, bias, gate);
}

// round 10
// speedup vs baseline: 3.9225x; 1.3302x over previous
#include <cuda_runtime.h>
#include <cuda_bf16.h>
#include <cuda_fp16.h>
#include <cstdint>

typedef unsigned long long ull;

#define Bn     16
#define CIN    128
#define Hh     8
#define MODESn 256
#define Ln     16384
#define BC     (Bn*CIN)     // 2048
#define NF     (2*MODESn)   // 512
#define SPLITS 4
#define XTROWS 16386        // 1 zero row + 16384 + 1 zero row
#define KC     384          // conv GEMM K = 3*128
#define YSCALE 1024.0f
#define YINV   (1.0f/1024.0f)

// ---------------- device scratch (no allocations allowed) -------------------
__device__ float2        g_sc[Ln];
__device__ __align__(16) __half g_Bf[(size_t)NF*Ln];    // fwd B fp16 (unscaled)
__device__ __align__(16) __half g_Bi[(size_t)Ln*NF];    // inv B fp16
__device__ __align__(16) __half g_xs_h[(size_t)BC*Ln];  // fwd A fp16 hi
__device__ __align__(16) __half g_xs_l[(size_t)BC*Ln];  // fwd A fp16 lo
__device__ float         g_XfP[(size_t)SPLITS*BC*NF];   // split-K partials
__device__ __align__(16) __half g_Ys_h[(size_t)BC*NF];  // inv A fp16 hi (x1024)
__device__ __align__(16) __half g_Ys_l[(size_t)BC*NF];
// conv: single-fp16 transposed padded x; W split fp16
__device__ __align__(16) __half g_xT[(size_t)Bn*XTROWS*CIN];
__device__ __align__(16) __half g_Wk_h[CIN*KC];
__device__ __align__(16) __half g_Wk_l[CIN*KC];

// ---------------- ptx helpers -------------------------------------------------
__device__ __forceinline__ uint32_t smem_u32(const void* p) {
    uint32_t a;
    asm("{ .reg .u64 t; cvta.to.shared.u64 t, %1; cvt.u32.u64 %0, t; }" : "=r"(a) : "l"(p));
    return a;
}
__device__ __forceinline__ void cpa16(uint32_t sdst, const void* gsrc) {
    asm volatile("cp.async.cg.shared.global [%0], [%1], 16;" :: "r"(sdst), "l"(gsrc));
}
#define CP_COMMIT() asm volatile("cp.async.commit_group;" ::: "memory")
#define CP_WAIT1()  asm volatile("cp.async.wait_group 1;" ::: "memory")

__device__ __forceinline__ void ldm4(uint32_t* r, uint32_t addr) {
    asm volatile("ldmatrix.sync.aligned.m8n8.x4.shared.b16 {%0,%1,%2,%3}, [%4];"
                 : "=r"(r[0]), "=r"(r[1]), "=r"(r[2]), "=r"(r[3]) : "r"(addr));
}
__device__ __forceinline__ void mma_f16(float* c, const uint32_t* a,
                                        uint32_t b0, uint32_t b1) {
    asm volatile("mma.sync.aligned.m16n8k16.row.col.f32.f16.f16.f32 "
                 "{%0,%1,%2,%3}, {%4,%5,%6,%7}, {%8,%9}, {%0,%1,%2,%3};"
                 : "+f"(c[0]), "+f"(c[1]), "+f"(c[2]), "+f"(c[3])
                 : "r"(a[0]), "r"(a[1]), "r"(a[2]), "r"(a[3]), "r"(b0), "r"(b1));
}
__device__ __forceinline__ void split2h(float v, __half& h, __half& l) {
    h = __float2half(v);
    l = __float2half(v - __half2float(h));
}

// ---------------- init kernels ------------------------------------------------
__global__ void k_sincos() {
    int j = blockIdx.x * 256 + threadIdx.x;
    float s, c;
    sincospif((float)j * (2.0f / Ln), &s, &c);
    g_sc[j] = make_float2(c, s);
}

__global__ void k_fillBf() {                       // [col=512 rows][K=16384], UNSCALED
    int n   = blockIdx.x * 256 + threadIdx.x;
    int col = blockIdx.y;
    int k   = col >> 1;
    float2 sc = g_sc[(k * n) & (Ln - 1)];
    float v = (col & 1) ? (-sc.y) : (sc.x);
    g_Bf[(size_t)col * Ln + n] = __float2half(v);
}

__global__ void k_fillBi() {                       // [n=16384 rows][K=512]
    int j = blockIdx.x * 256 + threadIdx.x;
    int n = blockIdx.y;
    int k = j >> 1;
    float2 sc = g_sc[(k * n) & (Ln - 1)];
    float ck = (k == 0) ? 1.0f : 2.0f;
    float v = (j & 1) ? (-ck * sc.y) : (ck * sc.x);
    g_Bi[(size_t)n * NF + j] = __float2half(v);
}

// fused: x -> fp16 h/l planes (fwd A) + transposed padded single-fp16 (conv B)
__global__ void __launch_bounds__(256) k_xprep(const float* __restrict__ x) {
    __shared__ float tile[32][33];
    const int b   = blockIdx.z;
    const int ciB = blockIdx.y * 32;
    const int nB  = blockIdx.x * 32;
    const int tx = threadIdx.x, ty = threadIdx.y;     // 32 x 8

#pragma unroll
    for (int j = 0; j < 4; ++j) {
        int ci = ciB + ty + j * 8;
        float v = x[((size_t)b * CIN + ci) * Ln + nB + tx];
        tile[ty + j * 8][tx] = v;
        __half hh, hl; split2h(v, hh, hl);
        size_t off = ((size_t)b * CIN + ci) * Ln + nB + tx;
        g_xs_h[off] = hh; g_xs_l[off] = hl;
    }
    __syncthreads();
#pragma unroll
    for (int j = 0; j < 4; ++j) {
        int nl = ty + j * 8;
        float v = tile[tx][nl];
        size_t off = ((size_t)b * XTROWS + 1 + nB + nl) * CIN + ciB + tx;
        g_xT[off] = __float2half(v);
    }
}

// conv weights -> Wk[co][d*128+ci] fp16 split
__global__ void k_wk(const float* __restrict__ w) {
    int idx = blockIdx.x * 256 + threadIdx.x;        // co*384 + d*128 + ci
    if (idx < CIN * KC) {
        int co = idx / KC;
        int r  = idx - co * KC;
        int d  = r >> 7;
        int ci = r & 127;
        float v = w[(co * CIN + ci) * 3 + d];
        __half h, l; split2h(v, h, l);
        g_Wk_h[idx] = h; g_Wk_l[idx] = l;
    }
}

// ---------------- mma.sync fp16 2-product GEMM ---------------------------------
// C[128,128] tile, BK=64, 8 warps, cp.async double buffer, ldmatrix fragments.
// 3 staged planes (Ah, Al, B) -> 111.6KB smem -> 2 CTAs/SM.
// MODE 0: C[z] = (Ah+Al)@B^T (fwd, z = k-split)
// MODE 1: C = g*((Ah+Al)@B^T*YINV + bias[m&127]) + (1-g)*C (inv blend)
// MODE 2: C[z] = (Ah+Al)@B[z]^T + bias[m&127] (conv; z = batch, B plane stride)
#define ROWB   144
#define PLANE  (128*ROWB)                // 18432
#define BUFSZ  (3*PLANE)                 // 55296
#define TCSM   (2*BUFSZ + 1024)          // 111616

template<int MODE>
__global__ void __launch_bounds__(256, 2) k_tc(
    const __half* __restrict__ Ah, const __half* __restrict__ Al,
    const __half* __restrict__ Bm,
    int ldA, int ldB, int nChunks, int kSplit, size_t bPlane,
    float* __restrict__ C, size_t cPlane, int ldC,
    const float* __restrict__ bias, const float* __restrict__ gate)
{
    extern __shared__ char smraw[];
    const uint32_t smBase = (smem_u32(smraw) + 1023u) & ~1023u;

    const int tid  = threadIdx.x;
    const int lane = tid & 31;
    const int w    = tid >> 5;
    const int wm   = w & 3;
    const int wn   = w >> 2;
    const int mBase = blockIdx.x * 128;
    const int nBase = blockIdx.y * 128;
    const int kOff  = blockIdx.z * kSplit;

    Bm += (size_t)blockIdx.z * bPlane;
    const __half* srcs[3] = {Ah, Al, Bm};

    const int sRow = tid >> 3;
    const int sC8  = tid & 7;

    const int g = lane >> 2;             // epilogue row group

    const int lrow = lane & 7;
    const int sel0 = (lane >> 3) & 1;
    const int sel1 = (lane >> 4) & 1;
    const uint32_t aLane = (uint32_t)((lrow + sel0 * 8) * ROWB + sel1 * 16);
    const uint32_t bLane = (uint32_t)((lrow + sel1 * 8) * ROWB + sel0 * 16);

    float c[2][8][4];
#pragma unroll
    for (int mt = 0; mt < 2; mt++)
#pragma unroll
        for (int nt = 0; nt < 8; nt++)
#pragma unroll
            for (int q = 0; q < 4; q++) c[mt][nt][q] = 0.f;

    auto loadStage = [&](int st) {
        const int buf = st & 1;
        const int kB  = kOff + st * 64;
        const uint32_t bufBase = smBase + buf * BUFSZ;
#pragma unroll
        for (int p = 0; p < 3; ++p) {
            const __half* src = srcs[p];
            const int rB = (p < 2) ? mBase : nBase;
            const int ld = (p < 2) ? ldA : ldB;
            const __half* g0 = src + (size_t)(rB + sRow) * ld + kB + sC8 * 8;
            const uint32_t d0 = bufBase + p * PLANE + sRow * ROWB + sC8 * 16;
#pragma unroll
            for (int i = 0; i < 4; ++i)
                cpa16(d0 + i * 32 * ROWB, g0 + (size_t)(32 * i) * ld);
        }
    };

    loadStage(0); CP_COMMIT();
    if (nChunks > 1) loadStage(1);
    CP_COMMIT();

#pragma unroll 1
    for (int ch = 0; ch < nChunks; ++ch) {
        CP_WAIT1();
        __syncthreads();

        const uint32_t bufBase = smBase + (ch & 1) * BUFSZ;
        const uint32_t aBase = bufBase + (wm * 32) * ROWB + aLane;
        const uint32_t bBase = bufBase + 2 * PLANE + (wn * 64) * ROWB + bLane;

#pragma unroll
        for (int k16 = 0; k16 < 4; ++k16) {
            const uint32_t kb = (uint32_t)(k16 * 32);
            uint32_t ah[2][4], al[2][4], bh[4][4];

#pragma unroll
            for (int mt = 0; mt < 2; ++mt) {
                const uint32_t rA = aBase + mt * 16 * ROWB + kb;
                ldm4(ah[mt], rA);
                ldm4(al[mt], rA + PLANE);
            }
#pragma unroll
            for (int pr = 0; pr < 4; ++pr)
                ldm4(bh[pr], bBase + pr * 16 * ROWB + kb);
#pragma unroll
            for (int mt = 0; mt < 2; ++mt)
#pragma unroll
                for (int nt = 0; nt < 8; ++nt) {
                    const int pr = nt >> 1, hf = (nt & 1) * 2;
                    mma_f16(c[mt][nt], ah[mt], bh[pr][hf], bh[pr][hf + 1]);
                    mma_f16(c[mt][nt], al[mt], bh[pr][hf], bh[pr][hf + 1]);
                }
        }
        __syncthreads();
        if (ch + 2 < nChunks) loadStage(ch + 2);
        CP_COMMIT();
    }

    float gg = 0.f, og = 0.f;
    if (MODE == 1) { gg = 1.0f / (1.0f + expf(-gate[0])); og = 1.0f - gg; }
    float* Cz = C + (size_t)blockIdx.z * cPlane;
#pragma unroll
    for (int mt = 0; mt < 2; ++mt) {
        const int r0 = mBase + wm * 32 + mt * 16 + g;
        float bv0 = 0.f, bv1 = 0.f;
        if (MODE != 0) { bv0 = bias[r0 & (CIN - 1)]; bv1 = bias[(r0 + 8) & (CIN - 1)]; }
#pragma unroll
        for (int nt = 0; nt < 8; ++nt) {
            const int cc = nBase + wn * 64 + nt * 8 + (lane & 3) * 2;
            float* p0 = Cz + (size_t)r0 * ldC + cc;
            float* p1 = Cz + (size_t)(r0 + 8) * ldC + cc;
            if (MODE == 1) {
                float2 o0 = *(const float2*)p0;
                float2 o1 = *(const float2*)p1;
                *(float2*)p0 = make_float2(gg * (c[mt][nt][0] * YINV + bv0) + og * o0.x,
                                           gg * (c[mt][nt][1] * YINV + bv0) + og * o0.y);
                *(float2*)p1 = make_float2(gg * (c[mt][nt][2] * YINV + bv1) + og * o1.x,
                                           gg * (c[mt][nt][3] * YINV + bv1) + og * o1.y);
            } else if (MODE == 2) {
                *(float2*)p0 = make_float2(c[mt][nt][0] + bv0, c[mt][nt][1] + bv0);
                *(float2*)p1 = make_float2(c[mt][nt][2] + bv1, c[mt][nt][3] + bv1);
            } else {
                *(float2*)p0 = make_float2(c[mt][nt][0], c[mt][nt][1]);
                *(float2*)p1 = make_float2(c[mt][nt][2], c[mt][nt][3]);
            }
        }
    }
}

// ---------------- per-mode complex 16x16 head mixing ---------------------------
// XfP is UNSCALED (basis had no 1/L): apply 2^-14 here; emit Ys = Y*1024 fp16 h/l.
__global__ void __launch_bounds__(128) k_mix(const float* __restrict__ wre,
                                             const float* __restrict__ wim) {
    const int kc = blockIdx.x;
    const int h  = blockIdx.y;
    const int b  = blockIdx.z;
    const int kg = kc * 128 + threadIdx.x;
    const size_t PL = (size_t)BC * NF;
    const float LI = 1.0f / (float)Ln;

    float xr[16], xi[16];
#pragma unroll
    for (int i = 0; i < 16; i++) {
        size_t off = ((size_t)(b * CIN + h * 16 + i) * NF) + 2 * kg;
        float sr = 0.f, si = 0.f;
#pragma unroll
        for (int s = 0; s < SPLITS; s++) {
            float2 v = *(const float2*)&g_XfP[s * PL + off];
            sr += v.x; si += v.y;
        }
        xr[i] = sr * LI; xi[i] = si * LI;
    }
#pragma unroll 1
    for (int o = 0; o < 16; o++) {
        float ar = 0.f, ai = 0.f;
#pragma unroll
        for (int i = 0; i < 16; i++) {
            int widx = ((h * 16 + i) * 16 + o) * MODESn + kg;
            float wr = wre[widx], wi = wim[widx];
            ar = fmaf(xr[i], wr, ar);
            ar = fmaf(-xi[i], wi, ar);
            ai = fmaf(xr[i], wi, ai);
            ai = fmaf(xi[i], wr, ai);
        }
        size_t off = ((size_t)(b * CIN + h * 16 + o) * NF) + 2 * kg;
        __half hh, ll;
        split2h(ar * YSCALE, hh, ll); g_Ys_h[off] = hh;     g_Ys_l[off] = ll;
        split2h(ai * YSCALE, hh, ll); g_Ys_h[off + 1] = hh; g_Ys_l[off + 1] = ll;
    }
}

// ---------------- launch --------------------------------------------------------
extern "C" void kernel_launch(void* const* d_in, const int* in_sizes, int n_in,
                              void* d_out, int out_size) {
    const float* x      = (const float*)d_in[0];
    const float* wre    = (const float*)d_in[1];
    const float* wim    = (const float*)d_in[2];
    const float* bias   = (const float*)d_in[3];
    const float* conv_w = (const float*)d_in[4];
    const float* conv_b = (const float*)d_in[5];
    const float* gate   = (const float*)d_in[6];
    float* out = (float*)d_out;

    // Resolve REAL device addresses of __device__ scratch (host shadows are
    // ATS-dereferenceable host memory — NOT the device arrays).
    void *p_xs_h, *p_xs_l, *p_Bf, *p_Bi, *p_XfP, *p_Ys_h, *p_Ys_l,
         *p_xT, *p_Wk_h, *p_Wk_l;
    cudaGetSymbolAddress(&p_xs_h, g_xs_h);
    cudaGetSymbolAddress(&p_xs_l, g_xs_l);
    cudaGetSymbolAddress(&p_Bf, g_Bf);
    cudaGetSymbolAddress(&p_Bi, g_Bi);
    cudaGetSymbolAddress(&p_XfP, g_XfP);
    cudaGetSymbolAddress(&p_Ys_h, g_Ys_h);
    cudaGetSymbolAddress(&p_Ys_l, g_Ys_l);
    cudaGetSymbolAddress(&p_xT, g_xT);
    cudaGetSymbolAddress(&p_Wk_h, g_Wk_h);
    cudaGetSymbolAddress(&p_Wk_l, g_Wk_l);

    cudaFuncSetAttribute(k_tc<0>, cudaFuncAttributeMaxDynamicSharedMemorySize, TCSM);
    cudaFuncSetAttribute(k_tc<1>, cudaFuncAttributeMaxDynamicSharedMemorySize, TCSM);
    cudaFuncSetAttribute(k_tc<2>, cudaFuncAttributeMaxDynamicSharedMemorySize, TCSM);

    // prep (ordered so tc<0> stays the 4th launch -> lands in ncu's window)
    k_sincos<<<Ln / 256, 256>>>();
    k_xprep<<<dim3(Ln / 32, CIN / 32, Bn), dim3(32, 8)>>>(x);
    k_fillBf<<<dim3(Ln / 256, NF), 256>>>();

    // forward DFT (fp16 2-product, split-K=4): g_XfP[s] = xs @ Bf^T  (unscaled)
    k_tc<0><<<dim3(BC / 128, NF / 128, SPLITS), 256, TCSM>>>(
        (const __half*)p_xs_h, (const __half*)p_xs_l, (const __half*)p_Bf,
        Ln, Ln, (Ln / SPLITS) / 64, Ln / SPLITS, 0,
        (float*)p_XfP, (size_t)BC * NF, NF, nullptr, nullptr);

    k_wk<<<(CIN * KC + 255) / 256, 256>>>(conv_w);
    k_fillBi<<<dim3(NF / 256, Ln), 256>>>();

    // complex head mixing (+ split-K reduce, 1/L scale, Ys = Y*1024 fp16)
    k_mix<<<dim3(2, Hh, Bn), 128>>>(wre, wim);

    // conv branch as GEMM (fp16 2-product, W split): out[b] = Wk @ xT[b]^T + conv_b
    k_tc<2><<<dim3(1, Ln / 128, Bn), 256, TCSM>>>(
        (const __half*)p_Wk_h, (const __half*)p_Wk_l, (const __half*)p_xT,
        KC, CIN, KC / 64, 0, (size_t)XTROWS * CIN,
        out, (size_t)CIN * Ln, Ln, conv_b, nullptr);

    // inverse DFT (fp16 2-product) + 1/1024 + bias + gated blend with conv
    k_tc<1><<<dim3(BC / 128, Ln / 128, 1), 256, TCSM>>>(
        (const __half*)p_Ys_h, (const __half*)p_Ys_l, (const __half*)p_Bi,
        NF, NF, NF / 64, 0, 0,
        out, 0, Ln, bias, gate);
}

// round 11
// speedup vs baseline: 5.0524x; 1.2881x over previous
#include <cuda_runtime.h>
#include <cuda_bf16.h>
#include <cuda_fp16.h>
#include <cstdint>

typedef unsigned long long ull;

#define Bn     16
#define CIN    128
#define Hh     8
#define MODESn 256
#define Ln     16384
#define BC     (Bn*CIN)     // 2048
#define NF     (2*MODESn)   // 512
#define SPLITS 4
#define XTROWS 16386        // 1 zero row + 16384 + 1 zero row
#define KC     384          // conv GEMM K = 3*128
#define YSCALE 1024.0f
#define YINV   (1.0f/1024.0f)

// ---------------- device scratch (no allocations allowed) -------------------
__device__ float2        g_sc[Ln];
__device__ __align__(16) __half g_Bf[(size_t)NF*Ln];    // fwd B fp16 (unscaled)
__device__ __align__(16) __half g_Bi[(size_t)Ln*NF];    // inv B fp16
__device__ __align__(16) __half g_xs[(size_t)BC*Ln];    // fwd A fp16 (single)
__device__ float         g_XfP[(size_t)SPLITS*BC*NF];   // split-K partials
__device__ __align__(16) __half g_Ys[(size_t)BC*NF];    // inv A fp16 (x1024, single)
// conv: single-fp16 transposed padded x; W split fp16 (2-product)
__device__ __align__(16) __half g_xT[(size_t)Bn*XTROWS*CIN];
__device__ __align__(16) __half g_Wk_h[CIN*KC];
__device__ __align__(16) __half g_Wk_l[CIN*KC];

// ---------------- ptx helpers -------------------------------------------------
__device__ __forceinline__ uint32_t smem_u32(const void* p) {
    uint32_t a;
    asm("{ .reg .u64 t; cvta.to.shared.u64 t, %1; cvt.u32.u64 %0, t; }" : "=r"(a) : "l"(p));
    return a;
}
__device__ __forceinline__ void cpa16(uint32_t sdst, const void* gsrc) {
    asm volatile("cp.async.cg.shared.global [%0], [%1], 16;" :: "r"(sdst), "l"(gsrc));
}
#define CP_COMMIT() asm volatile("cp.async.commit_group;" ::: "memory")
#define CP_WAIT1()  asm volatile("cp.async.wait_group 1;" ::: "memory")

__device__ __forceinline__ void ldm4(uint32_t* r, uint32_t addr) {
    asm volatile("ldmatrix.sync.aligned.m8n8.x4.shared.b16 {%0,%1,%2,%3}, [%4];"
                 : "=r"(r[0]), "=r"(r[1]), "=r"(r[2]), "=r"(r[3]) : "r"(addr));
}
__device__ __forceinline__ void mma_f16(float* c, const uint32_t* a,
                                        uint32_t b0, uint32_t b1) {
    asm volatile("mma.sync.aligned.m16n8k16.row.col.f32.f16.f16.f32 "
                 "{%0,%1,%2,%3}, {%4,%5,%6,%7}, {%8,%9}, {%0,%1,%2,%3};"
                 : "+f"(c[0]), "+f"(c[1]), "+f"(c[2]), "+f"(c[3])
                 : "r"(a[0]), "r"(a[1]), "r"(a[2]), "r"(a[3]), "r"(b0), "r"(b1));
}
__device__ __forceinline__ void split2h(float v, __half& h, __half& l) {
    h = __float2half(v);
    l = __float2half(v - __half2float(h));
}

// ---------------- init kernels ------------------------------------------------
__global__ void k_sincos() {
    int j = blockIdx.x * 256 + threadIdx.x;
    float s, c;
    sincospif((float)j * (2.0f / Ln), &s, &c);
    g_sc[j] = make_float2(c, s);
}

__global__ void k_fillBf() {                       // [col=512 rows][K=16384], UNSCALED
    int n   = blockIdx.x * 256 + threadIdx.x;
    int col = blockIdx.y;
    int k   = col >> 1;
    float2 sc = g_sc[(k * n) & (Ln - 1)];
    float v = (col & 1) ? (-sc.y) : (sc.x);
    g_Bf[(size_t)col * Ln + n] = __float2half(v);
}

__global__ void k_fillBi() {                       // [n=16384 rows][K=512]
    int j = blockIdx.x * 256 + threadIdx.x;
    int n = blockIdx.y;
    int k = j >> 1;
    float2 sc = g_sc[(k * n) & (Ln - 1)];
    float ck = (k == 0) ? 1.0f : 2.0f;
    float v = (j & 1) ? (-ck * sc.y) : (ck * sc.x);
    g_Bi[(size_t)n * NF + j] = __float2half(v);
}

// fused: x -> single fp16 plane (fwd A) + transposed padded single-fp16 (conv B)
__global__ void __launch_bounds__(256) k_xprep(const float* __restrict__ x) {
    __shared__ float tile[32][33];
    const int b   = blockIdx.z;
    const int ciB = blockIdx.y * 32;
    const int nB  = blockIdx.x * 32;
    const int tx = threadIdx.x, ty = threadIdx.y;     // 32 x 8

#pragma unroll
    for (int j = 0; j < 4; ++j) {
        int ci = ciB + ty + j * 8;
        float v = x[((size_t)b * CIN + ci) * Ln + nB + tx];
        tile[ty + j * 8][tx] = v;
        g_xs[((size_t)b * CIN + ci) * Ln + nB + tx] = __float2half(v);
    }
    __syncthreads();
#pragma unroll
    for (int j = 0; j < 4; ++j) {
        int nl = ty + j * 8;
        float v = tile[tx][nl];
        size_t off = ((size_t)b * XTROWS + 1 + nB + nl) * CIN + ciB + tx;
        g_xT[off] = __float2half(v);
    }
}

// conv weights -> Wk[co][d*128+ci] fp16 split
__global__ void k_wk(const float* __restrict__ w) {
    int idx = blockIdx.x * 256 + threadIdx.x;        // co*384 + d*128 + ci
    if (idx < CIN * KC) {
        int co = idx / KC;
        int r  = idx - co * KC;
        int d  = r >> 7;
        int ci = r & 127;
        float v = w[(co * CIN + ci) * 3 + d];
        __half h, l; split2h(v, h, l);
        g_Wk_h[idx] = h; g_Wk_l[idx] = l;
    }
}

// ---------------- mma.sync fp16 GEMM --------------------------------------------
// C[128,128] tile, BK=64, 8 warps, cp.async double buffer, ldmatrix fragments.
// MODE 0: 1-product, C[z] = A@B^T (fwd, z = k-split)                 [2 planes]
// MODE 1: 1-product, C = g*(A@B^T*YINV + bias) + (1-g)*C (inv blend) [2 planes]
// MODE 2: 2-product, C[z] = (Wh+Wl)@B[z]^T + bias (conv, z = batch)  [3 planes]
#define ROWB   144
#define PLANE  (128*ROWB)                // 18432

template<int MODE>
__global__ void __launch_bounds__(256, 2) k_tc(
    const __half* __restrict__ A0, const __half* __restrict__ A1,
    const __half* __restrict__ Bm,
    int ldA, int ldB, int nChunks, int kSplit, size_t bPlane,
    float* __restrict__ C, size_t cPlane, int ldC,
    const float* __restrict__ bias, const float* __restrict__ gate)
{
    constexpr int NPL = (MODE == 2) ? 3 : 2;        // staged planes per buffer
    constexpr uint32_t BUF = NPL * PLANE;

    extern __shared__ char smraw[];
    const uint32_t smBase = (smem_u32(smraw) + 1023u) & ~1023u;

    const int tid  = threadIdx.x;
    const int lane = tid & 31;
    const int w    = tid >> 5;
    const int wm   = w & 3;
    const int wn   = w >> 2;
    const int mBase = blockIdx.x * 128;
    const int nBase = blockIdx.y * 128;
    const int kOff  = blockIdx.z * kSplit;

    Bm += (size_t)blockIdx.z * bPlane;
    const __half* srcs[3];
    srcs[0] = A0;
    if (MODE == 2) { srcs[1] = A1; srcs[2] = Bm; } else { srcs[1] = Bm; srcs[2] = Bm; }

    const int sRow = tid >> 3;
    const int sC8  = tid & 7;

    const int g = lane >> 2;             // epilogue row group

    const int lrow = lane & 7;
    const int sel0 = (lane >> 3) & 1;
    const int sel1 = (lane >> 4) & 1;
    const uint32_t aLane = (uint32_t)((lrow + sel0 * 8) * ROWB + sel1 * 16);
    const uint32_t bLane = (uint32_t)((lrow + sel1 * 8) * ROWB + sel0 * 16);

    float c[2][8][4];
#pragma unroll
    for (int mt = 0; mt < 2; mt++)
#pragma unroll
        for (int nt = 0; nt < 8; nt++)
#pragma unroll
            for (int q = 0; q < 4; q++) c[mt][nt][q] = 0.f;

    auto loadStage = [&](int st) {
        const int buf = st & 1;
        const int kB  = kOff + st * 64;
        const uint32_t bufBase = smBase + buf * BUF;
#pragma unroll
        for (int p = 0; p < NPL; ++p) {
            const __half* src = srcs[p];
            const int rB = (p < NPL - 1) ? mBase : nBase;
            const int ld = (p < NPL - 1) ? ldA : ldB;
            const __half* g0 = src + (size_t)(rB + sRow) * ld + kB + sC8 * 8;
            const uint32_t d0 = bufBase + p * PLANE + sRow * ROWB + sC8 * 16;
#pragma unroll
            for (int i = 0; i < 4; ++i)
                cpa16(d0 + i * 32 * ROWB, g0 + (size_t)(32 * i) * ld);
        }
    };

    loadStage(0); CP_COMMIT();
    if (nChunks > 1) loadStage(1);
    CP_COMMIT();

#pragma unroll 1
    for (int ch = 0; ch < nChunks; ++ch) {
        CP_WAIT1();
        __syncthreads();

        const uint32_t bufBase = smBase + (ch & 1) * BUF;
        const uint32_t aBase = bufBase + (wm * 32) * ROWB + aLane;
        const uint32_t bBase = bufBase + (NPL - 1) * PLANE + (wn * 64) * ROWB + bLane;

#pragma unroll
        for (int k16 = 0; k16 < 4; ++k16) {
            const uint32_t kb = (uint32_t)(k16 * 32);
            uint32_t a0[2][4], a1[2][4], bh[4][4];

#pragma unroll
            for (int mt = 0; mt < 2; ++mt) {
                const uint32_t rA = aBase + mt * 16 * ROWB + kb;
                ldm4(a0[mt], rA);
                if (MODE == 2) ldm4(a1[mt], rA + PLANE);
            }
#pragma unroll
            for (int pr = 0; pr < 4; ++pr)
                ldm4(bh[pr], bBase + pr * 16 * ROWB + kb);
#pragma unroll
            for (int mt = 0; mt < 2; ++mt)
#pragma unroll
                for (int nt = 0; nt < 8; ++nt) {
                    const int pr = nt >> 1, hf = (nt & 1) * 2;
                    mma_f16(c[mt][nt], a0[mt], bh[pr][hf], bh[pr][hf + 1]);
                    if (MODE == 2)
                        mma_f16(c[mt][nt], a1[mt], bh[pr][hf], bh[pr][hf + 1]);
                }
        }
        __syncthreads();
        if (ch + 2 < nChunks) loadStage(ch + 2);
        CP_COMMIT();
    }

    float gg = 0.f, og = 0.f;
    if (MODE == 1) { gg = 1.0f / (1.0f + expf(-gate[0])); og = 1.0f - gg; }
    float* Cz = C + (size_t)blockIdx.z * cPlane;
#pragma unroll
    for (int mt = 0; mt < 2; ++mt) {
        const int r0 = mBase + wm * 32 + mt * 16 + g;
        float bv0 = 0.f, bv1 = 0.f;
        if (MODE != 0) { bv0 = bias[r0 & (CIN - 1)]; bv1 = bias[(r0 + 8) & (CIN - 1)]; }
#pragma unroll
        for (int nt = 0; nt < 8; ++nt) {
            const int cc = nBase + wn * 64 + nt * 8 + (lane & 3) * 2;
            float* p0 = Cz + (size_t)r0 * ldC + cc;
            float* p1 = Cz + (size_t)(r0 + 8) * ldC + cc;
            if (MODE == 1) {
                float2 o0 = *(const float2*)p0;
                float2 o1 = *(const float2*)p1;
                *(float2*)p0 = make_float2(gg * (c[mt][nt][0] * YINV + bv0) + og * o0.x,
                                           gg * (c[mt][nt][1] * YINV + bv0) + og * o0.y);
                *(float2*)p1 = make_float2(gg * (c[mt][nt][2] * YINV + bv1) + og * o1.x,
                                           gg * (c[mt][nt][3] * YINV + bv1) + og * o1.y);
            } else if (MODE == 2) {
                *(float2*)p0 = make_float2(c[mt][nt][0] + bv0, c[mt][nt][1] + bv0);
                *(float2*)p1 = make_float2(c[mt][nt][2] + bv1, c[mt][nt][3] + bv1);
            } else {
                *(float2*)p0 = make_float2(c[mt][nt][0], c[mt][nt][1]);
                *(float2*)p1 = make_float2(c[mt][nt][2], c[mt][nt][3]);
            }
        }
    }
}

#define TCSM01 (2*2*PLANE + 1024)        // 74752
#define TCSM2  (2*3*PLANE + 1024)        // 111616

// ---------------- per-mode complex 16x16 head mixing ---------------------------
// XfP is UNSCALED (basis had no 1/L): apply 2^-14 here; emit Ys = Y*1024 fp16.
__global__ void __launch_bounds__(128) k_mix(const float* __restrict__ wre,
                                             const float* __restrict__ wim) {
    const int kc = blockIdx.x;
    const int h  = blockIdx.y;
    const int b  = blockIdx.z;
    const int kg = kc * 128 + threadIdx.x;
    const size_t PL = (size_t)BC * NF;
    const float LI = 1.0f / (float)Ln;

    float xr[16], xi[16];
#pragma unroll
    for (int i = 0; i < 16; i++) {
        size_t off = ((size_t)(b * CIN + h * 16 + i) * NF) + 2 * kg;
        float sr = 0.f, si = 0.f;
#pragma unroll
        for (int s = 0; s < SPLITS; s++) {
            float2 v = *(const float2*)&g_XfP[s * PL + off];
            sr += v.x; si += v.y;
        }
        xr[i] = sr * LI; xi[i] = si * LI;
    }
#pragma unroll 1
    for (int o = 0; o < 16; o++) {
        float ar = 0.f, ai = 0.f;
#pragma unroll
        for (int i = 0; i < 16; i++) {
            int widx = ((h * 16 + i) * 16 + o) * MODESn + kg;
            float wr = wre[widx], wi = wim[widx];
            ar = fmaf(xr[i], wr, ar);
            ar = fmaf(-xi[i], wi, ar);
            ai = fmaf(xr[i], wi, ai);
            ai = fmaf(xi[i], wr, ai);
        }
        size_t off = ((size_t)(b * CIN + h * 16 + o) * NF) + 2 * kg;
        g_Ys[off]     = __float2half(ar * YSCALE);
        g_Ys[off + 1] = __float2half(ai * YSCALE);
    }
}

// ---------------- launch --------------------------------------------------------
extern "C" void kernel_launch(void* const* d_in, const int* in_sizes, int n_in,
                              void* d_out, int out_size) {
    const float* x      = (const float*)d_in[0];
    const float* wre    = (const float*)d_in[1];
    const float* wim    = (const float*)d_in[2];
    const float* bias   = (const float*)d_in[3];
    const float* conv_w = (const float*)d_in[4];
    const float* conv_b = (const float*)d_in[5];
    const float* gate   = (const float*)d_in[6];
    float* out = (float*)d_out;

    // Resolve REAL device addresses of __device__ scratch (host shadows are
    // ATS-dereferenceable host memory — NOT the device arrays).
    void *p_xs, *p_Bf, *p_Bi, *p_XfP, *p_Ys, *p_xT, *p_Wk_h, *p_Wk_l;
    cudaGetSymbolAddress(&p_xs, g_xs);
    cudaGetSymbolAddress(&p_Bf, g_Bf);
    cudaGetSymbolAddress(&p_Bi, g_Bi);
    cudaGetSymbolAddress(&p_XfP, g_XfP);
    cudaGetSymbolAddress(&p_Ys, g_Ys);
    cudaGetSymbolAddress(&p_xT, g_xT);
    cudaGetSymbolAddress(&p_Wk_h, g_Wk_h);
    cudaGetSymbolAddress(&p_Wk_l, g_Wk_l);

    cudaFuncSetAttribute(k_tc<0>, cudaFuncAttributeMaxDynamicSharedMemorySize, TCSM01);
    cudaFuncSetAttribute(k_tc<1>, cudaFuncAttributeMaxDynamicSharedMemorySize, TCSM01);
    cudaFuncSetAttribute(k_tc<2>, cudaFuncAttributeMaxDynamicSharedMemorySize, TCSM2);

    // prep (ordered so tc<0> stays the 4th launch -> lands in ncu's window)
    k_sincos<<<Ln / 256, 256>>>();
    k_xprep<<<dim3(Ln / 32, CIN / 32, Bn), dim3(32, 8)>>>(x);
    k_fillBf<<<dim3(Ln / 256, NF), 256>>>();

    // forward DFT (fp16 1-product, split-K=4): g_XfP[s] = xs @ Bf^T  (unscaled)
    k_tc<0><<<dim3(BC / 128, NF / 128, SPLITS), 256, TCSM01>>>(
        (const __half*)p_xs, nullptr, (const __half*)p_Bf,
        Ln, Ln, (Ln / SPLITS) / 64, Ln / SPLITS, 0,
        (float*)p_XfP, (size_t)BC * NF, NF, nullptr, nullptr);

    k_wk<<<(CIN * KC + 255) / 256, 256>>>(conv_w);
    k_fillBi<<<dim3(NF / 256, Ln), 256>>>();

    // complex head mixing (+ split-K reduce, 1/L scale, Ys = Y*1024 fp16)
    k_mix<<<dim3(2, Hh, Bn), 128>>>(wre, wim);

    // conv branch as GEMM (fp16 2-product, W split): out[b] = Wk @ xT[b]^T + conv_b
    k_tc<2><<<dim3(1, Ln / 128, Bn), 256, TCSM2>>>(
        (const __half*)p_Wk_h, (const __half*)p_Wk_l, (const __half*)p_xT,
        KC, CIN, KC / 64, 0, (size_t)XTROWS * CIN,
        out, (size_t)CIN * Ln, Ln, conv_b, nullptr);

    // inverse DFT (fp16 1-product) + 1/1024 + bias + gated blend with conv
    k_tc<1><<<dim3(BC / 128, Ln / 128, 1), 256, TCSM01>>>(
        (const __half*)p_Ys, nullptr, (const __half*)p_Bi,
        NF, NF, NF / 64, 0, 0,
        out, 0, Ln, bias, gate);
}

// round 12
// speedup vs baseline: 6.3530x; 1.2574x over previous
#include <cuda_runtime.h>
#include <cuda_bf16.h>
#include <cuda_fp16.h>
#include <cstdint>

typedef unsigned long long ull;

#define Bn     16
#define CIN    128
#define Hh     8
#define MODESn 256
#define Ln     16384
#define BC     (Bn*CIN)     // 2048
#define NF     (2*MODESn)   // 512
#define SPLITS 4
#define XTROWS 16386        // 1 zero row + 16384 + 1 zero row
#define KC     384          // conv K segment = 3*128
#define YSCALE 1024.0f
#define YINV   (1.0f/1024.0f)

// ---------------- device scratch (no allocations allowed) -------------------
__device__ float2        g_sc[Ln];
__device__ __align__(16) __half g_Bf[(size_t)NF*Ln];    // fwd B fp16 (unscaled)
__device__ __align__(16) __half g_Bi[(size_t)Ln*NF];    // inv B fp16
__device__ __align__(16) __half g_xs[(size_t)BC*Ln];    // fwd A fp16
__device__ float         g_XfP[(size_t)SPLITS*BC*NF];   // split-K partials
__device__ __align__(16) __half g_Ys[(size_t)BC*NF];    // inv A fp16 (x1024)
__device__ __align__(16) __half g_xT[(size_t)Bn*XTROWS*CIN];  // conv B (padded, T)
__device__ __align__(16) __half g_Wg[CIN*KC];           // conv W * (1-g)*YSCALE/g

// ---------------- ptx helpers -------------------------------------------------
__device__ __forceinline__ uint32_t smem_u32(const void* p) {
    uint32_t a;
    asm("{ .reg .u64 t; cvta.to.shared.u64 t, %1; cvt.u32.u64 %0, t; }" : "=r"(a) : "l"(p));
    return a;
}
__device__ __forceinline__ void cpa16(uint32_t sdst, const void* gsrc) {
    asm volatile("cp.async.cg.shared.global [%0], [%1], 16;" :: "r"(sdst), "l"(gsrc));
}
#define CP_COMMIT() asm volatile("cp.async.commit_group;" ::: "memory")
#define CP_WAIT1()  asm volatile("cp.async.wait_group 1;" ::: "memory")

__device__ __forceinline__ void ldm4(uint32_t* r, uint32_t addr) {
    asm volatile("ldmatrix.sync.aligned.m8n8.x4.shared.b16 {%0,%1,%2,%3}, [%4];"
                 : "=r"(r[0]), "=r"(r[1]), "=r"(r[2]), "=r"(r[3]) : "r"(addr));
}
__device__ __forceinline__ void mma_f16(float* c, const uint32_t* a,
                                        uint32_t b0, uint32_t b1) {
    asm volatile("mma.sync.aligned.m16n8k16.row.col.f32.f16.f16.f32 "
                 "{%0,%1,%2,%3}, {%4,%5,%6,%7}, {%8,%9}, {%0,%1,%2,%3};"
                 : "+f"(c[0]), "+f"(c[1]), "+f"(c[2]), "+f"(c[3])
                 : "r"(a[0]), "r"(a[1]), "r"(a[2]), "r"(a[3]), "r"(b0), "r"(b1));
}

// ---------------- init kernels ------------------------------------------------
__global__ void k_sincos() {
    int j = blockIdx.x * 256 + threadIdx.x;
    float s, c;
    sincospif((float)j * (2.0f / Ln), &s, &c);
    g_sc[j] = make_float2(c, s);
}

__global__ void k_fillBf() {                       // [col=512 rows][K=16384], UNSCALED
    int n   = blockIdx.x * 256 + threadIdx.x;
    int col = blockIdx.y;
    int k   = col >> 1;
    float2 sc = g_sc[(k * n) & (Ln - 1)];
    float v = (col & 1) ? (-sc.y) : (sc.x);
    g_Bf[(size_t)col * Ln + n] = __float2half(v);
}

__global__ void k_fillBi() {                       // [n=16384 rows][K=512]
    int j = blockIdx.x * 256 + threadIdx.x;
    int n = blockIdx.y;
    int k = j >> 1;
    float2 sc = g_sc[(k * n) & (Ln - 1)];
    float ck = (k == 0) ? 1.0f : 2.0f;
    float v = (j & 1) ? (-ck * sc.y) : (ck * sc.x);
    g_Bi[(size_t)n * NF + j] = __float2half(v);
}

// fused: x -> single fp16 plane (fwd A) + transposed padded single-fp16 (conv B)
__global__ void __launch_bounds__(256) k_xprep(const float* __restrict__ x) {
    __shared__ float tile[32][33];
    const int b   = blockIdx.z;
    const int ciB = blockIdx.y * 32;
    const int nB  = blockIdx.x * 32;
    const int tx = threadIdx.x, ty = threadIdx.y;     // 32 x 8

#pragma unroll
    for (int j = 0; j < 4; ++j) {
        int ci = ciB + ty + j * 8;
        float v = x[((size_t)b * CIN + ci) * Ln + nB + tx];
        tile[ty + j * 8][tx] = v;
        g_xs[((size_t)b * CIN + ci) * Ln + nB + tx] = __float2half(v);
    }
    __syncthreads();
#pragma unroll
    for (int j = 0; j < 4; ++j) {
        int nl = ty + j * 8;
        float v = tile[tx][nl];
        size_t off = ((size_t)b * XTROWS + 1 + nB + nl) * CIN + ciB + tx;
        g_xT[off] = __float2half(v);
    }
}

// conv weights -> Wg[co][d*128+ci] fp16, pre-scaled by (1-g)*YSCALE/g
__global__ void k_wk(const float* __restrict__ w, const float* __restrict__ gate) {
    int idx = blockIdx.x * 256 + threadIdx.x;        // co*384 + d*128 + ci
    if (idx < CIN * KC) {
        int co = idx / KC;
        int r  = idx - co * KC;
        int d  = r >> 7;
        int ci = r & 127;
        float gg = 1.0f / (1.0f + expf(-gate[0]));
        float alpha = (1.0f - gg) * YSCALE / gg;
        g_Wg[idx] = __float2half(w[(co * CIN + ci) * 3 + d] * alpha);
    }
}

// ---------------- mma.sync fp16 1-product GEMM ---------------------------------
// C[128,128] tile, BK=64, 8 warps, cp.async double buffer, ldmatrix fragments.
// MODE 0: fwd: C[z] = A0 @ B0^T, kOff = z*kSplit, nChunks = kSplit/64.
// MODE 1: fused inverse+conv: 14 chunks; ch<8: Ys(ld512) x Bi(ld512);
//         ch>=8: Wg(ld384) x xT[b](ld128). Epilogue:
//         out = g*YINV*acc + (g*bias + (1-g)*cb).   (b = blockIdx.x)
#define ROWB   144
#define PLANE  (128*ROWB)                // 18432
#define BUF    (2*PLANE)
#define TCSM   (2*BUF + 1024)            // 74752 -> 2 CTAs/SM

template<int MODE>
__global__ void __launch_bounds__(256, 2) k_tc(
    const __half* __restrict__ A0, const __half* __restrict__ B0,
    const __half* __restrict__ A1, const __half* __restrict__ B1,
    int ldA, int ldB, int nChunks, int kSplit,
    float* __restrict__ C, size_t cPlane, int ldC,
    const float* __restrict__ bias, const float* __restrict__ cb,
    const float* __restrict__ gate)
{
    extern __shared__ char smraw[];
    const uint32_t smBase = (smem_u32(smraw) + 1023u) & ~1023u;

    const int tid  = threadIdx.x;
    const int lane = tid & 31;
    const int w    = tid >> 5;
    const int wm   = w & 3;
    const int wn   = w >> 2;
    const int mBase = blockIdx.x * 128;
    const int nBase = blockIdx.y * 128;
    const int kOff  = blockIdx.z * kSplit;

    // conv-segment B base for this batch (MODE 1): xT[b], b = blockIdx.x
    const __half* B1x = (MODE == 1) ? (B1 + (size_t)blockIdx.x * XTROWS * CIN) : B1;

    const int sRow = tid >> 3;
    const int sC8  = tid & 7;

    const int g = lane >> 2;             // epilogue row group

    const int lrow = lane & 7;
    const int sel0 = (lane >> 3) & 1;
    const int sel1 = (lane >> 4) & 1;
    const uint32_t aLane = (uint32_t)((lrow + sel0 * 8) * ROWB + sel1 * 16);
    const uint32_t bLane = (uint32_t)((lrow + sel1 * 8) * ROWB + sel0 * 16);

    float c[2][8][4];
#pragma unroll
    for (int mt = 0; mt < 2; mt++)
#pragma unroll
        for (int nt = 0; nt < 8; nt++)
#pragma unroll
            for (int q = 0; q < 4; q++) c[mt][nt][q] = 0.f;

    auto loadStage = [&](int st) {
        const uint32_t bufBase = smBase + (st & 1) * BUF;
        const __half *gA, *gB;
        int lA, lB;
        if (MODE == 0 || st < 8) {
            const int kB = (MODE == 0 ? kOff + st * 64 : st * 64);
            gA = A0 + (size_t)(mBase + sRow) * ldA + kB + sC8 * 8;
            gB = B0 + (size_t)(nBase + sRow) * ldB + kB + sC8 * 8;
            lA = ldA; lB = ldB;
        } else {
            const int kB = (st - 8) * 64;
            gA = A1 + (size_t)sRow * KC + kB + sC8 * 8;            // Wg row = co
            gB = B1x + (size_t)(nBase + sRow) * CIN + kB + sC8 * 8; // xT overlap rows
            lA = KC; lB = CIN;
        }
        const uint32_t dA = bufBase + sRow * ROWB + sC8 * 16;
        const uint32_t dB = bufBase + PLANE + sRow * ROWB + sC8 * 16;
#pragma unroll
        for (int i = 0; i < 4; ++i) {
            cpa16(dA + i * 32 * ROWB, gA + (size_t)(32 * i) * lA);
            cpa16(dB + i * 32 * ROWB, gB + (size_t)(32 * i) * lB);
        }
    };

    loadStage(0); CP_COMMIT();
    if (nChunks > 1) loadStage(1);
    CP_COMMIT();

#pragma unroll 1
    for (int ch = 0; ch < nChunks; ++ch) {
        CP_WAIT1();
        __syncthreads();

        const uint32_t bufBase = smBase + (ch & 1) * BUF;
        const uint32_t aBase = bufBase + (wm * 32) * ROWB + aLane;
        const uint32_t bBase = bufBase + PLANE + (wn * 64) * ROWB + bLane;

#pragma unroll
        for (int k16 = 0; k16 < 4; ++k16) {
            const uint32_t kb = (uint32_t)(k16 * 32);
            uint32_t a0[2][4], bh[4][4];

#pragma unroll
            for (int mt = 0; mt < 2; ++mt)
                ldm4(a0[mt], aBase + mt * 16 * ROWB + kb);
#pragma unroll
            for (int pr = 0; pr < 4; ++pr)
                ldm4(bh[pr], bBase + pr * 16 * ROWB + kb);
#pragma unroll
            for (int mt = 0; mt < 2; ++mt)
#pragma unroll
                for (int nt = 0; nt < 8; ++nt) {
                    const int pr = nt >> 1, hf = (nt & 1) * 2;
                    mma_f16(c[mt][nt], a0[mt], bh[pr][hf], bh[pr][hf + 1]);
                }
        }
        __syncthreads();
        if (ch + 2 < nChunks) loadStage(ch + 2);
        CP_COMMIT();
    }

    float gg = 0.f, sc = 1.f;
    if (MODE == 1) { gg = 1.0f / (1.0f + expf(-gate[0])); sc = gg * YINV; }
    float* Cz = C + (size_t)blockIdx.z * cPlane;
#pragma unroll
    for (int mt = 0; mt < 2; ++mt) {
        const int r0 = mBase + wm * 32 + mt * 16 + g;
        float bf0 = 0.f, bf1 = 0.f;
        if (MODE == 1) {
            bf0 = gg * bias[r0 & (CIN - 1)] + (1.0f - gg) * cb[r0 & (CIN - 1)];
            bf1 = gg * bias[(r0 + 8) & (CIN - 1)] + (1.0f - gg) * cb[(r0 + 8) & (CIN - 1)];
        }
#pragma unroll
        for (int nt = 0; nt < 8; ++nt) {
            const int cc = nBase + wn * 64 + nt * 8 + (lane & 3) * 2;
            float* p0 = Cz + (size_t)r0 * ldC + cc;
            float* p1 = Cz + (size_t)(r0 + 8) * ldC + cc;
            if (MODE == 1) {
                *(float2*)p0 = make_float2(sc * c[mt][nt][0] + bf0,
                                           sc * c[mt][nt][1] + bf0);
                *(float2*)p1 = make_float2(sc * c[mt][nt][2] + bf1,
                                           sc * c[mt][nt][3] + bf1);
            } else {
                *(float2*)p0 = make_float2(c[mt][nt][0], c[mt][nt][1]);
                *(float2*)p1 = make_float2(c[mt][nt][2], c[mt][nt][3]);
            }
        }
    }
}

// ---------------- per-mode complex 16x16 head mixing ---------------------------
// XfP is UNSCALED (basis had no 1/L): apply 2^-14 here; emit Ys = Y*1024 fp16.
__global__ void __launch_bounds__(128) k_mix(const float* __restrict__ wre,
                                             const float* __restrict__ wim) {
    const int kc = blockIdx.x;
    const int h  = blockIdx.y;
    const int b  = blockIdx.z;
    const int kg = kc * 128 + threadIdx.x;
    const size_t PL = (size_t)BC * NF;
    const float LI = 1.0f / (float)Ln;

    float xr[16], xi[16];
#pragma unroll
    for (int i = 0; i < 16; i++) {
        size_t off = ((size_t)(b * CIN + h * 16 + i) * NF) + 2 * kg;
        float sr = 0.f, si = 0.f;
#pragma unroll
        for (int s = 0; s < SPLITS; s++) {
            float2 v = *(const float2*)&g_XfP[s * PL + off];
            sr += v.x; si += v.y;
        }
        xr[i] = sr * LI; xi[i] = si * LI;
    }
#pragma unroll 1
    for (int o = 0; o < 16; o++) {
        float ar = 0.f, ai = 0.f;
#pragma unroll
        for (int i = 0; i < 16; i++) {
            int widx = ((h * 16 + i) * 16 + o) * MODESn + kg;
            float wr = wre[widx], wi = wim[widx];
            ar = fmaf(xr[i], wr, ar);
            ar = fmaf(-xi[i], wi, ar);
            ai = fmaf(xr[i], wi, ai);
            ai = fmaf(xi[i], wr, ai);
        }
        size_t off = ((size_t)(b * CIN + h * 16 + o) * NF) + 2 * kg;
        g_Ys[off]     = __float2half(ar * YSCALE);
        g_Ys[off + 1] = __float2half(ai * YSCALE);
    }
}

// ---------------- launch --------------------------------------------------------
extern "C" void kernel_launch(void* const* d_in, const int* in_sizes, int n_in,
                              void* d_out, int out_size) {
    const float* x      = (const float*)d_in[0];
    const float* wre    = (const float*)d_in[1];
    const float* wim    = (const float*)d_in[2];
    const float* bias   = (const float*)d_in[3];
    const float* conv_w = (const float*)d_in[4];
    const float* conv_b = (const float*)d_in[5];
    const float* gate   = (const float*)d_in[6];
    float* out = (float*)d_out;

    // Resolve REAL device addresses of __device__ scratch (host shadows are
    // ATS-dereferenceable host memory — NOT the device arrays).
    void *p_xs, *p_Bf, *p_Bi, *p_XfP, *p_Ys, *p_xT, *p_Wg;
    cudaGetSymbolAddress(&p_xs, g_xs);
    cudaGetSymbolAddress(&p_Bf, g_Bf);
    cudaGetSymbolAddress(&p_Bi, g_Bi);
    cudaGetSymbolAddress(&p_XfP, g_XfP);
    cudaGetSymbolAddress(&p_Ys, g_Ys);
    cudaGetSymbolAddress(&p_xT, g_xT);
    cudaGetSymbolAddress(&p_Wg, g_Wg);

    cudaFuncSetAttribute(k_tc<0>, cudaFuncAttributeMaxDynamicSharedMemorySize, TCSM);
    cudaFuncSetAttribute(k_tc<1>, cudaFuncAttributeMaxDynamicSharedMemorySize, TCSM);

    // prep (tc<0> stays the 4th launch -> lands in ncu's window)
    k_sincos<<<Ln / 256, 256>>>();
    k_xprep<<<dim3(Ln / 32, CIN / 32, Bn), dim3(32, 8)>>>(x);
    k_fillBf<<<dim3(Ln / 256, NF), 256>>>();

    // forward DFT (fp16 1-product, split-K=4): g_XfP[s] = xs @ Bf^T (unscaled)
    k_tc<0><<<dim3(BC / 128, NF / 128, SPLITS), 256, TCSM>>>(
        (const __half*)p_xs, (const __half*)p_Bf, nullptr, nullptr,
        Ln, Ln, (Ln / SPLITS) / 64, Ln / SPLITS,
        (float*)p_XfP, (size_t)BC * NF, NF, nullptr, nullptr, nullptr);

    k_wk<<<(CIN * KC + 255) / 256, 256>>>(conv_w, gate);
    k_fillBi<<<dim3(NF / 256, Ln), 256>>>();

    // complex head mixing (+ split-K reduce, 1/L scale, Ys = Y*1024 fp16)
    k_mix<<<dim3(2, Hh, Bn), 128>>>(wre, wim);

    // fused inverse DFT + conv + bias + gated blend, K = 512 + 384
    k_tc<1><<<dim3(BC / 128, Ln / 128, 1), 256, TCSM>>>(
        (const __half*)p_Ys, (const __half*)p_Bi,
        (const __half*)p_Wg, (const __half*)p_xT,
        NF, NF, (NF + KC) / 64, 0,
        out, 0, Ln, bias, conv_b, gate);
}

// round 13
// speedup vs baseline: 7.6051x; 1.1971x over previous
#include <cuda_runtime.h>
#include <cuda_bf16.h>
#include <cuda_fp16.h>
#include <cstdint>

typedef unsigned long long ull;

#define Bn     16
#define CIN    128
#define Hh     8
#define MODESn 256
#define Ln     16384
#define LH     8192         // L/2 (radix-2 fold)
#define BC     (Bn*CIN)     // 2048
#define NF     (2*MODESn)   // 512
#define SPLITS 4
#define XTROWS 16386        // 1 zero row + 16384 + 1 zero row
#define KC     384          // conv K segment = 3*128
#define YSCALE 1024.0f
#define YINV   (1.0f/1024.0f)

// ---------------- device scratch (no allocations allowed) -------------------
__device__ float2        g_sc[Ln];
// folded fwd A: [group][2048][8192]; group 0 = xe (even k), 1 = xo (odd k)
__device__ __align__(16) __half g_xf[(size_t)2*BC*LH];
// folded fwd B: [group][256 rows][8192]; row 2m = cos, 2m+1 = -sin for k=2m+g
__device__ __align__(16) __half g_Bf[(size_t)2*MODESn*LH];
__device__ __align__(16) __half g_Bi[(size_t)Ln*NF];    // inv B fp16
__device__ float         g_XfP[(size_t)SPLITS*BC*NF];   // split-K partials (group-major cols)
__device__ __align__(16) __half g_Ys[(size_t)BC*NF];    // inv A fp16 (x1024)
__device__ __align__(16) __half g_xT[(size_t)Bn*XTROWS*CIN];  // conv B (padded, T)
__device__ __align__(16) __half g_Wg[CIN*KC];           // conv W * (1-g)*YSCALE/g

// ---------------- ptx helpers -------------------------------------------------
__device__ __forceinline__ uint32_t smem_u32(const void* p) {
    uint32_t a;
    asm("{ .reg .u64 t; cvta.to.shared.u64 t, %1; cvt.u32.u64 %0, t; }" : "=r"(a) : "l"(p));
    return a;
}
__device__ __forceinline__ void cpa16(uint32_t sdst, const void* gsrc) {
    asm volatile("cp.async.cg.shared.global [%0], [%1], 16;" :: "r"(sdst), "l"(gsrc));
}
#define CP_COMMIT() asm volatile("cp.async.commit_group;" ::: "memory")
#define CP_WAIT1()  asm volatile("cp.async.wait_group 1;" ::: "memory")

__device__ __forceinline__ void ldm4(uint32_t* r, uint32_t addr) {
    asm volatile("ldmatrix.sync.aligned.m8n8.x4.shared.b16 {%0,%1,%2,%3}, [%4];"
                 : "=r"(r[0]), "=r"(r[1]), "=r"(r[2]), "=r"(r[3]) : "r"(addr));
}
__device__ __forceinline__ void mma_f16(float* c, const uint32_t* a,
                                        uint32_t b0, uint32_t b1) {
    asm volatile("mma.sync.aligned.m16n8k16.row.col.f32.f16.f16.f32 "
                 "{%0,%1,%2,%3}, {%4,%5,%6,%7}, {%8,%9}, {%0,%1,%2,%3};"
                 : "+f"(c[0]), "+f"(c[1]), "+f"(c[2]), "+f"(c[3])
                 : "r"(a[0]), "r"(a[1]), "r"(a[2]), "r"(a[3]), "r"(b0), "r"(b1));
}

// ---------------- init kernels ------------------------------------------------
__global__ void k_sincos() {
    int j = blockIdx.x * 256 + threadIdx.x;
    float s, c;
    sincospif((float)j * (2.0f / Ln), &s, &c);
    g_sc[j] = make_float2(c, s);
}

// folded forward basis: [g][j][n], k = 2*(j>>1)+g, n<8192 (unscaled)
__global__ void k_fillBf() {
    int n  = blockIdx.x * 256 + threadIdx.x;     // 0..8191
    int jj = blockIdx.y;                         // 0..511
    int gp = jj >> 8;
    int j  = jj & 255;
    int k  = 2 * (j >> 1) + gp;
    float2 sc = g_sc[(k * n) & (Ln - 1)];
    float v = (j & 1) ? (-sc.y) : (sc.x);
    g_Bf[((size_t)gp * MODESn + j) * LH + n] = __float2half(v);
}

__global__ void k_fillBi() {                     // [n=16384 rows][K=512]
    int j = blockIdx.x * 256 + threadIdx.x;
    int n = blockIdx.y;
    int k = j >> 1;
    float2 sc = g_sc[(k * n) & (Ln - 1)];
    float ck = (k == 0) ? 1.0f : 2.0f;
    float v = (j & 1) ? (-ck * sc.y) : (ck * sc.x);
    g_Bi[(size_t)n * NF + j] = __float2half(v);
}

// fused: x -> radix-2 folds xe/xo (fwd A) + transposed padded fp16 (conv B)
// grid (8192/32, CIN/32, Bn), block (32,8). Lower half n = nB+tx, upper +8192.
__global__ void __launch_bounds__(256) k_xprep(const float* __restrict__ x) {
    __shared__ float t0[32][33];
    __shared__ float t1[32][33];
    const int b   = blockIdx.z;
    const int ciB = blockIdx.y * 32;
    const int nB  = blockIdx.x * 32;
    const int tx = threadIdx.x, ty = threadIdx.y;

#pragma unroll
    for (int j = 0; j < 4; ++j) {
        int ci = ciB + ty + j * 8;
        size_t base = ((size_t)b * CIN + ci) * Ln + nB + tx;
        float v0 = x[base];
        float v1 = x[base + LH];
        t0[ty + j * 8][tx] = v0;
        t1[ty + j * 8][tx] = v1;
        size_t fo = ((size_t)b * CIN + ci) * LH + nB + tx;
        g_xf[fo]                    = __float2half(v0 + v1);   // xe (even k)
        g_xf[(size_t)BC * LH + fo]  = __float2half(v0 - v1);   // xo (odd k)
    }
    __syncthreads();
#pragma unroll
    for (int j = 0; j < 4; ++j) {
        int nl = ty + j * 8;
        float a  = t0[tx][nl];
        float bu = t1[tx][nl];
        size_t lo = ((size_t)b * XTROWS + 1 + nB + nl) * CIN + ciB + tx;
        g_xT[lo]                          = __float2half(a);
        g_xT[lo + (size_t)LH * CIN]       = __float2half(bu);
    }
}

// conv weights -> Wg[co][d*128+ci] fp16, pre-scaled by (1-g)*YSCALE/g
__global__ void k_wk(const float* __restrict__ w, const float* __restrict__ gate) {
    int idx = blockIdx.x * 256 + threadIdx.x;
    if (idx < CIN * KC) {
        int co = idx / KC;
        int r  = idx - co * KC;
        int d  = r >> 7;
        int ci = r & 127;
        float gg = 1.0f / (1.0f + expf(-gate[0]));
        float alpha = (1.0f - gg) * YSCALE / gg;
        g_Wg[idx] = __float2half(w[(co * CIN + ci) * 3 + d] * alpha);
    }
}

// ---------------- mma.sync fp16 1-product GEMM ---------------------------------
// C[128,128] tile, BK=64, 8 warps, cp.async double buffer, ldmatrix fragments.
// MODE 0: folded fwd. blockIdx.z = group*SPLITS + split. A/B offset by group
//         planes (aPlane/bPlane); C col offset group*256. kOff = split*kSplit.
// MODE 1: fused inverse+conv: 14 chunks; ch<8: Ys(ld512) x Bi(ld512);
//         ch>=8: Wg(ld384) x xT[b](ld128). out = g*YINV*acc + (g*bias+(1-g)*cb).
#define ROWB   144
#define PLANE  (128*ROWB)
#define BUF    (2*PLANE)
#define TCSM   (2*BUF + 1024)            // 74752 -> 2 CTAs/SM

template<int MODE>
__global__ void __launch_bounds__(256, 2) k_tc(
    const __half* __restrict__ A0, const __half* __restrict__ B0,
    const __half* __restrict__ A1, const __half* __restrict__ B1,
    int ldA, int ldB, int nChunks, int kSplit, size_t aPlane, size_t bPlane,
    float* __restrict__ C, size_t cPlane, int ldC,
    const float* __restrict__ bias, const float* __restrict__ cb,
    const float* __restrict__ gate)
{
    extern __shared__ char smraw[];
    const uint32_t smBase = (smem_u32(smraw) + 1023u) & ~1023u;

    const int tid  = threadIdx.x;
    const int lane = tid & 31;
    const int w    = tid >> 5;
    const int wm   = w & 3;
    const int wn   = w >> 2;
    const int mBase = blockIdx.x * 128;
    const int nBase = blockIdx.y * 128;

    int grp = 0, spl = blockIdx.z;
    if (MODE == 0) { grp = blockIdx.z >> 2; spl = blockIdx.z & 3; }
    const int kOff = spl * kSplit;
    A0 += (size_t)grp * aPlane;
    B0 += (size_t)grp * bPlane;

    // conv-segment B base for this batch (MODE 1): xT[b], b = blockIdx.x
    const __half* B1x = (MODE == 1) ? (B1 + (size_t)blockIdx.x * XTROWS * CIN) : B1;

    const int sRow = tid >> 3;
    const int sC8  = tid & 7;

    const int g = lane >> 2;             // epilogue row group

    const int lrow = lane & 7;
    const int sel0 = (lane >> 3) & 1;
    const int sel1 = (lane >> 4) & 1;
    const uint32_t aLane = (uint32_t)((lrow + sel0 * 8) * ROWB + sel1 * 16);
    const uint32_t bLane = (uint32_t)((lrow + sel1 * 8) * ROWB + sel0 * 16);

    float c[2][8][4];
#pragma unroll
    for (int mt = 0; mt < 2; mt++)
#pragma unroll
        for (int nt = 0; nt < 8; nt++)
#pragma unroll
            for (int q = 0; q < 4; q++) c[mt][nt][q] = 0.f;

    auto loadStage = [&](int st) {
        const uint32_t bufBase = smBase + (st & 1) * BUF;
        const __half *gA, *gB;
        int lA, lB;
        if (MODE == 0 || st < 8) {
            const int kB = kOff + st * 64;
            gA = A0 + (size_t)(mBase + sRow) * ldA + kB + sC8 * 8;
            gB = B0 + (size_t)(nBase + sRow) * ldB + kB + sC8 * 8;
            lA = ldA; lB = ldB;
        } else {
            const int kB = (st - 8) * 64;
            gA = A1 + (size_t)sRow * KC + kB + sC8 * 8;             // Wg row = co
            gB = B1x + (size_t)(nBase + sRow) * CIN + kB + sC8 * 8; // xT overlap rows
            lA = KC; lB = CIN;
        }
        const uint32_t dA = bufBase + sRow * ROWB + sC8 * 16;
        const uint32_t dB = bufBase + PLANE + sRow * ROWB + sC8 * 16;
#pragma unroll
        for (int i = 0; i < 4; ++i) {
            cpa16(dA + i * 32 * ROWB, gA + (size_t)(32 * i) * lA);
            cpa16(dB + i * 32 * ROWB, gB + (size_t)(32 * i) * lB);
        }
    };

    loadStage(0); CP_COMMIT();
    if (nChunks > 1) loadStage(1);
    CP_COMMIT();

#pragma unroll 1
    for (int ch = 0; ch < nChunks; ++ch) {
        CP_WAIT1();
        __syncthreads();

        const uint32_t bufBase = smBase + (ch & 1) * BUF;
        const uint32_t aBase = bufBase + (wm * 32) * ROWB + aLane;
        const uint32_t bBase = bufBase + PLANE + (wn * 64) * ROWB + bLane;

#pragma unroll
        for (int k16 = 0; k16 < 4; ++k16) {
            const uint32_t kb = (uint32_t)(k16 * 32);
            uint32_t a0[2][4], bh[4][4];

#pragma unroll
            for (int mt = 0; mt < 2; ++mt)
                ldm4(a0[mt], aBase + mt * 16 * ROWB + kb);
#pragma unroll
            for (int pr = 0; pr < 4; ++pr)
                ldm4(bh[pr], bBase + pr * 16 * ROWB + kb);
#pragma unroll
            for (int mt = 0; mt < 2; ++mt)
#pragma unroll
                for (int nt = 0; nt < 8; ++nt) {
                    const int pr = nt >> 1, hf = (nt & 1) * 2;
                    mma_f16(c[mt][nt], a0[mt], bh[pr][hf], bh[pr][hf + 1]);
                }
        }
        __syncthreads();
        if (ch + 2 < nChunks) loadStage(ch + 2);
        CP_COMMIT();
    }

    float gg = 0.f, sc = 1.f;
    if (MODE == 1) { gg = 1.0f / (1.0f + expf(-gate[0])); sc = gg * YINV; }
    float* Cz = C + (size_t)spl * cPlane + (MODE == 0 ? grp * 256 : 0);
#pragma unroll
    for (int mt = 0; mt < 2; ++mt) {
        const int r0 = mBase + wm * 32 + mt * 16 + g;
        float bf0 = 0.f, bf1 = 0.f;
        if (MODE == 1) {
            bf0 = gg * bias[r0 & (CIN - 1)] + (1.0f - gg) * cb[r0 & (CIN - 1)];
            bf1 = gg * bias[(r0 + 8) & (CIN - 1)] + (1.0f - gg) * cb[(r0 + 8) & (CIN - 1)];
        }
#pragma unroll
        for (int nt = 0; nt < 8; ++nt) {
            const int cc = nBase + wn * 64 + nt * 8 + (lane & 3) * 2;
            float* p0 = Cz + (size_t)r0 * ldC + cc;
            float* p1 = Cz + (size_t)(r0 + 8) * ldC + cc;
            if (MODE == 1) {
                *(float2*)p0 = make_float2(sc * c[mt][nt][0] + bf0,
                                           sc * c[mt][nt][1] + bf0);
                *(float2*)p1 = make_float2(sc * c[mt][nt][2] + bf1,
                                           sc * c[mt][nt][3] + bf1);
            } else {
                *(float2*)p0 = make_float2(c[mt][nt][0], c[mt][nt][1]);
                *(float2*)p1 = make_float2(c[mt][nt][2], c[mt][nt][3]);
            }
        }
    }
}

// ---------------- per-mode complex 16x16 head mixing ---------------------------
// XfP cols are group-major: col(Re_k) = (k&1)*256 + (k>>1)*2. Apply 1/L; emit
// Ys = Y*1024 fp16 in standard interleaved layout.
__global__ void __launch_bounds__(128) k_mix(const float* __restrict__ wre,
                                             const float* __restrict__ wim) {
    const int kc = blockIdx.x;
    const int h  = blockIdx.y;
    const int b  = blockIdx.z;
    const int kg = kc * 128 + threadIdx.x;
    const size_t PL = (size_t)BC * NF;
    const float LI = 1.0f / (float)Ln;
    const int colRe = (kg & 1) * 256 + (kg >> 1) * 2;

    float xr[16], xi[16];
#pragma unroll
    for (int i = 0; i < 16; i++) {
        size_t off = ((size_t)(b * CIN + h * 16 + i) * NF) + colRe;
        float sr = 0.f, si = 0.f;
#pragma unroll
        for (int s = 0; s < SPLITS; s++) {
            float2 v = *(const float2*)&g_XfP[s * PL + off];
            sr += v.x; si += v.y;
        }
        xr[i] = sr * LI; xi[i] = si * LI;
    }
#pragma unroll 1
    for (int o = 0; o < 16; o++) {
        float ar = 0.f, ai = 0.f;
#pragma unroll
        for (int i = 0; i < 16; i++) {
            int widx = ((h * 16 + i) * 16 + o) * MODESn + kg;
            float wr = wre[widx], wi = wim[widx];
            ar = fmaf(xr[i], wr, ar);
            ar = fmaf(-xi[i], wi, ar);
            ai = fmaf(xr[i], wi, ai);
            ai = fmaf(xi[i], wr, ai);
        }
        size_t off = ((size_t)(b * CIN + h * 16 + o) * NF) + 2 * kg;
        g_Ys[off]     = __float2half(ar * YSCALE);
        g_Ys[off + 1] = __float2half(ai * YSCALE);
    }
}

// ---------------- launch --------------------------------------------------------
extern "C" void kernel_launch(void* const* d_in, const int* in_sizes, int n_in,
                              void* d_out, int out_size) {
    const float* x      = (const float*)d_in[0];
    const float* wre    = (const float*)d_in[1];
    const float* wim    = (const float*)d_in[2];
    const float* bias   = (const float*)d_in[3];
    const float* conv_w = (const float*)d_in[4];
    const float* conv_b = (const float*)d_in[5];
    const float* gate   = (const float*)d_in[6];
    float* out = (float*)d_out;

    // Resolve REAL device addresses of __device__ scratch (host shadows are
    // ATS-dereferenceable host memory — NOT the device arrays).
    void *p_xf, *p_Bf, *p_Bi, *p_XfP, *p_Ys, *p_xT, *p_Wg;
    cudaGetSymbolAddress(&p_xf, g_xf);
    cudaGetSymbolAddress(&p_Bf, g_Bf);
    cudaGetSymbolAddress(&p_Bi, g_Bi);
    cudaGetSymbolAddress(&p_XfP, g_XfP);
    cudaGetSymbolAddress(&p_Ys, g_Ys);
    cudaGetSymbolAddress(&p_xT, g_xT);
    cudaGetSymbolAddress(&p_Wg, g_Wg);

    cudaFuncSetAttribute(k_tc<0>, cudaFuncAttributeMaxDynamicSharedMemorySize, TCSM);
    cudaFuncSetAttribute(k_tc<1>, cudaFuncAttributeMaxDynamicSharedMemorySize, TCSM);

    // prep (tc<0> stays the 4th launch -> lands in ncu's window)
    k_sincos<<<Ln / 256, 256>>>();
    k_xprep<<<dim3(LH / 32, CIN / 32, Bn), dim3(32, 8)>>>(x);
    k_fillBf<<<dim3(LH / 256, NF), 256>>>();

    // folded forward DFT (fp16, radix-2): per group g, XfP cols [g*256, g*256+256)
    // = xf[g] @ Bf[g]^T, K = 8192, split-K = 4. grid z = group*4 + split.
    k_tc<0><<<dim3(BC / 128, 2, 2 * SPLITS), 256, TCSM>>>(
        (const __half*)p_xf, (const __half*)p_Bf, nullptr, nullptr,
        LH, LH, (LH / SPLITS) / 64, LH / SPLITS,
        (size_t)BC * LH, (size_t)MODESn * LH,
        (float*)p_XfP, (size_t)BC * NF, NF, nullptr, nullptr, nullptr);

    k_wk<<<(CIN * KC + 255) / 256, 256>>>(conv_w, gate);
    k_fillBi<<<dim3(NF / 256, Ln), 256>>>();

    // complex head mixing (+ split-K reduce, 1/L scale, Ys = Y*1024 fp16)
    k_mix<<<dim3(2, Hh, Bn), 128>>>(wre, wim);

    // fused inverse DFT + conv + bias + gated blend, K = 512 + 384
    k_tc<1><<<dim3(BC / 128, Ln / 128, 1), 256, TCSM>>>(
        (const __half*)p_Ys, (const __half*)p_Bi,
        (const __half*)p_Wg, (const __half*)p_xT,
        NF, NF, (NF + KC) / 64, 0, 0, 0,
        out, 0, Ln, bias, conv_b, gate);
}

// round 14
// speedup vs baseline: 7.6388x; 1.0044x over previous
#include <cuda_runtime.h>
#include <cuda_bf16.h>
#include <cuda_fp16.h>
#include <cstdint>

typedef unsigned long long ull;

#define Bn     16
#define CIN    128
#define Hh     8
#define MODESn 256
#define Ln     16384
#define LH     8192         // L/2 (radix-2 fold)
#define BC     (Bn*CIN)     // 2048
#define NF     (2*MODESn)   // 512
#define SPLITS 4
#define XTROWS 16386        // 1 zero row + 16384 + 1 zero row
#define KC     384          // conv K segment = 3*128
#define YSCALE 1024.0f
#define YINV   (1.0f/1024.0f)

// ---------------- device scratch (no allocations allowed) -------------------
// folded fwd A: [group][2048][8192]; group 0 = xe (even k), 1 = xo (odd k)
__device__ __align__(16) __half g_xf[(size_t)2*BC*LH];
// folded fwd B: [group][256 rows][8192]; row 2m = cos, 2m+1 = -sin for k=2m+g
__device__ __align__(16) __half g_Bf[(size_t)2*MODESn*LH];
__device__ __align__(16) __half g_Bi[(size_t)Ln*NF];    // inv B fp16
__device__ float         g_XfP[(size_t)SPLITS*BC*NF];   // split-K partials (group-major cols)
__device__ __align__(16) __half g_Ys[(size_t)BC*NF];    // inv A fp16 (x1024)
__device__ __align__(16) __half g_xT[(size_t)Bn*XTROWS*CIN];  // conv B (padded, T)
__device__ __align__(16) __half g_Wg[CIN*KC];           // conv W * (1-g)*YSCALE/g

// ---------------- ptx helpers -------------------------------------------------
__device__ __forceinline__ uint32_t smem_u32(const void* p) {
    uint32_t a;
    asm("{ .reg .u64 t; cvta.to.shared.u64 t, %1; cvt.u32.u64 %0, t; }" : "=r"(a) : "l"(p));
    return a;
}
__device__ __forceinline__ void cpa16(uint32_t sdst, const void* gsrc) {
    asm volatile("cp.async.cg.shared.global [%0], [%1], 16;" :: "r"(sdst), "l"(gsrc));
}
#define CP_COMMIT() asm volatile("cp.async.commit_group;" ::: "memory")
#define CP_WAIT1()  asm volatile("cp.async.wait_group 1;" ::: "memory")

__device__ __forceinline__ void ldm4(uint32_t* r, uint32_t addr) {
    asm volatile("ldmatrix.sync.aligned.m8n8.x4.shared.b16 {%0,%1,%2,%3}, [%4];"
                 : "=r"(r[0]), "=r"(r[1]), "=r"(r[2]), "=r"(r[3]) : "r"(addr));
}
__device__ __forceinline__ void mma_f16(float* c, const uint32_t* a,
                                        uint32_t b0, uint32_t b1) {
    asm volatile("mma.sync.aligned.m16n8k16.row.col.f32.f16.f16.f32 "
                 "{%0,%1,%2,%3}, {%4,%5,%6,%7}, {%8,%9}, {%0,%1,%2,%3};"
                 : "+f"(c[0]), "+f"(c[1]), "+f"(c[2]), "+f"(c[3])
                 : "r"(a[0]), "r"(a[1]), "r"(a[2]), "r"(a[3]), "r"(b0), "r"(b1));
}

// ---------------- init kernels ------------------------------------------------
// folded forward basis: [g][j][n], k = 2*(j>>1)+g, n<8192 (unscaled)
__global__ void k_fillBf() {
    int n  = blockIdx.x * 256 + threadIdx.x;     // 0..8191
    int jj = blockIdx.y;                         // 0..511
    int gp = jj >> 8;
    int j  = jj & 255;
    int k  = 2 * (j >> 1) + gp;
    int idx = (k * n) & (Ln - 1);
    float s, c;
    sincospif((float)idx * (2.0f / Ln), &s, &c);
    float v = (j & 1) ? (-s) : (c);
    g_Bf[((size_t)gp * MODESn + j) * LH + n] = __float2half(v);
}

__global__ void k_fillBi() {                     // [n=16384 rows][K=512]
    int j = blockIdx.x * 256 + threadIdx.x;
    int n = blockIdx.y;
    int k = j >> 1;
    int idx = (k * n) & (Ln - 1);
    float s, c;
    sincospif((float)idx * (2.0f / Ln), &s, &c);
    float ck = (k == 0) ? 1.0f : 2.0f;
    float v = (j & 1) ? (-ck * s) : (ck * c);
    g_Bi[(size_t)n * NF + j] = __float2half(v);
}

// fused: x -> radix-2 folds xe/xo (fwd A) + transposed padded fp16 (conv B)
__global__ void __launch_bounds__(256) k_xprep(const float* __restrict__ x) {
    __shared__ float t0[32][33];
    __shared__ float t1[32][33];
    const int b   = blockIdx.z;
    const int ciB = blockIdx.y * 32;
    const int nB  = blockIdx.x * 32;
    const int tx = threadIdx.x, ty = threadIdx.y;

#pragma unroll
    for (int j = 0; j < 4; ++j) {
        int ci = ciB + ty + j * 8;
        size_t base = ((size_t)b * CIN + ci) * Ln + nB + tx;
        float v0 = x[base];
        float v1 = x[base + LH];
        t0[ty + j * 8][tx] = v0;
        t1[ty + j * 8][tx] = v1;
        size_t fo = ((size_t)b * CIN + ci) * LH + nB + tx;
        g_xf[fo]                    = __float2half(v0 + v1);   // xe (even k)
        g_xf[(size_t)BC * LH + fo]  = __float2half(v0 - v1);   // xo (odd k)
    }
    __syncthreads();
#pragma unroll
    for (int j = 0; j < 4; ++j) {
        int nl = ty + j * 8;
        float a  = t0[tx][nl];
        float bu = t1[tx][nl];
        size_t lo = ((size_t)b * XTROWS + 1 + nB + nl) * CIN + ciB + tx;
        g_xT[lo]                    = __float2half(a);
        g_xT[lo + (size_t)LH * CIN] = __float2half(bu);
    }
}

// conv weights -> Wg[co][d*128+ci] fp16, pre-scaled by (1-g)*YSCALE/g
__global__ void k_wk(const float* __restrict__ w, const float* __restrict__ gate) {
    int idx = blockIdx.x * 256 + threadIdx.x;
    if (idx < CIN * KC) {
        int co = idx / KC;
        int r  = idx - co * KC;
        int d  = r >> 7;
        int ci = r & 127;
        float gg = 1.0f / (1.0f + expf(-gate[0]));
        float alpha = (1.0f - gg) * YSCALE / gg;
        g_Wg[idx] = __float2half(w[(co * CIN + ci) * 3 + d] * alpha);
    }
}

// ---------------- mma.sync fp16 1-product GEMM ---------------------------------
// C[128,128] tile, BK=64, 8 warps, cp.async TRIPLE buffer (1 barrier/chunk),
// ldmatrix fragments, 144B-padded rows.
// MODE 0: folded fwd. blockIdx.z = group*SPLITS + split. A/B offset by group
//         planes (aPlane/bPlane); C col offset group*256. kOff = split*kSplit.
// MODE 1: fused inverse+conv: 14 chunks; ch<8: Ys(ld512) x Bi(ld512);
//         ch>=8: Wg(ld384) x xT[b](ld128). out = g*YINV*acc + (g*bias+(1-g)*cb).
#define ROWB   144
#define PLANE  (128*ROWB)                // 18432
#define BUF    (2*PLANE)                 // 36864
#define TCSM   (3*BUF + 1024)            // 111616 -> 2 CTAs/SM (223KB < 228KB)

template<int MODE>
__global__ void __launch_bounds__(256, 2) k_tc(
    const __half* __restrict__ A0, const __half* __restrict__ B0,
    const __half* __restrict__ A1, const __half* __restrict__ B1,
    int ldA, int ldB, int nChunks, int kSplit, size_t aPlane, size_t bPlane,
    float* __restrict__ C, size_t cPlane, int ldC,
    const float* __restrict__ bias, const float* __restrict__ cb,
    const float* __restrict__ gate)
{
    extern __shared__ char smraw[];
    const uint32_t smBase = (smem_u32(smraw) + 1023u) & ~1023u;

    const int tid  = threadIdx.x;
    const int lane = tid & 31;
    const int w    = tid >> 5;
    const int wm   = w & 3;
    const int wn   = w >> 2;
    const int mBase = blockIdx.x * 128;
    const int nBase = blockIdx.y * 128;

    int grp = 0, spl = blockIdx.z;
    if (MODE == 0) { grp = blockIdx.z >> 2; spl = blockIdx.z & 3; }
    const int kOff = spl * kSplit;
    A0 += (size_t)grp * aPlane;
    B0 += (size_t)grp * bPlane;

    // conv-segment B base for this batch (MODE 1): xT[b], b = blockIdx.x
    const __half* B1x = (MODE == 1) ? (B1 + (size_t)blockIdx.x * XTROWS * CIN) : B1;

    const int sRow = tid >> 3;
    const int sC8  = tid & 7;

    const int g = lane >> 2;             // epilogue row group

    const int lrow = lane & 7;
    const int sel0 = (lane >> 3) & 1;
    const int sel1 = (lane >> 4) & 1;
    const uint32_t aLane = (uint32_t)((lrow + sel0 * 8) * ROWB + sel1 * 16);
    const uint32_t bLane = (uint32_t)((lrow + sel1 * 8) * ROWB + sel0 * 16);

    float c[2][8][4];
#pragma unroll
    for (int mt = 0; mt < 2; mt++)
#pragma unroll
        for (int nt = 0; nt < 8; nt++)
#pragma unroll
            for (int q = 0; q < 4; q++) c[mt][nt][q] = 0.f;

    auto loadStage = [&](int st) {
        const uint32_t bufBase = smBase + (uint32_t)(st % 3) * BUF;
        const __half *gA, *gB;
        int lA, lB;
        if (MODE == 0 || st < 8) {
            const int kB = kOff + st * 64;
            gA = A0 + (size_t)(mBase + sRow) * ldA + kB + sC8 * 8;
            gB = B0 + (size_t)(nBase + sRow) * ldB + kB + sC8 * 8;
            lA = ldA; lB = ldB;
        } else {
            const int kB = (st - 8) * 64;
            gA = A1 + (size_t)sRow * KC + kB + sC8 * 8;             // Wg row = co
            gB = B1x + (size_t)(nBase + sRow) * CIN + kB + sC8 * 8; // xT overlap rows
            lA = KC; lB = CIN;
        }
        const uint32_t dA = bufBase + sRow * ROWB + sC8 * 16;
        const uint32_t dB = bufBase + PLANE + sRow * ROWB + sC8 * 16;
#pragma unroll
        for (int i = 0; i < 4; ++i) {
            cpa16(dA + i * 32 * ROWB, gA + (size_t)(32 * i) * lA);
            cpa16(dB + i * 32 * ROWB, gB + (size_t)(32 * i) * lB);
        }
    };

    loadStage(0); CP_COMMIT();
    if (nChunks > 1) loadStage(1);
    CP_COMMIT();

#pragma unroll 1
    for (int ch = 0; ch < nChunks; ++ch) {
        CP_WAIT1();
        __syncthreads();     // buffer ch%3 ready & all warps done with ch-1

        const uint32_t bufBase = smBase + (uint32_t)(ch % 3) * BUF;
        const uint32_t aBase = bufBase + (wm * 32) * ROWB + aLane;
        const uint32_t bBase = bufBase + PLANE + (wn * 64) * ROWB + bLane;

        // prefetch next-next chunk into buffer (ch+2)%3 == (ch-1)%3 (free now)
        if (ch + 2 < nChunks) loadStage(ch + 2);
        CP_COMMIT();

#pragma unroll
        for (int k16 = 0; k16 < 4; ++k16) {
            const uint32_t kb = (uint32_t)(k16 * 32);
            uint32_t a0[2][4], bh[4][4];

#pragma unroll
            for (int mt = 0; mt < 2; ++mt)
                ldm4(a0[mt], aBase + mt * 16 * ROWB + kb);
#pragma unroll
            for (int pr = 0; pr < 4; ++pr)
                ldm4(bh[pr], bBase + pr * 16 * ROWB + kb);
#pragma unroll
            for (int mt = 0; mt < 2; ++mt)
#pragma unroll
                for (int nt = 0; nt < 8; ++nt) {
                    const int pr = nt >> 1, hf = (nt & 1) * 2;
                    mma_f16(c[mt][nt], a0[mt], bh[pr][hf], bh[pr][hf + 1]);
                }
        }
    }

    float gg = 0.f, sc = 1.f;
    if (MODE == 1) { gg = 1.0f / (1.0f + expf(-gate[0])); sc = gg * YINV; }
    float* Cz = C + (size_t)spl * cPlane + (MODE == 0 ? grp * 256 : 0);
#pragma unroll
    for (int mt = 0; mt < 2; ++mt) {
        const int r0 = mBase + wm * 32 + mt * 16 + g;
        float bf0 = 0.f, bf1 = 0.f;
        if (MODE == 1) {
            bf0 = gg * bias[r0 & (CIN - 1)] + (1.0f - gg) * cb[r0 & (CIN - 1)];
            bf1 = gg * bias[(r0 + 8) & (CIN - 1)] + (1.0f - gg) * cb[(r0 + 8) & (CIN - 1)];
        }
#pragma unroll
        for (int nt = 0; nt < 8; ++nt) {
            const int cc = nBase + wn * 64 + nt * 8 + (lane & 3) * 2;
            float* p0 = Cz + (size_t)r0 * ldC + cc;
            float* p1 = Cz + (size_t)(r0 + 8) * ldC + cc;
            if (MODE == 1) {
                *(float2*)p0 = make_float2(sc * c[mt][nt][0] + bf0,
                                           sc * c[mt][nt][1] + bf0);
                *(float2*)p1 = make_float2(sc * c[mt][nt][2] + bf1,
                                           sc * c[mt][nt][3] + bf1);
            } else {
                *(float2*)p0 = make_float2(c[mt][nt][0], c[mt][nt][1]);
                *(float2*)p1 = make_float2(c[mt][nt][2], c[mt][nt][3]);
            }
        }
    }
}

// ---------------- per-mode complex 16x16 head mixing ---------------------------
// XfP cols are group-major: col(Re_k) = (k&1)*256 + (k>>1)*2. Apply 1/L; emit
// Ys = Y*1024 fp16 in standard interleaved layout.
__global__ void __launch_bounds__(128) k_mix(const float* __restrict__ wre,
                                             const float* __restrict__ wim) {
    const int kc = blockIdx.x;
    const int h  = blockIdx.y;
    const int b  = blockIdx.z;
    const int kg = kc * 128 + threadIdx.x;
    const size_t PL = (size_t)BC * NF;
    const float LI = 1.0f / (float)Ln;
    const int colRe = (kg & 1) * 256 + (kg >> 1) * 2;

    float xr[16], xi[16];
#pragma unroll
    for (int i = 0; i < 16; i++) {
        size_t off = ((size_t)(b * CIN + h * 16 + i) * NF) + colRe;
        float sr = 0.f, si = 0.f;
#pragma unroll
        for (int s = 0; s < SPLITS; s++) {
            float2 v = *(const float2*)&g_XfP[s * PL + off];
            sr += v.x; si += v.y;
        }
        xr[i] = sr * LI; xi[i] = si * LI;
    }
#pragma unroll 1
    for (int o = 0; o < 16; o++) {
        float ar = 0.f, ai = 0.f;
#pragma unroll
        for (int i = 0; i < 16; i++) {
            int widx = ((h * 16 + i) * 16 + o) * MODESn + kg;
            float wr = wre[widx], wi = wim[widx];
            ar = fmaf(xr[i], wr, ar);
            ar = fmaf(-xi[i], wi, ar);
            ai = fmaf(xr[i], wi, ai);
            ai = fmaf(xi[i], wr, ai);
        }
        size_t off = ((size_t)(b * CIN + h * 16 + o) * NF) + 2 * kg;
        g_Ys[off]     = __float2half(ar * YSCALE);
        g_Ys[off + 1] = __float2half(ai * YSCALE);
    }
}

// ---------------- launch --------------------------------------------------------
extern "C" void kernel_launch(void* const* d_in, const int* in_sizes, int n_in,
                              void* d_out, int out_size) {
    const float* x      = (const float*)d_in[0];
    const float* wre    = (const float*)d_in[1];
    const float* wim    = (const float*)d_in[2];
    const float* bias   = (const float*)d_in[3];
    const float* conv_w = (const float*)d_in[4];
    const float* conv_b = (const float*)d_in[5];
    const float* gate   = (const float*)d_in[6];
    float* out = (float*)d_out;

    // Resolve REAL device addresses of __device__ scratch (host shadows are
    // ATS-dereferenceable host memory — NOT the device arrays).
    void *p_xf, *p_Bf, *p_Bi, *p_XfP, *p_Ys, *p_xT, *p_Wg;
    cudaGetSymbolAddress(&p_xf, g_xf);
    cudaGetSymbolAddress(&p_Bf, g_Bf);
    cudaGetSymbolAddress(&p_Bi, g_Bi);
    cudaGetSymbolAddress(&p_XfP, g_XfP);
    cudaGetSymbolAddress(&p_Ys, g_Ys);
    cudaGetSymbolAddress(&p_xT, g_xT);
    cudaGetSymbolAddress(&p_Wg, g_Wg);

    cudaFuncSetAttribute(k_tc<0>, cudaFuncAttributeMaxDynamicSharedMemorySize, TCSM);
    cudaFuncSetAttribute(k_tc<1>, cudaFuncAttributeMaxDynamicSharedMemorySize, TCSM);

    // prep (tc<0> stays the 4th launch -> lands in ncu's window)
    k_xprep<<<dim3(LH / 32, CIN / 32, Bn), dim3(32, 8)>>>(x);
    k_fillBf<<<dim3(LH / 256, NF), 256>>>();
    k_fillBi<<<dim3(NF / 256, Ln), 256>>>();

    // folded forward DFT (fp16, radix-2): per group g, XfP cols [g*256, g*256+256)
    // = xf[g] @ Bf[g]^T, K = 8192, split-K = 4. grid z = group*4 + split.
    k_tc<0><<<dim3(BC / 128, 2, 2 * SPLITS), 256, TCSM>>>(
        (const __half*)p_xf, (const __half*)p_Bf, nullptr, nullptr,
        LH, LH, (LH / SPLITS) / 64, LH / SPLITS,
        (size_t)BC * LH, (size_t)MODESn * LH,
        (float*)p_XfP, (size_t)BC * NF, NF, nullptr, nullptr, nullptr);

    k_wk<<<(CIN * KC + 255) / 256, 256>>>(conv_w, gate);

    // complex head mixing (+ split-K reduce, 1/L scale, Ys = Y*1024 fp16)
    k_mix<<<dim3(2, Hh, Bn), 128>>>(wre, wim);

    // fused inverse DFT + conv + bias + gated blend, K = 512 + 384
    k_tc<1><<<dim3(BC / 128, Ln / 128, 1), 256, TCSM>>>(
        (const __half*)p_Ys, (const __half*)p_Bi,
        (const __half*)p_Wg, (const __half*)p_xT,
        NF, NF, (NF + KC) / 64, 0, 0, 0,
        out, 0, Ln, bias, conv_b, gate);
}

// round 15
// speedup vs baseline: 8.5545x; 1.1199x over previous
#include <cuda_runtime.h>
#include <cuda_bf16.h>
#include <cuda_fp16.h>
#include <cstdint>

typedef unsigned long long ull;

#define Bn     16
#define CIN    128
#define Hh     8
#define MODESn 256
#define Ln     16384
#define LH     8192         // L/2 (radix-2 fold)
#define BC     (Bn*CIN)     // 2048
#define NF     (2*MODESn)   // 512
#define HM     MODESn       // 256 = cols per parity plane (128 k's x re/im)
#define SPLITS 4
#define XT2R   (LH+2)       // 8194: halo + 8192 + halo
#define KC     384          // conv K segment = 3*128
#define YSCALE 1024.0f
#define YINV   (1.0f/1024.0f)

// ---------------- device scratch (no allocations allowed) -------------------
// folded fwd A: [group][2048][8192]; group 0 = xe (even k), 1 = xo (odd k)
__device__ __align__(16) __half g_xf[(size_t)2*BC*LH];
// folded fwd B: [group][256 rows][8192]
__device__ __align__(16) __half g_Bf[(size_t)2*MODESn*LH];
// parity-split inverse basis: [p][8192 rows(n)][256 cols(j)], k = 2*(j>>1)+p
__device__ __align__(16) __half g_Bi[(size_t)2*LH*HM];
__device__ float         g_XfP[(size_t)SPLITS*BC*NF];   // fwd split-K partials
// parity-split Y: [p][2048][256] fp16 (x1024)
__device__ __align__(16) __half g_Ys[(size_t)2*BC*HM];
// parity-folded conv inputs, transposed+halo: [p][b][8194][128]
__device__ __align__(16) __half g_xT[(size_t)2*Bn*XT2R*CIN];
__device__ __align__(16) __half g_Wg[CIN*KC];           // conv W * (1-g)*YSCALE/(2g)

// ---------------- ptx helpers -------------------------------------------------
__device__ __forceinline__ uint32_t smem_u32(const void* p) {
    uint32_t a;
    asm("{ .reg .u64 t; cvta.to.shared.u64 t, %1; cvt.u32.u64 %0, t; }" : "=r"(a) : "l"(p));
    return a;
}
__device__ __forceinline__ void cpa16(uint32_t sdst, const void* gsrc) {
    asm volatile("cp.async.cg.shared.global [%0], [%1], 16;" :: "r"(sdst), "l"(gsrc));
}
#define CP_COMMIT() asm volatile("cp.async.commit_group;" ::: "memory")
#define CP_WAIT1()  asm volatile("cp.async.wait_group 1;" ::: "memory")

__device__ __forceinline__ void ldm4(uint32_t* r, uint32_t addr) {
    asm volatile("ldmatrix.sync.aligned.m8n8.x4.shared.b16 {%0,%1,%2,%3}, [%4];"
                 : "=r"(r[0]), "=r"(r[1]), "=r"(r[2]), "=r"(r[3]) : "r"(addr));
}
__device__ __forceinline__ void mma_f16(float* c, const uint32_t* a,
                                        uint32_t b0, uint32_t b1) {
    asm volatile("mma.sync.aligned.m16n8k16.row.col.f32.f16.f16.f32 "
                 "{%0,%1,%2,%3}, {%4,%5,%6,%7}, {%8,%9}, {%0,%1,%2,%3};"
                 : "+f"(c[0]), "+f"(c[1]), "+f"(c[2]), "+f"(c[3])
                 : "r"(a[0]), "r"(a[1]), "r"(a[2]), "r"(a[3]), "r"(b0), "r"(b1));
}

// ---------------- init kernels ------------------------------------------------
// folded forward basis: [g][j][n], k = 2*(j>>1)+g, n<8192 (unscaled)
__global__ void k_fillBf() {
    int n  = blockIdx.x * 256 + threadIdx.x;
    int jj = blockIdx.y;
    int gp = jj >> 8;
    int j  = jj & 255;
    int k  = 2 * (j >> 1) + gp;
    int idx = (k * n) & (Ln - 1);
    float s, c;
    sincospif((float)idx * (2.0f / Ln), &s, &c);
    g_Bf[((size_t)gp * MODESn + j) * LH + n] = __float2half((j & 1) ? -s : c);
}

// parity-split inverse basis: plane p, row n<8192, col j: k=2*(j>>1)+p
__global__ void k_fillBi() {
    int j  = blockIdx.x * 256 + threadIdx.x;     // 0..511 -> (p, jl)
    int n  = blockIdx.y;                         // 0..8191
    int p  = j >> 8;
    int jl = j & 255;
    int k  = 2 * (jl >> 1) + p;
    int idx = (k * n) & (Ln - 1);
    float s, c;
    sincospif((float)idx * (2.0f / Ln), &s, &c);
    float ck = (k == 0) ? 1.0f : 2.0f;
    float v = (jl & 1) ? (-ck * s) : (ck * c);
    g_Bi[((size_t)p * LH + n) * HM + jl] = __float2half(v);
}

// fused: x -> radix-2 folds xe/xo (fwd A, row-major) + (conv B, transposed+halo)
__global__ void __launch_bounds__(256) k_xprep(const float* __restrict__ x) {
    __shared__ float t0[32][33];
    __shared__ float t1[32][33];
    const int b   = blockIdx.z;
    const int ciB = blockIdx.y * 32;
    const int nB  = blockIdx.x * 32;
    const int tx = threadIdx.x, ty = threadIdx.y;

#pragma unroll
    for (int j = 0; j < 4; ++j) {
        int ci = ciB + ty + j * 8;
        size_t base = ((size_t)b * CIN + ci) * Ln + nB + tx;
        float v0 = x[base];
        float v1 = x[base + LH];
        t0[ty + j * 8][tx] = v0 + v1;   // xe
        t1[ty + j * 8][tx] = v0 - v1;   // xo
        size_t fo = ((size_t)b * CIN + ci) * LH + nB + tx;
        g_xf[fo]                   = __float2half(v0 + v1);
        g_xf[(size_t)BC * LH + fo] = __float2half(v0 - v1);
    }
    __syncthreads();
#pragma unroll
    for (int j = 0; j < 4; ++j) {
        int nl = ty + j * 8;
        size_t lo = ((size_t)b * XT2R + 1 + nB + nl) * CIN + ciB + tx;
        g_xT[lo]                          = __float2half(t0[tx][nl]);
        g_xT[lo + (size_t)Bn * XT2R * CIN] = __float2half(t1[tx][nl]);
    }
}

// halo rows: row 0 <- n=-1: xe=x[8191], xo=-x[8191]; row 8193 <- n=8192: both x[8192]
__global__ void k_halo(const float* __restrict__ x) {
    int t  = blockIdx.x * 256 + threadIdx.x;     // b*128+ci
    if (t >= Bn * CIN) return;
    int b = t >> 7, ci = t & 127;
    float xl = x[((size_t)b * CIN + ci) * Ln + LH - 1];   // x[8191]
    float xu = x[((size_t)b * CIN + ci) * Ln + LH];       // x[8192]
    size_t pe = ((size_t)b * XT2R) * CIN + ci;
    size_t po = pe + (size_t)Bn * XT2R * CIN;
    g_xT[pe]                              = __float2half(xl);
    g_xT[po]                              = __float2half(-xl);
    g_xT[pe + (size_t)(XT2R - 1) * CIN]   = __float2half(xu);
    g_xT[po + (size_t)(XT2R - 1) * CIN]   = __float2half(xu);
}

// conv weights -> Wg[co][d*128+ci] fp16, pre-scaled by (1-g)*YSCALE/(2g)
__global__ void k_wk(const float* __restrict__ w, const float* __restrict__ gate) {
    int idx = blockIdx.x * 256 + threadIdx.x;
    if (idx < CIN * KC) {
        int co = idx / KC;
        int r  = idx - co * KC;
        int d  = r >> 7;
        int ci = r & 127;
        float gg = 1.0f / (1.0f + expf(-gate[0]));
        float alpha = (1.0f - gg) * YSCALE / (2.0f * gg);
        g_Wg[idx] = __float2half(w[(co * CIN + ci) * 3 + d] * alpha);
    }
}

#define ROWB   144
#define PLANE  (128*ROWB)                // 128-row plane
#define HPLANE (64*ROWB)                 // 64-row plane

// ---------------- forward GEMM (unchanged, proven) ------------------------------
// C[128,128] tile, BK=64, triple buffer, grid z = group*SPLITS + split.
#define FBUF   (2*PLANE)
#define FTCSM  (3*FBUF + 1024)

__global__ void __launch_bounds__(256, 2) k_tcF(
    const __half* __restrict__ A0, const __half* __restrict__ B0,
    int nChunks, int kSplit, float* __restrict__ C)
{
    extern __shared__ char smraw[];
    const uint32_t smBase = (smem_u32(smraw) + 1023u) & ~1023u;

    const int tid  = threadIdx.x;
    const int lane = tid & 31;
    const int w    = tid >> 5;
    const int wm   = w & 3;
    const int wn   = w >> 2;
    const int mBase = blockIdx.x * 128;
    const int nBase = blockIdx.y * 128;
    const int grp = blockIdx.z >> 2, spl = blockIdx.z & 3;
    const int kOff = spl * kSplit;
    A0 += (size_t)grp * BC * LH;
    B0 += (size_t)grp * MODESn * LH;

    const int sRow = tid >> 3;
    const int sC8  = tid & 7;
    const int g = lane >> 2;
    const int lrow = lane & 7;
    const int sel0 = (lane >> 3) & 1;
    const int sel1 = (lane >> 4) & 1;
    const uint32_t aLane = (uint32_t)((lrow + sel0 * 8) * ROWB + sel1 * 16);
    const uint32_t bLane = (uint32_t)((lrow + sel1 * 8) * ROWB + sel0 * 16);

    float c[2][8][4];
#pragma unroll
    for (int mt = 0; mt < 2; mt++)
#pragma unroll
        for (int nt = 0; nt < 8; nt++)
#pragma unroll
            for (int q = 0; q < 4; q++) c[mt][nt][q] = 0.f;

    auto loadStage = [&](int st) {
        const uint32_t bufBase = smBase + (uint32_t)(st % 3) * FBUF;
        const int kB = kOff + st * 64;
        const __half* gA = A0 + (size_t)(mBase + sRow) * LH + kB + sC8 * 8;
        const __half* gB = B0 + (size_t)(nBase + sRow) * LH + kB + sC8 * 8;
        const uint32_t dA = bufBase + sRow * ROWB + sC8 * 16;
        const uint32_t dB = bufBase + PLANE + sRow * ROWB + sC8 * 16;
#pragma unroll
        for (int i = 0; i < 4; ++i) {
            cpa16(dA + i * 32 * ROWB, gA + (size_t)(32 * i) * LH);
            cpa16(dB + i * 32 * ROWB, gB + (size_t)(32 * i) * LH);
        }
    };

    loadStage(0); CP_COMMIT();
    loadStage(1); CP_COMMIT();

#pragma unroll 1
    for (int ch = 0; ch < nChunks; ++ch) {
        CP_WAIT1();
        __syncthreads();
        const uint32_t bufBase = smBase + (uint32_t)(ch % 3) * FBUF;
        const uint32_t aBase = bufBase + (wm * 32) * ROWB + aLane;
        const uint32_t bBase = bufBase + PLANE + (wn * 64) * ROWB + bLane;
        if (ch + 2 < nChunks) loadStage(ch + 2);
        CP_COMMIT();
#pragma unroll
        for (int k16 = 0; k16 < 4; ++k16) {
            const uint32_t kb = (uint32_t)(k16 * 32);
            uint32_t a0[2][4], bh[4][4];
#pragma unroll
            for (int mt = 0; mt < 2; ++mt)
                ldm4(a0[mt], aBase + mt * 16 * ROWB + kb);
#pragma unroll
            for (int pr = 0; pr < 4; ++pr)
                ldm4(bh[pr], bBase + pr * 16 * ROWB + kb);
#pragma unroll
            for (int mt = 0; mt < 2; ++mt)
#pragma unroll
                for (int nt = 0; nt < 8; ++nt) {
                    const int pr = nt >> 1, hf = (nt & 1) * 2;
                    mma_f16(c[mt][nt], a0[mt], bh[pr][hf], bh[pr][hf + 1]);
                }
        }
    }

    float* Cz = C + (size_t)spl * BC * NF + grp * 256;
#pragma unroll
    for (int mt = 0; mt < 2; ++mt) {
        const int r0 = mBase + wm * 32 + mt * 16 + g;
#pragma unroll
        for (int nt = 0; nt < 8; ++nt) {
            const int cc = nBase + wn * 64 + nt * 8 + (lane & 3) * 2;
            *(float2*)(Cz + (size_t)r0 * NF + cc) =
                make_float2(c[mt][nt][0], c[mt][nt][1]);
            *(float2*)(Cz + (size_t)(r0 + 8) * NF + cc) =
                make_float2(c[mt][nt][2], c[mt][nt][3]);
        }
    }
}

// ---------------- dual-parity inverse+conv GEMM --------------------------------
// C tile: rows 128 (one batch), cols 64 (n < 8192); dual accumulators E/O.
// 10 chunks: ch<4 spectral (YsE/YsO K=256, BiE/BiO), ch>=4 conv (Wg K=384,
// xTE/xTO overlapping-window). Epilogue: out[n] = sc*(E+O)+bf,
// out[n+8192] = sc*(E-O)+bf.
// SMEM stage: [AE 128r][AO 128r][BE 64r][BO 64r] = 384*144 = 55296; double buf.
#define DBUF   (2*PLANE + 2*HPLANE)      // 55296
#define DTCSM  (2*DBUF + 1024)           // 111616 -> 2 CTAs/SM

__global__ void __launch_bounds__(256, 2) k_tcD(
    const __half* __restrict__ Ys, const __half* __restrict__ Bi,
    const __half* __restrict__ Wg, const __half* __restrict__ xT,
    float* __restrict__ C,
    const float* __restrict__ bias, const float* __restrict__ cb,
    const float* __restrict__ gate)
{
    extern __shared__ char smraw[];
    const uint32_t smBase = (smem_u32(smraw) + 1023u) & ~1023u;

    const int tid  = threadIdx.x;
    const int lane = tid & 31;
    const int w    = tid >> 5;
    const int wm   = w & 3;              // m: 4 x 32
    const int wn   = w >> 2;             // n: 2 x 32
    const int mBase = blockIdx.x * 128;  // batch = blockIdx.x
    const int nBase = blockIdx.y * 64;

    const __half* YsO = Ys + (size_t)BC * HM;
    const __half* BiO = Bi + (size_t)LH * HM;
    const __half* xTE = xT + (size_t)blockIdx.x * XT2R * CIN;
    const __half* xTO = xTE + (size_t)Bn * XT2R * CIN;

    const int sRow  = tid >> 3;          // 0..31 (A staging, x4 -> 128 rows)
    const int sC8   = tid & 7;
    const int g = lane >> 2;
    const int lrow = lane & 7;
    const int sel0 = (lane >> 3) & 1;
    const int sel1 = (lane >> 4) & 1;
    const uint32_t aLane = (uint32_t)((lrow + sel0 * 8) * ROWB + sel1 * 16);
    const uint32_t bLane = (uint32_t)((lrow + sel1 * 8) * ROWB + sel0 * 16);

    const uint32_t offAO = PLANE;
    const uint32_t offBE = 2 * PLANE;
    const uint32_t offBO = 2 * PLANE + HPLANE;

    float cE[2][4][4], cO[2][4][4];
#pragma unroll
    for (int mt = 0; mt < 2; mt++)
#pragma unroll
        for (int nt = 0; nt < 4; nt++)
#pragma unroll
            for (int q = 0; q < 4; q++) { cE[mt][nt][q] = 0.f; cO[mt][nt][q] = 0.f; }

    auto loadStage = [&](int st) {
        const uint32_t bufBase = smBase + (uint32_t)(st & 1) * DBUF;
        const uint32_t dA  = bufBase + sRow * ROWB + sC8 * 16;
        const uint32_t dAO = dA + offAO;
        const uint32_t dBE = bufBase + offBE + sRow * ROWB + sC8 * 16;  // rows 0..31 (+32)
        const uint32_t dBO = dBE + HPLANE - 0 + (offBO - offBE - HPLANE); // = bufBase+offBO+...
        if (st < 4) {
            const int kB = st * 64;
            const __half* gAE = Ys  + (size_t)(mBase + sRow) * HM + kB + sC8 * 8;
            const __half* gAO = YsO + (size_t)(mBase + sRow) * HM + kB + sC8 * 8;
#pragma unroll
            for (int i = 0; i < 4; ++i) {
                cpa16(dA  + i * 32 * ROWB, gAE + (size_t)(32 * i) * HM);
                cpa16(dAO + i * 32 * ROWB, gAO + (size_t)(32 * i) * HM);
            }
            const __half* gBE = Bi  + (size_t)(nBase + sRow) * HM + kB + sC8 * 8;
            const __half* gBO = BiO + (size_t)(nBase + sRow) * HM + kB + sC8 * 8;
            const uint32_t bo = bufBase + offBO + sRow * ROWB + sC8 * 16;
            const uint32_t be = bufBase + offBE + sRow * ROWB + sC8 * 16;
#pragma unroll
            for (int i = 0; i < 2; ++i) {           // 32 rows x2 -> 64
                cpa16(be + i * 32 * ROWB, gBE + (size_t)(32 * i) * HM);
                cpa16(bo + i * 32 * ROWB, gBO + (size_t)(32 * i) * HM);
            }
        } else {
            const int kB = (st - 4) * 64;
            const __half* gW = Wg + (size_t)sRow * KC + kB + sC8 * 8;
#pragma unroll
            for (int i = 0; i < 4; ++i)
                cpa16(dA + i * 32 * ROWB, gW + (size_t)(32 * i) * KC);
            // overlapping-window conv B: row r reads xT[(nBase+r)*128 + kB ...]
            const __half* gBE = xTE + (size_t)(nBase + sRow) * CIN + kB + sC8 * 8;
            const __half* gBO = xTO + (size_t)(nBase + sRow) * CIN + kB + sC8 * 8;
            const uint32_t be = bufBase + offBE + sRow * ROWB + sC8 * 16;
            const uint32_t bo = bufBase + offBO + sRow * ROWB + sC8 * 16;
#pragma unroll
            for (int i = 0; i < 2; ++i) {
                cpa16(be + i * 32 * ROWB, gBE + (size_t)(32 * i) * CIN);
                cpa16(bo + i * 32 * ROWB, gBO + (size_t)(32 * i) * CIN);
            }
        }
    };

    loadStage(0); CP_COMMIT();
    loadStage(1); CP_COMMIT();

    const int nChunks = 10;
#pragma unroll 1
    for (int ch = 0; ch < nChunks; ++ch) {
        CP_WAIT1();
        __syncthreads();

        const uint32_t bufBase = smBase + (uint32_t)(ch & 1) * DBUF;
        const bool conv = (ch >= 4);
        const uint32_t aE = bufBase + (wm * 32) * ROWB + aLane;
        const uint32_t aO = conv ? aE : (aE + offAO);   // conv: Wg shared
        const uint32_t bE = bufBase + offBE + (wn * 32) * ROWB + bLane;
        const uint32_t bO = bufBase + offBO + (wn * 32) * ROWB + bLane;

#pragma unroll
        for (int k16 = 0; k16 < 4; ++k16) {
            const uint32_t kb = (uint32_t)(k16 * 32);
            uint32_t fAE[2][4], fAO[2][4], fBE[2][4], fBO[2][4];
#pragma unroll
            for (int mt = 0; mt < 2; ++mt) {
                ldm4(fAE[mt], aE + mt * 16 * ROWB + kb);
                ldm4(fAO[mt], aO + mt * 16 * ROWB + kb);
            }
#pragma unroll
            for (int pr = 0; pr < 2; ++pr) {
                ldm4(fBE[pr], bE + pr * 16 * ROWB + kb);
                ldm4(fBO[pr], bO + pr * 16 * ROWB + kb);
            }
#pragma unroll
            for (int mt = 0; mt < 2; ++mt)
#pragma unroll
                for (int nt = 0; nt < 4; ++nt) {
                    const int pr = nt >> 1, hf = (nt & 1) * 2;
                    mma_f16(cE[mt][nt], fAE[mt], fBE[pr][hf], fBE[pr][hf + 1]);
                    mma_f16(cO[mt][nt], fAO[mt], fBO[pr][hf], fBO[pr][hf + 1]);
                }
        }
        __syncthreads();
        if (ch + 2 < nChunks) loadStage(ch + 2);
        CP_COMMIT();
    }

    const float gg = 1.0f / (1.0f + expf(-gate[0]));
    const float sc = gg * YINV;
#pragma unroll
    for (int mt = 0; mt < 2; ++mt) {
        const int r0 = mBase + wm * 32 + mt * 16 + g;
        const float bf0 = gg * bias[r0 & (CIN - 1)] + (1.0f - gg) * cb[r0 & (CIN - 1)];
        const float bf1 = gg * bias[(r0 + 8) & (CIN - 1)] + (1.0f - gg) * cb[(r0 + 8) & (CIN - 1)];
#pragma unroll
        for (int nt = 0; nt < 4; ++nt) {
            const int cc = nBase + wn * 32 + nt * 8 + (lane & 3) * 2;
            float* p0 = C + (size_t)r0 * Ln + cc;
            float* p1 = C + (size_t)(r0 + 8) * Ln + cc;
            float e0 = cE[mt][nt][0], o0 = cO[mt][nt][0];
            float e1 = cE[mt][nt][1], o1 = cO[mt][nt][1];
            float e2 = cE[mt][nt][2], o2 = cO[mt][nt][2];
            float e3 = cE[mt][nt][3], o3 = cO[mt][nt][3];
            *(float2*)p0        = make_float2(sc * (e0 + o0) + bf0, sc * (e1 + o1) + bf0);
            *(float2*)(p0 + LH) = make_float2(sc * (e0 - o0) + bf0, sc * (e1 - o1) + bf0);
            *(float2*)p1        = make_float2(sc * (e2 + o2) + bf1, sc * (e3 + o3) + bf1);
            *(float2*)(p1 + LH) = make_float2(sc * (e2 - o2) + bf1, sc * (e3 - o3) + bf1);
        }
    }
}

// ---------------- per-mode complex 16x16 head mixing ---------------------------
// XfP cols group-major: col(Re_k) = (k&1)*256 + (k>>1)*2. Emit Ys parity-split:
// plane p = k&1, col (k>>1)*2, value Y*1024 fp16.
__global__ void __launch_bounds__(128) k_mix(const float* __restrict__ wre,
                                             const float* __restrict__ wim) {
    const int kc = blockIdx.x;
    const int h  = blockIdx.y;
    const int b  = blockIdx.z;
    const int kg = kc * 128 + threadIdx.x;
    const size_t PL = (size_t)BC * NF;
    const float LI = 1.0f / (float)Ln;
    const int colRe = (kg & 1) * 256 + (kg >> 1) * 2;
    const size_t ysP = (size_t)(kg & 1) * BC * HM;
    const int ysCol = (kg >> 1) * 2;

    float xr[16], xi[16];
#pragma unroll
    for (int i = 0; i < 16; i++) {
        size_t off = ((size_t)(b * CIN + h * 16 + i) * NF) + colRe;
        float sr = 0.f, si = 0.f;
#pragma unroll
        for (int s = 0; s < SPLITS; s++) {
            float2 v = *(const float2*)&g_XfP[s * PL + off];
            sr += v.x; si += v.y;
        }
        xr[i] = sr * LI; xi[i] = si * LI;
    }
#pragma unroll 1
    for (int o = 0; o < 16; o++) {
        float ar = 0.f, ai = 0.f;
#pragma unroll
        for (int i = 0; i < 16; i++) {
            int widx = ((h * 16 + i) * 16 + o) * MODESn + kg;
            float wr = wre[widx], wi = wim[widx];
            ar = fmaf(xr[i], wr, ar);
            ar = fmaf(-xi[i], wi, ar);
            ai = fmaf(xr[i], wi, ai);
            ai = fmaf(xi[i], wr, ai);
        }
        size_t off = ysP + (size_t)(b * CIN + h * 16 + o) * HM + ysCol;
        g_Ys[off]     = __float2half(ar * YSCALE);
        g_Ys[off + 1] = __float2half(ai * YSCALE);
    }
}

// ---------------- launch --------------------------------------------------------
extern "C" void kernel_launch(void* const* d_in, const int* in_sizes, int n_in,
                              void* d_out, int out_size) {
    const float* x      = (const float*)d_in[0];
    const float* wre    = (const float*)d_in[1];
    const float* wim    = (const float*)d_in[2];
    const float* bias   = (const float*)d_in[3];
    const float* conv_w = (const float*)d_in[4];
    const float* conv_b = (const float*)d_in[5];
    const float* gate   = (const float*)d_in[6];
    float* out = (float*)d_out;

    // Resolve REAL device addresses of __device__ scratch (host shadows are
    // ATS-dereferenceable host memory — NOT the device arrays).
    void *p_xf, *p_Bf, *p_Bi, *p_XfP, *p_Ys, *p_xT, *p_Wg;
    cudaGetSymbolAddress(&p_xf, g_xf);
    cudaGetSymbolAddress(&p_Bf, g_Bf);
    cudaGetSymbolAddress(&p_Bi, g_Bi);
    cudaGetSymbolAddress(&p_XfP, g_XfP);
    cudaGetSymbolAddress(&p_Ys, g_Ys);
    cudaGetSymbolAddress(&p_xT, g_xT);
    cudaGetSymbolAddress(&p_Wg, g_Wg);

    cudaFuncSetAttribute(k_tcF, cudaFuncAttributeMaxDynamicSharedMemorySize, FTCSM);
    cudaFuncSetAttribute(k_tcD, cudaFuncAttributeMaxDynamicSharedMemorySize, DTCSM);

    // prep (tcF stays the 4th launch -> lands in ncu's window)
    k_xprep<<<dim3(LH / 32, CIN / 32, Bn), dim3(32, 8)>>>(x);
    k_halo<<<(Bn * CIN + 255) / 256, 256>>>(x);
    k_fillBf<<<dim3(LH / 256, NF), 256>>>();

    // folded forward DFT (fp16, radix-2): K=8192, split-K=4, z = group*4+split
    k_tcF<<<dim3(BC / 128, 2, 2 * SPLITS), 256, FTCSM>>>(
        (const __half*)p_xf, (const __half*)p_Bf,
        (LH / SPLITS) / 64, LH / SPLITS, (float*)p_XfP);

    k_fillBi<<<dim3(NF / 256, LH), 256>>>();
    k_wk<<<(CIN * KC + 255) / 256, 256>>>(conv_w, gate);

    // complex head mixing (+ split-K reduce, 1/L scale, parity-split Ys x1024)
    k_mix<<<dim3(2, Hh, Bn), 128>>>(wre, wim);

    // dual-parity fused inverse DFT + conv + bias + gated blend
    k_tcD<<<dim3(BC / 128, LH / 64, 1), 256, DTCSM>>>(
        (const __half*)p_Ys, (const __half*)p_Bi,
        (const __half*)p_Wg, (const __half*)p_xT,
        out, bias, conv_b, gate);
}

// round 16
// speedup vs baseline: 8.6293x; 1.0087x over previous
#include <cuda_runtime.h>
#include <cuda_bf16.h>
#include <cuda_fp16.h>
#include <cstdint>

typedef unsigned long long ull;

#define Bn     16
#define CIN    128
#define Hh     8
#define MODESn 256
#define Ln     16384
#define LH     8192         // L/2
#define LQ     4096         // L/4
#define BC     (Bn*CIN)     // 2048
#define NF     (2*MODESn)   // 512
#define HM     MODESn       // 256 cols per parity plane
#define SPLITS 8            // forward split-K planes
#define XT2R   (LH+2)       // 8194: halo + 8192 + halo
#define KC     384          // conv K segment = 3*128
#define YSCALE 1024.0f
#define YINV   (1.0f/1024.0f)

// forward A plane offsets inside g_xf: [xo: BC*LH][xee: BC*LQ][xeo: BC*LQ]
#define XO_OFF  ((size_t)0)
#define XEE_OFF ((size_t)BC*LH)
#define XEO_OFF ((size_t)BC*LH + (size_t)BC*LQ)
// forward B offsets inside g_Bf: [B1(odd): 256*8192][B0e: 128*4096][B0o: 128*4096]
#define B1_N    ((size_t)256*LH)
#define B0_N    ((size_t)128*LQ)
#define B0E_OFF (B1_N)
#define B0O_OFF (B1_N + B0_N)

// ---------------- device scratch (no allocations allowed) -------------------
__device__ __align__(16) __half g_xf[(size_t)2*BC*LH];          // xo | xee | xeo
__device__ __align__(16) __half g_Bf[(size_t)2*MODESn*LH];      // B1 | B0e | B0o
__device__ __align__(16) __half g_Bi[(size_t)2*LH*HM];          // parity inverse basis
__device__ float         g_XfP[(size_t)SPLITS*BC*NF];           // fwd split-K partials
__device__ __align__(16) __half g_Ys[(size_t)2*BC*HM];          // parity Y (x1024)
__device__ __align__(16) __half g_xT[(size_t)2*Bn*XT2R*CIN];    // conv xe|xo (T + halo)
__device__ __align__(16) __half g_Wg[CIN*KC];                   // conv W *(1-g)*YSCALE/(2g)

// ---------------- ptx helpers -------------------------------------------------
__device__ __forceinline__ uint32_t smem_u32(const void* p) {
    uint32_t a;
    asm("{ .reg .u64 t; cvta.to.shared.u64 t, %1; cvt.u32.u64 %0, t; }" : "=r"(a) : "l"(p));
    return a;
}
__device__ __forceinline__ void cpa16(uint32_t sdst, const void* gsrc) {
    asm volatile("cp.async.cg.shared.global [%0], [%1], 16;" :: "r"(sdst), "l"(gsrc));
}
#define CP_COMMIT() asm volatile("cp.async.commit_group;" ::: "memory")
#define CP_WAIT1()  asm volatile("cp.async.wait_group 1;" ::: "memory")

__device__ __forceinline__ void ldm4(uint32_t* r, uint32_t addr) {
    asm volatile("ldmatrix.sync.aligned.m8n8.x4.shared.b16 {%0,%1,%2,%3}, [%4];"
                 : "=r"(r[0]), "=r"(r[1]), "=r"(r[2]), "=r"(r[3]) : "r"(addr));
}
__device__ __forceinline__ void mma_f16(float* c, const uint32_t* a,
                                        uint32_t b0, uint32_t b1) {
    asm volatile("mma.sync.aligned.m16n8k16.row.col.f32.f16.f16.f32 "
                 "{%0,%1,%2,%3}, {%4,%5,%6,%7}, {%8,%9}, {%0,%1,%2,%3};"
                 : "+f"(c[0]), "+f"(c[1]), "+f"(c[2]), "+f"(c[3])
                 : "r"(a[0]), "r"(a[1]), "r"(a[2]), "r"(a[3]), "r"(b0), "r"(b1));
}

// ---------------- init kernels ------------------------------------------------
// forward basis, three regions (all unscaled, theta = 2*pi*k*n/L):
//  B1  [j<256][n<8192]: k = 2*(j>>1)+1 (odd)
//  B0e [j<128][n<4096]: k = 4*(j>>1)
//  B0o [j<128][n<4096]: k = 4*(j>>1)+2
__global__ void k_fillBf() {
    size_t idx = (size_t)blockIdx.x * 256 + threadIdx.x;
    int j, n, k;
    if (idx < B1_N)            { j = (int)(idx >> 13); n = (int)(idx & 8191); k = 2 * (j >> 1) + 1; }
    else if (idx < B0O_OFF)    { size_t r = idx - B0E_OFF; j = (int)(r >> 12); n = (int)(r & 4095); k = 4 * (j >> 1); }
    else                       { size_t r = idx - B0O_OFF; j = (int)(r >> 12); n = (int)(r & 4095); k = 4 * (j >> 1) + 2; }
    int a = (k * n) & (Ln - 1);
    float s, c;
    sincospif((float)a * (2.0f / Ln), &s, &c);
    g_Bf[idx] = __float2half((j & 1) ? -s : c);
}

// parity-split inverse basis: plane p, row n<8192, col j: k=2*(j>>1)+p
__global__ void k_fillBi() {
    int j  = blockIdx.x * 256 + threadIdx.x;
    int n  = blockIdx.y;
    int p  = j >> 8;
    int jl = j & 255;
    int k  = 2 * (jl >> 1) + p;
    int a = (k * n) & (Ln - 1);
    float s, c;
    sincospif((float)a * (2.0f / Ln), &s, &c);
    float ck = (k == 0) ? 1.0f : 2.0f;
    g_Bi[((size_t)p * LH + n) * HM + jl] = __float2half((jl & 1) ? -ck * s : ck * c);
}

// x -> fwd A planes (xo K=8192, xee/xeo K=4096) + conv planes (xe/xo, T+halo)
// grid (LQ/32, CIN/32, Bn), block (32,8); each position reads 4 quarters.
__global__ void __launch_bounds__(256) k_xprep(const float* __restrict__ x) {
    __shared__ float sel[32][33], seh[32][33], sol[32][33], soh[32][33];
    const int b   = blockIdx.z;
    const int ciB = blockIdx.y * 32;
    const int nB  = blockIdx.x * 32;
    const int tx = threadIdx.x, ty = threadIdx.y;

#pragma unroll
    for (int j = 0; j < 4; ++j) {
        int ci = ciB + ty + j * 8;
        size_t base = ((size_t)b * CIN + ci) * Ln + nB + tx;
        float q0 = x[base];
        float q1 = x[base + LQ];
        float q2 = x[base + 2 * LQ];
        float q3 = x[base + 3 * LQ];
        float xel = q0 + q2, xeh = q1 + q3;      // xe at n, n+4096
        float xol = q0 - q2, xoh = q1 - q3;      // xo at n, n+4096
        sel[ty + j * 8][tx] = xel; seh[ty + j * 8][tx] = xeh;
        sol[ty + j * 8][tx] = xol; soh[ty + j * 8][tx] = xoh;
        // forward A planes (row-major)
        size_t fo = XO_OFF + ((size_t)b * CIN + ci) * LH + nB + tx;
        g_xf[fo]      = __float2half(xol);
        g_xf[fo + LQ] = __float2half(xoh);
        size_t fe = ((size_t)b * CIN + ci) * LQ + nB + tx;
        g_xf[XEE_OFF + fe] = __float2half(xel + xeh);   // xee
        g_xf[XEO_OFF + fe] = __float2half(xel - xeh);   // xeo
    }
    __syncthreads();
#pragma unroll
    for (int j = 0; j < 4; ++j) {
        int nl = ty + j * 8;
        size_t lo = ((size_t)b * XT2R + 1 + nB + nl) * CIN + ciB + tx;
        size_t hi = lo + (size_t)LQ * CIN;
        const size_t OFFO = (size_t)Bn * XT2R * CIN;
        g_xT[lo]        = __float2half(sel[tx][nl]);
        g_xT[hi]        = __float2half(seh[tx][nl]);
        g_xT[lo + OFFO] = __float2half(sol[tx][nl]);
        g_xT[hi + OFFO] = __float2half(soh[tx][nl]);
    }
}

// halo rows: n=-1 -> xe=x[8191], xo=-x[8191]; n=8192 -> both x[8192]
__global__ void k_halo(const float* __restrict__ x) {
    int t = blockIdx.x * 256 + threadIdx.x;
    if (t >= Bn * CIN) return;
    int b = t >> 7, ci = t & 127;
    float xl = x[((size_t)b * CIN + ci) * Ln + LH - 1];
    float xu = x[((size_t)b * CIN + ci) * Ln + LH];
    size_t pe = ((size_t)b * XT2R) * CIN + ci;
    size_t po = pe + (size_t)Bn * XT2R * CIN;
    g_xT[pe]                            = __float2half(xl);
    g_xT[po]                            = __float2half(-xl);
    g_xT[pe + (size_t)(XT2R - 1) * CIN] = __float2half(xu);
    g_xT[po + (size_t)(XT2R - 1) * CIN] = __float2half(xu);
}

// conv weights -> Wg[co][d*128+ci] fp16, pre-scaled by (1-g)*YSCALE/(2g)
__global__ void k_wk(const float* __restrict__ w, const float* __restrict__ gate) {
    int idx = blockIdx.x * 256 + threadIdx.x;
    if (idx < CIN * KC) {
        int co = idx / KC;
        int r  = idx - co * KC;
        int d  = r >> 7;
        int ci = r & 127;
        float gg = 1.0f / (1.0f + expf(-gate[0]));
        float alpha = (1.0f - gg) * YSCALE / (2.0f * gg);
        g_Wg[idx] = __float2half(w[(co * CIN + ci) * 3 + d] * alpha);
    }
}

#define ROWB   144
#define PLANE  (128*ROWB)
#define HPLANE (64*ROWB)

// ---------------- forward GEMM: balanced 16-chunk CTAs --------------------------
// grid (16 m-tiles, 24): zz<16: odd group, split=zz>>1 (8 splits), ntile=zz&1;
// zz in [16,20): xee subgroup, split=zz-16; zz in [20,24): xeo, split=zz-20.
// All segments: kSplit=1024 -> 16 chunks of 64.
#define FBUF   (2*PLANE)
#define FTCSM  (3*FBUF + 1024)

__global__ void __launch_bounds__(256, 2) k_tcF(float* __restrict__ C)
{
    extern __shared__ char smraw[];
    const uint32_t smBase = (smem_u32(smraw) + 1023u) & ~1023u;

    const int tid  = threadIdx.x;
    const int lane = tid & 31;
    const int w    = tid >> 5;
    const int wm   = w & 3;
    const int wn   = w >> 2;
    const int mBase = blockIdx.x * 128;

    // segment decode
    const int zz = blockIdx.y;
    const __half *A, *B;
    int lA, lB, kOff, colBase, spl;
    if (zz < 16) {
        spl = zz >> 1;
        int nt = zz & 1;
        A = g_xf + XO_OFF;           lA = LH;
        B = g_Bf + (size_t)nt * 128 * LH; lB = LH;
        kOff = spl * 1024;
        colBase = 256 + nt * 128;
    } else if (zz < 20) {
        spl = zz - 16;
        A = g_xf + XEE_OFF;          lA = LQ;
        B = g_Bf + B0E_OFF;          lB = LQ;
        kOff = spl * 1024;
        colBase = 0;
    } else {
        spl = zz - 20;
        A = g_xf + XEO_OFF;          lA = LQ;
        B = g_Bf + B0O_OFF;          lB = LQ;
        kOff = spl * 1024;
        colBase = 128;
    }

    const int sRow = tid >> 3;
    const int sC8  = tid & 7;
    const int g = lane >> 2;
    const int lrow = lane & 7;
    const int sel0 = (lane >> 3) & 1;
    const int sel1 = (lane >> 4) & 1;
    const uint32_t aLane = (uint32_t)((lrow + sel0 * 8) * ROWB + sel1 * 16);
    const uint32_t bLane = (uint32_t)((lrow + sel1 * 8) * ROWB + sel0 * 16);

    float c[2][8][4];
#pragma unroll
    for (int mt = 0; mt < 2; mt++)
#pragma unroll
        for (int nt = 0; nt < 8; nt++)
#pragma unroll
            for (int q = 0; q < 4; q++) c[mt][nt][q] = 0.f;

    auto loadStage = [&](int st) {
        const uint32_t bufBase = smBase + (uint32_t)(st % 3) * FBUF;
        const int kB = kOff + st * 64;
        const __half* gA = A + (size_t)(mBase + sRow) * lA + kB + sC8 * 8;
        const __half* gB = B + (size_t)sRow * lB + kB + sC8 * 8;
        const uint32_t dA = bufBase + sRow * ROWB + sC8 * 16;
        const uint32_t dB = bufBase + PLANE + sRow * ROWB + sC8 * 16;
#pragma unroll
        for (int i = 0; i < 4; ++i) {
            cpa16(dA + i * 32 * ROWB, gA + (size_t)(32 * i) * lA);
            cpa16(dB + i * 32 * ROWB, gB + (size_t)(32 * i) * lB);
        }
    };

    loadStage(0); CP_COMMIT();
    loadStage(1); CP_COMMIT();

    const int nChunks = 16;
#pragma unroll 1
    for (int ch = 0; ch < nChunks; ++ch) {
        CP_WAIT1();
        __syncthreads();
        const uint32_t bufBase = smBase + (uint32_t)(ch % 3) * FBUF;
        const uint32_t aBase = bufBase + (wm * 32) * ROWB + aLane;
        const uint32_t bBase = bufBase + PLANE + (wn * 64) * ROWB + bLane;
        if (ch + 2 < nChunks) loadStage(ch + 2);
        CP_COMMIT();
#pragma unroll
        for (int k16 = 0; k16 < 4; ++k16) {
            const uint32_t kb = (uint32_t)(k16 * 32);
            uint32_t a0[2][4], bh[4][4];
#pragma unroll
            for (int mt = 0; mt < 2; ++mt)
                ldm4(a0[mt], aBase + mt * 16 * ROWB + kb);
#pragma unroll
            for (int pr = 0; pr < 4; ++pr)
                ldm4(bh[pr], bBase + pr * 16 * ROWB + kb);
#pragma unroll
            for (int mt = 0; mt < 2; ++mt)
#pragma unroll
                for (int nt = 0; nt < 8; ++nt) {
                    const int pr = nt >> 1, hf = (nt & 1) * 2;
                    mma_f16(c[mt][nt], a0[mt], bh[pr][hf], bh[pr][hf + 1]);
                }
        }
    }

    float* Cz = C + (size_t)spl * BC * NF + colBase;
#pragma unroll
    for (int mt = 0; mt < 2; ++mt) {
        const int r0 = mBase + wm * 32 + mt * 16 + g;
#pragma unroll
        for (int nt = 0; nt < 8; ++nt) {
            const int cc = wn * 64 + nt * 8 + (lane & 3) * 2;
            *(float2*)(Cz + (size_t)r0 * NF + cc) =
                make_float2(c[mt][nt][0], c[mt][nt][1]);
            *(float2*)(Cz + (size_t)(r0 + 8) * NF + cc) =
                make_float2(c[mt][nt][2], c[mt][nt][3]);
        }
    }
}

// ---------------- dual-parity inverse+conv GEMM (unchanged from R15) -----------
#define DBUF   (2*PLANE + 2*HPLANE)
#define DTCSM  (2*DBUF + 1024)

__global__ void __launch_bounds__(256, 2) k_tcD(
    const __half* __restrict__ Ys, const __half* __restrict__ Bi,
    const __half* __restrict__ Wg, const __half* __restrict__ xT,
    float* __restrict__ C,
    const float* __restrict__ bias, const float* __restrict__ cb,
    const float* __restrict__ gate)
{
    extern __shared__ char smraw[];
    const uint32_t smBase = (smem_u32(smraw) + 1023u) & ~1023u;

    const int tid  = threadIdx.x;
    const int lane = tid & 31;
    const int w    = tid >> 5;
    const int wm   = w & 3;
    const int wn   = w >> 2;
    const int mBase = blockIdx.x * 128;
    const int nBase = blockIdx.y * 64;

    const __half* YsO = Ys + (size_t)BC * HM;
    const __half* BiO = Bi + (size_t)LH * HM;
    const __half* xTE = xT + (size_t)blockIdx.x * XT2R * CIN;
    const __half* xTO = xTE + (size_t)Bn * XT2R * CIN;

    const int sRow  = tid >> 3;
    const int sC8   = tid & 7;
    const int g = lane >> 2;
    const int lrow = lane & 7;
    const int sel0 = (lane >> 3) & 1;
    const int sel1 = (lane >> 4) & 1;
    const uint32_t aLane = (uint32_t)((lrow + sel0 * 8) * ROWB + sel1 * 16);
    const uint32_t bLane = (uint32_t)((lrow + sel1 * 8) * ROWB + sel0 * 16);

    const uint32_t offAO = PLANE;
    const uint32_t offBE = 2 * PLANE;
    const uint32_t offBO = 2 * PLANE + HPLANE;

    float cE[2][4][4], cO[2][4][4];
#pragma unroll
    for (int mt = 0; mt < 2; mt++)
#pragma unroll
        for (int nt = 0; nt < 4; nt++)
#pragma unroll
            for (int q = 0; q < 4; q++) { cE[mt][nt][q] = 0.f; cO[mt][nt][q] = 0.f; }

    auto loadStage = [&](int st) {
        const uint32_t bufBase = smBase + (uint32_t)(st & 1) * DBUF;
        const uint32_t dA  = bufBase + sRow * ROWB + sC8 * 16;
        const uint32_t dAO = dA + offAO;
        if (st < 4) {
            const int kB = st * 64;
            const __half* gAE = Ys  + (size_t)(mBase + sRow) * HM + kB + sC8 * 8;
            const __half* gAO = YsO + (size_t)(mBase + sRow) * HM + kB + sC8 * 8;
#pragma unroll
            for (int i = 0; i < 4; ++i) {
                cpa16(dA  + i * 32 * ROWB, gAE + (size_t)(32 * i) * HM);
                cpa16(dAO + i * 32 * ROWB, gAO + (size_t)(32 * i) * HM);
            }
            const __half* gBE = Bi  + (size_t)(nBase + sRow) * HM + kB + sC8 * 8;
            const __half* gBO = BiO + (size_t)(nBase + sRow) * HM + kB + sC8 * 8;
            const uint32_t be = bufBase + offBE + sRow * ROWB + sC8 * 16;
            const uint32_t bo = bufBase + offBO + sRow * ROWB + sC8 * 16;
#pragma unroll
            for (int i = 0; i < 2; ++i) {
                cpa16(be + i * 32 * ROWB, gBE + (size_t)(32 * i) * HM);
                cpa16(bo + i * 32 * ROWB, gBO + (size_t)(32 * i) * HM);
            }
        } else {
            const int kB = (st - 4) * 64;
            const __half* gW = Wg + (size_t)sRow * KC + kB + sC8 * 8;
#pragma unroll
            for (int i = 0; i < 4; ++i)
                cpa16(dA + i * 32 * ROWB, gW + (size_t)(32 * i) * KC);
            const __half* gBE = xTE + (size_t)(nBase + sRow) * CIN + kB + sC8 * 8;
            const __half* gBO = xTO + (size_t)(nBase + sRow) * CIN + kB + sC8 * 8;
            const uint32_t be = bufBase + offBE + sRow * ROWB + sC8 * 16;
            const uint32_t bo = bufBase + offBO + sRow * ROWB + sC8 * 16;
#pragma unroll
            for (int i = 0; i < 2; ++i) {
                cpa16(be + i * 32 * ROWB, gBE + (size_t)(32 * i) * CIN);
                cpa16(bo + i * 32 * ROWB, gBO + (size_t)(32 * i) * CIN);
            }
        }
    };

    loadStage(0); CP_COMMIT();
    loadStage(1); CP_COMMIT();

    const int nChunks = 10;
#pragma unroll 1
    for (int ch = 0; ch < nChunks; ++ch) {
        CP_WAIT1();
        __syncthreads();

        const uint32_t bufBase = smBase + (uint32_t)(ch & 1) * DBUF;
        const bool conv = (ch >= 4);
        const uint32_t aE = bufBase + (wm * 32) * ROWB + aLane;
        const uint32_t aO = conv ? aE : (aE + offAO);
        const uint32_t bE = bufBase + offBE + (wn * 32) * ROWB + bLane;
        const uint32_t bO = bufBase + offBO + (wn * 32) * ROWB + bLane;

#pragma unroll
        for (int k16 = 0; k16 < 4; ++k16) {
            const uint32_t kb = (uint32_t)(k16 * 32);
            uint32_t fAE[2][4], fAO[2][4], fBE[2][4], fBO[2][4];
#pragma unroll
            for (int mt = 0; mt < 2; ++mt) {
                ldm4(fAE[mt], aE + mt * 16 * ROWB + kb);
                ldm4(fAO[mt], aO + mt * 16 * ROWB + kb);
            }
#pragma unroll
            for (int pr = 0; pr < 2; ++pr) {
                ldm4(fBE[pr], bE + pr * 16 * ROWB + kb);
                ldm4(fBO[pr], bO + pr * 16 * ROWB + kb);
            }
#pragma unroll
            for (int mt = 0; mt < 2; ++mt)
#pragma unroll
                for (int nt = 0; nt < 4; ++nt) {
                    const int pr = nt >> 1, hf = (nt & 1) * 2;
                    mma_f16(cE[mt][nt], fAE[mt], fBE[pr][hf], fBE[pr][hf + 1]);
                    mma_f16(cO[mt][nt], fAO[mt], fBO[pr][hf], fBO[pr][hf + 1]);
                }
        }
        __syncthreads();
        if (ch + 2 < nChunks) loadStage(ch + 2);
        CP_COMMIT();
    }

    const float gg = 1.0f / (1.0f + expf(-gate[0]));
    const float sc = gg * YINV;
#pragma unroll
    for (int mt = 0; mt < 2; ++mt) {
        const int r0 = mBase + wm * 32 + mt * 16 + g;
        const float bf0 = gg * bias[r0 & (CIN - 1)] + (1.0f - gg) * cb[r0 & (CIN - 1)];
        const float bf1 = gg * bias[(r0 + 8) & (CIN - 1)] + (1.0f - gg) * cb[(r0 + 8) & (CIN - 1)];
#pragma unroll
        for (int nt = 0; nt < 4; ++nt) {
            const int cc = nBase + wn * 32 + nt * 8 + (lane & 3) * 2;
            float* p0 = C + (size_t)r0 * Ln + cc;
            float* p1 = C + (size_t)(r0 + 8) * Ln + cc;
            float e0 = cE[mt][nt][0], o0 = cO[mt][nt][0];
            float e1 = cE[mt][nt][1], o1 = cO[mt][nt][1];
            float e2 = cE[mt][nt][2], o2 = cO[mt][nt][2];
            float e3 = cE[mt][nt][3], o3 = cO[mt][nt][3];
            *(float2*)p0        = make_float2(sc * (e0 + o0) + bf0, sc * (e1 + o1) + bf0);
            *(float2*)(p0 + LH) = make_float2(sc * (e0 - o0) + bf0, sc * (e1 - o1) + bf0);
            *(float2*)p1        = make_float2(sc * (e2 + o2) + bf1, sc * (e3 + o3) + bf1);
            *(float2*)(p1 + LH) = make_float2(sc * (e2 - o2) + bf1, sc * (e3 - o3) + bf1);
        }
    }
}

// ---------------- per-mode complex 16x16 head mixing ---------------------------
// XfP col(Re_k): k odd -> 256+(k>>1)*2; k%4==0 -> (k>>2)*2; k%4==2 -> 128+(k>>2)*2.
// Sum all 8 split planes (planes 4-7 are zero for even-k cols). Emit Ys parity.
__global__ void __launch_bounds__(128) k_mix(const float* __restrict__ wre,
                                             const float* __restrict__ wim) {
    const int kc = blockIdx.x;
    const int h  = blockIdx.y;
    const int b  = blockIdx.z;
    const int kg = kc * 128 + threadIdx.x;
    const size_t PL = (size_t)BC * NF;
    const float LI = 1.0f / (float)Ln;
    const int colRe = (kg & 1) ? (256 + (kg >> 1) * 2)
                   : ((kg & 2) ? (128 + (kg >> 2) * 2) : ((kg >> 2) * 2));
    const size_t ysP = (size_t)(kg & 1) * BC * HM;
    const int ysCol = (kg >> 1) * 2;

    float xr[16], xi[16];
#pragma unroll
    for (int i = 0; i < 16; i++) {
        size_t off = ((size_t)(b * CIN + h * 16 + i) * NF) + colRe;
        float sr = 0.f, si = 0.f;
#pragma unroll
        for (int s = 0; s < SPLITS; s++) {
            float2 v = *(const float2*)&g_XfP[s * PL + off];
            sr += v.x; si += v.y;
        }
        xr[i] = sr * LI; xi[i] = si * LI;
    }
#pragma unroll 1
    for (int o = 0; o < 16; o++) {
        float ar = 0.f, ai = 0.f;
#pragma unroll
        for (int i = 0; i < 16; i++) {
            int widx = ((h * 16 + i) * 16 + o) * MODESn + kg;
            float wr = wre[widx], wi = wim[widx];
            ar = fmaf(xr[i], wr, ar);
            ar = fmaf(-xi[i], wi, ar);
            ai = fmaf(xr[i], wi, ai);
            ai = fmaf(xi[i], wr, ai);
        }
        size_t off = ysP + (size_t)(b * CIN + h * 16 + o) * HM + ysCol;
        g_Ys[off]     = __float2half(ar * YSCALE);
        g_Ys[off + 1] = __float2half(ai * YSCALE);
    }
}

// ---------------- launch --------------------------------------------------------
extern "C" void kernel_launch(void* const* d_in, const int* in_sizes, int n_in,
                              void* d_out, int out_size) {
    const float* x      = (const float*)d_in[0];
    const float* wre    = (const float*)d_in[1];
    const float* wim    = (const float*)d_in[2];
    const float* bias   = (const float*)d_in[3];
    const float* conv_w = (const float*)d_in[4];
    const float* conv_b = (const float*)d_in[5];
    const float* gate   = (const float*)d_in[6];
    float* out = (float*)d_out;

    // Resolve REAL device addresses of __device__ scratch (host shadows are
    // ATS-dereferenceable host memory — NOT the device arrays).
    void *p_Bi, *p_XfP, *p_Ys, *p_xT, *p_Wg;
    cudaGetSymbolAddress(&p_Bi, g_Bi);
    cudaGetSymbolAddress(&p_XfP, g_XfP);
    cudaGetSymbolAddress(&p_Ys, g_Ys);
    cudaGetSymbolAddress(&p_xT, g_xT);
    cudaGetSymbolAddress(&p_Wg, g_Wg);

    cudaFuncSetAttribute(k_tcF, cudaFuncAttributeMaxDynamicSharedMemorySize, FTCSM);
    cudaFuncSetAttribute(k_tcD, cudaFuncAttributeMaxDynamicSharedMemorySize, DTCSM);

    // prep (tcF stays the 4th launch -> lands in ncu's window)
    k_xprep<<<dim3(LQ / 32, CIN / 32, Bn), dim3(32, 8)>>>(x);
    k_halo<<<(Bn * CIN + 255) / 256, 256>>>(x);
    k_fillBf<<<(unsigned)((B1_N + 2 * B0_N) / 256), 256>>>();

    // balanced folded forward DFT: 384 uniform CTAs x 16 chunks
    k_tcF<<<dim3(BC / 128, 24), 256, FTCSM>>>((float*)p_XfP);

    k_fillBi<<<dim3(NF / 256, LH), 256>>>();
    k_wk<<<(CIN * KC + 255) / 256, 256>>>(conv_w, gate);

    // complex head mixing (+ 8-plane split-K reduce, 1/L, parity-split Ys x1024)
    k_mix<<<dim3(2, Hh, Bn), 128>>>(wre, wim);

    // dual-parity fused inverse DFT + conv + bias + gated blend
    k_tcD<<<dim3(BC / 128, LH / 64, 1), 256, DTCSM>>>(
        (const __half*)p_Ys, (const __half*)p_Bi,
        (const __half*)p_Wg, (const __half*)p_xT,
        out, bias, conv_b, gate);
}